// round 1
// baseline (speedup 1.0000x reference)
#include <cuda_runtime.h>
#include <cuda_bf16.h>
#include <math.h>
#include <float.h>
#include <limits.h>

// ---------------- problem constants (fixed shapes) ----------------
#define NROWS 6272      // embedding rows
#define MROWS 32768     // memory bank rows
#define DDIM  128
#define BATCH 8
#define PPB   784       // patches per batch (28*28)
#define WIO   28
#define OUTSZ 224
#define KNEIGH 9
#define KSIZE 33
#define KRAD  16

#define BN 64           // emb rows per block
#define BM 64           // mb rows per tile
#define NSPLIT 4
#define MS (MROWS / NSPLIT)   // 8192
#define TILES (MS / BM)       // 128
#define LDT 129               // padded tile stride

// ---------------- device scratch (no allocations allowed) ----------------
__device__ float g_y2[MROWS];                 // ||memory_bank[m]||^2
__device__ float g_pval[NSPLIT * NROWS];      // partial max of s
__device__ int   g_pidx[NSPLIT * NROWS];
__device__ float g_pscore[NROWS];             // patch scores (min dist)
__device__ int   g_ploc[NROWS];               // argmin locations
__device__ int   g_qrow[BATCH];               // global emb row of max patch
__device__ float g_score[BATCH];
__device__ int   g_nnidx[BATCH];
__device__ float g_dnn[BATCH * MROWS];
__device__ float g_gauss[KSIZE];
__device__ float g_umap[BATCH * OUTSZ * OUTSZ];
__device__ float g_vtmp[BATCH * OUTSZ * OUTSZ];

// ---------------- gaussian kernel init ----------------
__global__ void k_gauss_init() {
    if (threadIdx.x == 0) {
        float tmp[KSIZE];
        float s = 0.0f;
        for (int i = 0; i < KSIZE; i++) {
            float x = (float)i - (float)(KSIZE - 1) * 0.5f;
            float t = x / 4.0f;
            tmp[i] = expf(-0.5f * t * t);
            s += tmp[i];
        }
        for (int i = 0; i < KSIZE; i++) g_gauss[i] = tmp[i] / s;
    }
}

// ---------------- memory bank row norms ----------------
// one warp per row; 8 warps per block
__global__ void k_y2(const float* __restrict__ mb) {
    int warp = threadIdx.x >> 5;
    int lane = threadIdx.x & 31;
    int row = blockIdx.x * 8 + warp;
    if (row >= MROWS) return;
    float4 v = reinterpret_cast<const float4*>(mb + (size_t)row * DDIM)[lane];
    float s = v.x * v.x + v.y * v.y + v.z * v.z + v.w * v.w;
    #pragma unroll
    for (int o = 16; o > 0; o >>= 1) s += __shfl_xor_sync(0xFFFFFFFF, s, o);
    if (lane == 0) g_y2[row] = s;
}

// ---------------- fused distance GEMM + per-row running argmax of s ----------------
// grid: (NROWS/BN, NSPLIT), block: 256 threads (16x16), 4x4 micro-tile,
// interleaved output mapping rows = ty+16i, cols = tx+16j (bank-conflict free)
extern __shared__ float s_mem[];

__global__ void __launch_bounds__(256) k_dist(const float* __restrict__ emb,
                                              const float* __restrict__ mb) {
    float* sA = s_mem;              // BN x LDT
    float* sB = s_mem + BN * LDT;   // BM x LDT

    const int tid = threadIdx.x;
    const int tx = tid & 15;
    const int ty = tid >> 4;
    const int rowBase = blockIdx.x * BN;
    const int mBase = blockIdx.y * MS;

    // load embedding tile once (64 x 128)
    #pragma unroll
    for (int k = 0; k < 8; k++) {
        int lin = (k * 256 + tid) * 4;
        int r = lin >> 7, d = lin & 127;
        float4 v = *reinterpret_cast<const float4*>(emb + (size_t)(rowBase + r) * DDIM + d);
        float* p = &sA[r * LDT + d];
        p[0] = v.x; p[1] = v.y; p[2] = v.z; p[3] = v.w;
    }

    int rA[4], rB[4];
    #pragma unroll
    for (int i = 0; i < 4; i++) rA[i] = (ty + 16 * i) * LDT;
    #pragma unroll
    for (int j = 0; j < 4; j++) rB[j] = (tx + 16 * j) * LDT;

    float bestV[4];
    int bestI[4];
    #pragma unroll
    for (int i = 0; i < 4; i++) { bestV[i] = -FLT_MAX; bestI[i] = INT_MAX; }

    for (int t = 0; t < TILES; t++) {
        __syncthreads();   // protect sB from previous iteration's readers
        const int mrow0 = mBase + t * BM;
        #pragma unroll
        for (int k = 0; k < 8; k++) {
            int lin = (k * 256 + tid) * 4;
            int r = lin >> 7, d = lin & 127;
            float4 v = *reinterpret_cast<const float4*>(mb + (size_t)(mrow0 + r) * DDIM + d);
            float* p = &sB[r * LDT + d];
            p[0] = v.x; p[1] = v.y; p[2] = v.z; p[3] = v.w;
        }
        __syncthreads();

        float acc[4][4];
        #pragma unroll
        for (int i = 0; i < 4; i++)
            #pragma unroll
            for (int j = 0; j < 4; j++) acc[i][j] = 0.0f;

        #pragma unroll 4
        for (int d = 0; d < DDIM; d++) {
            float a0 = sA[rA[0] + d], a1 = sA[rA[1] + d];
            float a2 = sA[rA[2] + d], a3 = sA[rA[3] + d];
            float b0 = sB[rB[0] + d], b1 = sB[rB[1] + d];
            float b2 = sB[rB[2] + d], b3 = sB[rB[3] + d];
            acc[0][0] += a0 * b0; acc[0][1] += a0 * b1; acc[0][2] += a0 * b2; acc[0][3] += a0 * b3;
            acc[1][0] += a1 * b0; acc[1][1] += a1 * b1; acc[1][2] += a1 * b2; acc[1][3] += a1 * b3;
            acc[2][0] += a2 * b0; acc[2][1] += a2 * b1; acc[2][2] += a2 * b2; acc[2][3] += a2 * b3;
            acc[3][0] += a3 * b0; acc[3][1] += a3 * b1; acc[3][2] += a3 * b2; acc[3][3] += a3 * b3;
        }

        #pragma unroll
        for (int j = 0; j < 4; j++) {
            int col = mrow0 + tx + 16 * j;
            float half_y2 = 0.5f * g_y2[col];
            #pragma unroll
            for (int i = 0; i < 4; i++) {
                float s = acc[i][j] - half_y2;
                if (s > bestV[i] || (s == bestV[i] && col < bestI[i])) {
                    bestV[i] = s; bestI[i] = col;
                }
            }
        }
    }

    // block-level reduce per row (reuse sA region)
    __syncthreads();
    float* sRv = sA;                          // 64*16 floats
    int* sRi = reinterpret_cast<int*>(sA + BN * 16);
    #pragma unroll
    for (int i = 0; i < 4; i++) {
        int r = ty + 16 * i;
        sRv[r * 16 + tx] = bestV[i];
        sRi[r * 16 + tx] = bestI[i];
    }
    __syncthreads();
    if (tid < BN) {
        float bv = -FLT_MAX; int bi = INT_MAX;
        #pragma unroll
        for (int x = 0; x < 16; x++) {
            float v = sRv[tid * 16 + x];
            int ii = sRi[tid * 16 + x];
            if (v > bv || (v == bv && ii < bi)) { bv = v; bi = ii; }
        }
        int row = rowBase + tid;
        g_pval[blockIdx.y * NROWS + row] = bv;
        g_pidx[blockIdx.y * NROWS + row] = bi;
    }
}

// ---------------- combine split partials -> patch scores + locations ----------------
__global__ void k_reduce(const float* __restrict__ emb) {
    int row = blockIdx.x * 256 + threadIdx.x;
    if (row >= NROWS) return;
    float bv = -FLT_MAX; int bi = INT_MAX;
    #pragma unroll
    for (int s = 0; s < NSPLIT; s++) {
        float v = g_pval[s * NROWS + row];
        int ii = g_pidx[s * NROWS + row];
        if (v > bv || (v == bv && ii < bi)) { bv = v; bi = ii; }
    }
    float x2 = 0.0f;
    const float4* e = reinterpret_cast<const float4*>(emb + (size_t)row * DDIM);
    #pragma unroll
    for (int d = 0; d < DDIM / 4; d++) {
        float4 v = e[d];
        x2 += v.x * v.x + v.y * v.y + v.z * v.z + v.w * v.w;
    }
    float d2 = x2 - 2.0f * bv;
    g_pscore[row] = sqrtf(fmaxf(d2, 0.0f));
    g_ploc[row] = bi;
}

// ---------------- per-image argmax patch ----------------
__global__ void k_imgmax() {
    int b = blockIdx.x;
    int tid = threadIdx.x;
    __shared__ float sv[256];
    __shared__ int si[256];
    float bv = -FLT_MAX; int bi = INT_MAX;
    for (int p = tid; p < PPB; p += 256) {
        float v = g_pscore[b * PPB + p];
        if (v > bv || (v == bv && p < bi)) { bv = v; bi = p; }
    }
    sv[tid] = bv; si[tid] = bi;
    __syncthreads();
    for (int s = 128; s > 0; s >>= 1) {
        if (tid < s) {
            if (sv[tid + s] > sv[tid] || (sv[tid + s] == sv[tid] && si[tid + s] < si[tid])) {
                sv[tid] = sv[tid + s]; si[tid] = si[tid + s];
            }
        }
        __syncthreads();
    }
    if (tid == 0) {
        g_score[b] = sv[0];
        g_qrow[b] = b * PPB + si[0];
        g_nnidx[b] = g_ploc[b * PPB + si[0]];
    }
}

// ---------------- d_nn = dist(memory_bank[nn_idx[b]], memory_bank) ----------------
// grid (MROWS/8, BATCH), block 256 = 8 warps, one warp per mb row
__global__ void k_dnn(const float* __restrict__ mb) {
    int b = blockIdx.y;
    int warp = threadIdx.x >> 5;
    int lane = threadIdx.x & 31;
    int row = blockIdx.x * 8 + warp;
    int nn = g_nnidx[b];
    float4 q = reinterpret_cast<const float4*>(mb + (size_t)nn * DDIM)[lane];
    float4 m = reinterpret_cast<const float4*>(mb + (size_t)row * DDIM)[lane];
    float dot = q.x * m.x + q.y * m.y + q.z * m.z + q.w * m.w;
    #pragma unroll
    for (int o = 16; o > 0; o >>= 1) dot += __shfl_xor_sync(0xFFFFFFFF, dot, o);
    if (lane == 0) {
        float d2 = g_y2[nn] - 2.0f * dot + g_y2[row];
        g_dnn[b * MROWS + row] = sqrtf(fmaxf(d2, 0.0f));
    }
}

// ---------------- top-9 selection + softmax reweight -> pred_score ----------------
__global__ void k_final(const float* __restrict__ emb, const float* __restrict__ mb,
                        float* __restrict__ out) {
    int b = blockIdx.x;
    int tid = threadIdx.x;
    __shared__ float sv[256];
    __shared__ int si[256];
    __shared__ int sel[KNEIGH];
    __shared__ float dists[KNEIGH];

    for (int it = 0; it < KNEIGH; it++) {
        float bv = FLT_MAX; int bi = INT_MAX;
        for (int m = tid; m < MROWS; m += 256) {
            bool skip = false;
            for (int s2 = 0; s2 < it; s2++) if (sel[s2] == m) skip = true;
            if (skip) continue;
            float v = g_dnn[b * MROWS + m];
            if (v < bv || (v == bv && m < bi)) { bv = v; bi = m; }
        }
        sv[tid] = bv; si[tid] = bi;
        __syncthreads();
        for (int s = 128; s > 0; s >>= 1) {
            if (tid < s) {
                if (sv[tid + s] < sv[tid] || (sv[tid + s] == sv[tid] && si[tid + s] < si[tid])) {
                    sv[tid] = sv[tid + s]; si[tid] = si[tid + s];
                }
            }
            __syncthreads();
        }
        if (tid == 0) sel[it] = si[0];
        __syncthreads();
    }

    if (tid < KNEIGH) {
        const float* q = emb + (size_t)g_qrow[b] * DDIM;
        const float* m = mb + (size_t)sel[tid] * DDIM;
        float dot = 0.0f, q2 = 0.0f;
        #pragma unroll 4
        for (int d = 0; d < DDIM; d++) { dot += q[d] * m[d]; q2 += q[d] * q[d]; }
        float d2 = q2 - 2.0f * dot + g_y2[sel[tid]];
        dists[tid] = sqrtf(fmaxf(d2, 0.0f));
    }
    __syncthreads();
    if (tid == 0) {
        float mx = dists[0];
        for (int j = 1; j < KNEIGH; j++) mx = fmaxf(mx, dists[j]);
        float sum = 0.0f, e0 = 0.0f;
        for (int j = 0; j < KNEIGH; j++) {
            float e = expf(dists[j] - mx);
            if (j == 0) e0 = e;
            sum += e;
        }
        out[b] = (1.0f - e0 / sum) * g_score[b];
    }
}

// ---------------- bilinear upsample 28x28 -> 224x224, align_corners=False ----------------
__global__ void k_upsample() {
    int o = blockIdx.x * 256 + threadIdx.x;
    if (o >= BATCH * OUTSZ * OUTSZ) return;
    int b = o / (OUTSZ * OUTSZ);
    int r = o % (OUTSZ * OUTSZ);
    int U = r / OUTSZ;
    int V = r % OUTSZ;
    float su = ((float)U + 0.5f) * 0.125f - 0.5f;
    float sv = ((float)V + 0.5f) * 0.125f - 0.5f;
    int u0 = (int)floorf(su);
    int v0 = (int)floorf(sv);
    float tu = su - (float)u0;
    float tv = sv - (float)v0;
    int u0c = min(max(u0, 0), WIO - 1);
    int u1c = min(max(u0 + 1, 0), WIO - 1);
    int v0c = min(max(v0, 0), WIO - 1);
    int v1c = min(max(v0 + 1, 0), WIO - 1);
    const float* p = g_pscore + b * PPB;
    float v00 = p[u0c * WIO + v0c];
    float v01 = p[u0c * WIO + v1c];
    float v10 = p[u1c * WIO + v0c];
    float v11 = p[u1c * WIO + v1c];
    float top = v00 + tv * (v01 - v00);
    float bot = v10 + tv * (v11 - v10);
    g_umap[o] = top + tu * (bot - top);
}

// ---------------- separable Gaussian blur, reflect padding ----------------
__global__ void k_vblur() {
    int o = blockIdx.x * 256 + threadIdx.x;
    if (o >= BATCH * OUTSZ * OUTSZ) return;
    int b = o / (OUTSZ * OUTSZ);
    int r = o % (OUTSZ * OUTSZ);
    int U = r / OUTSZ;
    int V = r % OUTSZ;
    const float* base = g_umap + b * OUTSZ * OUTSZ;
    float acc = 0.0f;
    #pragma unroll
    for (int k = 0; k < KSIZE; k++) {
        int i = U - KRAD + k;
        if (i < 0) i = -i;
        if (i > OUTSZ - 1) i = 2 * (OUTSZ - 1) - i;
        acc += g_gauss[k] * base[i * OUTSZ + V];
    }
    g_vtmp[o] = acc;
}

__global__ void k_hblur(float* __restrict__ out) {
    int o = blockIdx.x * 256 + threadIdx.x;
    if (o >= BATCH * OUTSZ * OUTSZ) return;
    int b = o / (OUTSZ * OUTSZ);
    int r = o % (OUTSZ * OUTSZ);
    int U = r / OUTSZ;
    int V = r % OUTSZ;
    const float* base = g_vtmp + b * OUTSZ * OUTSZ + U * OUTSZ;
    float acc = 0.0f;
    #pragma unroll
    for (int k = 0; k < KSIZE; k++) {
        int j = V - KRAD + k;
        if (j < 0) j = -j;
        if (j > OUTSZ - 1) j = 2 * (OUTSZ - 1) - j;
        acc += g_gauss[k] * base[j];
    }
    out[BATCH + o] = acc;   // anomaly map after pred_score[0..7]
}

// ---------------- launcher ----------------
extern "C" void kernel_launch(void* const* d_in, const int* in_sizes, int n_in,
                              void* d_out, int out_size) {
    const float* emb = (const float*)d_in[0];
    const float* mb = (const float*)d_in[1];
    float* out = (float*)d_out;

    static bool attr_set = false;
    if (!attr_set) {
        cudaFuncSetAttribute(k_dist, cudaFuncAttributeMaxDynamicSharedMemorySize,
                             2 * BN * LDT * (int)sizeof(float));
        attr_set = true;
    }

    k_gauss_init<<<1, 32>>>();
    k_y2<<<MROWS / 8, 256>>>(mb);

    dim3 gdist(NROWS / BN, NSPLIT);
    k_dist<<<gdist, 256, 2 * BN * LDT * sizeof(float)>>>(emb, mb);

    k_reduce<<<(NROWS + 255) / 256, 256>>>(emb);
    k_imgmax<<<BATCH, 256>>>();

    dim3 gdnn(MROWS / 8, BATCH);
    k_dnn<<<gdnn, 256>>>(mb);

    k_final<<<BATCH, 256>>>(emb, mb, out);

    int nmap = BATCH * OUTSZ * OUTSZ;
    k_upsample<<<(nmap + 255) / 256, 256>>>();
    k_vblur<<<(nmap + 255) / 256, 256>>>();
    k_hblur<<<(nmap + 255) / 256, 256>>>(out);
}

// round 2
// speedup vs baseline: 1.6048x; 1.6048x over previous
#include <cuda_runtime.h>
#include <cuda_bf16.h>
#include <math.h>
#include <float.h>
#include <limits.h>
#include <stdint.h>

// ---------------- problem constants (fixed shapes) ----------------
#define NROWS 6272      // embedding rows
#define MROWS 32768     // memory bank rows
#define DDIM  128
#define BATCH 8
#define PPB   784       // patches per batch (28*28)
#define WIO   28
#define OUTSZ 224
#define KNEIGH 9
#define KSIZE 33
#define KRAD  16

#define NSPLIT 3
#define BNR 128         // emb rows per block
#define BMC 128         // mb cols per tile
#define NTILES (MROWS / BMC)   // 256

// ---------------- device scratch (no allocations allowed) ----------------
__device__ float g_y2[MROWS];                 // ||memory_bank[m]||^2
__device__ float g_pval[NSPLIT * NROWS];      // partial max of s
__device__ int   g_pidx[NSPLIT * NROWS];
__device__ float g_pscore[NROWS];             // patch scores (min dist)
__device__ int   g_ploc[NROWS];               // argmin locations
__device__ int   g_qrow[BATCH];               // global emb row of max patch
__device__ float g_score[BATCH];
__device__ int   g_nnidx[BATCH];
__device__ float g_dnn[BATCH * MROWS];
__device__ float g_gauss[KSIZE];
__device__ float g_umap[BATCH * OUTSZ * OUTSZ];
__device__ float g_vtmp[BATCH * OUTSZ * OUTSZ];

// ---------------- gaussian kernel init ----------------
__global__ void k_gauss_init() {
    if (threadIdx.x == 0) {
        float tmp[KSIZE];
        float s = 0.0f;
        for (int i = 0; i < KSIZE; i++) {
            float x = (float)i - (float)(KSIZE - 1) * 0.5f;
            float t = x / 4.0f;
            tmp[i] = expf(-0.5f * t * t);
            s += tmp[i];
        }
        for (int i = 0; i < KSIZE; i++) g_gauss[i] = tmp[i] / s;
    }
}

// ---------------- memory bank row norms ----------------
__global__ void k_y2(const float* __restrict__ mb) {
    int warp = threadIdx.x >> 5;
    int lane = threadIdx.x & 31;
    int row = blockIdx.x * 8 + warp;
    if (row >= MROWS) return;
    float4 v = reinterpret_cast<const float4*>(mb + (size_t)row * DDIM)[lane];
    float s = v.x * v.x + v.y * v.y + v.z * v.z + v.w * v.w;
    #pragma unroll
    for (int o = 16; o > 0; o >>= 1) s += __shfl_xor_sync(0xFFFFFFFF, s, o);
    if (lane == 0) g_y2[row] = s;
}

// ---------------- fused distance GEMM (FFMA2 packed fp32) + argmax ----------------
// Block: 256 threads (16x16). Block tile: 128 emb rows x 128 mb cols.
// Thread micro-tile: 8 rows (8*ty..+7) x 8 cols (tx+16j), accumulators packed
// as f32x2 over row pairs. A and B stored TRANSPOSED (d-major) in smem.
extern __shared__ float s_mem[];

__global__ void __launch_bounds__(256) k_dist(const float* __restrict__ emb,
                                              const float* __restrict__ mb) {
    float* sAt = s_mem;                   // [d][r]  128 x 128
    float* sBt = s_mem + DDIM * BNR;      // [d][c]  128 x 128

    const int tid = threadIdx.x;
    const int tx = tid & 15;
    const int ty = tid >> 4;
    const int rowBase = blockIdx.x * BNR;

    int tile0, tile1;
    if (blockIdx.y == 0)      { tile0 = 0;   tile1 = 86;  }
    else if (blockIdx.y == 1) { tile0 = 86;  tile1 = 171; }
    else                      { tile0 = 171; tile1 = NTILES; }

    // --- load A tile transposed: sAt[d*128 + r] = emb[rowBase+r][d] ---
    #pragma unroll
    for (int k = 0; k < 16; k++) {
        int idx = k * 256 + tid;
        int r = idx & 127;
        int d4 = (idx >> 7) << 2;
        float4 v = *reinterpret_cast<const float4*>(emb + (size_t)(rowBase + r) * DDIM + d4);
        sAt[(d4 + 0) * BNR + r] = v.x;
        sAt[(d4 + 1) * BNR + r] = v.y;
        sAt[(d4 + 2) * BNR + r] = v.z;
        sAt[(d4 + 3) * BNR + r] = v.w;
    }

    // shared-space base addresses
    uint32_t sbase;
    asm("{ .reg .u64 t; cvta.to.shared.u64 t, %1; cvt.u32.u64 %0, t; }"
        : "=r"(sbase) : "l"(s_mem));
    const uint32_t aBase = sbase + (uint32_t)(8 * ty) * 4u;
    const uint32_t bBase = sbase + (uint32_t)(DDIM * BNR) * 4u + (uint32_t)tx * 4u;

    float bestV[8];
    int bestI[8];
    #pragma unroll
    for (int i = 0; i < 8; i++) { bestV[i] = -FLT_MAX; bestI[i] = INT_MAX; }

    for (int t = tile0; t < tile1; t++) {
        __syncthreads();   // protect sBt from previous iteration's readers
        const int col0 = t * BMC;
        // --- load B tile transposed: sBt[d*128 + c] = mb[col0+c][d] ---
        #pragma unroll
        for (int k = 0; k < 16; k++) {
            int idx = k * 256 + tid;
            int c = idx & 127;
            int d4 = (idx >> 7) << 2;
            float4 v = *reinterpret_cast<const float4*>(mb + (size_t)(col0 + c) * DDIM + d4);
            sBt[(d4 + 0) * BMC + c] = v.x;
            sBt[(d4 + 1) * BMC + c] = v.y;
            sBt[(d4 + 2) * BMC + c] = v.z;
            sBt[(d4 + 3) * BMC + c] = v.w;
        }
        __syncthreads();

        unsigned long long acc[4][8];
        #pragma unroll
        for (int pi = 0; pi < 4; pi++)
            #pragma unroll
            for (int j = 0; j < 8; j++) acc[pi][j] = 0ull;

        uint32_t aA = aBase;
        uint32_t bA = bBase;
        #pragma unroll 2
        for (int d = 0; d < DDIM; d++) {
            unsigned long long ap[4];
            asm("ld.shared.v2.b64 {%0,%1}, [%2];"
                : "=l"(ap[0]), "=l"(ap[1]) : "r"(aA));
            asm("ld.shared.v2.b64 {%0,%1}, [%2];"
                : "=l"(ap[2]), "=l"(ap[3]) : "r"(aA + 16u));

            unsigned long long bd[8];
            #pragma unroll
            for (int j = 0; j < 8; j++) {
                uint32_t bu;
                asm("ld.shared.b32 %0, [%1];" : "=r"(bu) : "r"(bA + (uint32_t)(j * 64)));
                asm("mov.b64 %0, {%1,%1};" : "=l"(bd[j]) : "r"(bu));
            }

            #pragma unroll
            for (int pi = 0; pi < 4; pi++)
                #pragma unroll
                for (int j = 0; j < 8; j++)
                    asm("fma.rn.f32x2 %0, %1, %2, %0;"
                        : "+l"(acc[pi][j]) : "l"(ap[pi]), "l"(bd[j]));

            aA += BNR * 4u;
            bA += BMC * 4u;
        }

        // --- per-tile epilogue: s = dot - 0.5*||y||^2, running argmax ---
        #pragma unroll
        for (int j = 0; j < 8; j++) {
            int col = col0 + tx + 16 * j;
            float hy2 = 0.5f * g_y2[col];
            #pragma unroll
            for (int pi = 0; pi < 4; pi++) {
                uint32_t lo, hi;
                asm("mov.b64 {%0,%1}, %2;" : "=r"(lo), "=r"(hi) : "l"(acc[pi][j]));
                float s0 = __uint_as_float(lo) - hy2;
                float s1 = __uint_as_float(hi) - hy2;
                int i0 = 2 * pi, i1 = 2 * pi + 1;
                if (s0 > bestV[i0] || (s0 == bestV[i0] && col < bestI[i0])) {
                    bestV[i0] = s0; bestI[i0] = col;
                }
                if (s1 > bestV[i1] || (s1 == bestV[i1] && col < bestI[i1])) {
                    bestV[i1] = s1; bestI[i1] = col;
                }
            }
        }
    }

    // --- block-level reduce per row across the 16 tx lanes (reuse sAt) ---
    __syncthreads();
    float* sRv = s_mem;                                    // 128*16 floats
    int* sRi = reinterpret_cast<int*>(s_mem + BNR * 16);
    #pragma unroll
    for (int i = 0; i < 8; i++) {
        int r = 8 * ty + i;
        sRv[r * 16 + tx] = bestV[i];
        sRi[r * 16 + tx] = bestI[i];
    }
    __syncthreads();
    if (tid < BNR) {
        float bv = -FLT_MAX; int bi = INT_MAX;
        #pragma unroll
        for (int x = 0; x < 16; x++) {
            float v = sRv[tid * 16 + x];
            int ii = sRi[tid * 16 + x];
            if (v > bv || (v == bv && ii < bi)) { bv = v; bi = ii; }
        }
        int row = rowBase + tid;
        g_pval[blockIdx.y * NROWS + row] = bv;
        g_pidx[blockIdx.y * NROWS + row] = bi;
    }
}

// ---------------- combine split partials -> patch scores + locations ----------------
__global__ void k_reduce(const float* __restrict__ emb) {
    int row = blockIdx.x * 256 + threadIdx.x;
    if (row >= NROWS) return;
    float bv = -FLT_MAX; int bi = INT_MAX;
    #pragma unroll
    for (int s = 0; s < NSPLIT; s++) {
        float v = g_pval[s * NROWS + row];
        int ii = g_pidx[s * NROWS + row];
        if (v > bv || (v == bv && ii < bi)) { bv = v; bi = ii; }
    }
    float x2 = 0.0f;
    const float4* e = reinterpret_cast<const float4*>(emb + (size_t)row * DDIM);
    #pragma unroll
    for (int d = 0; d < DDIM / 4; d++) {
        float4 v = e[d];
        x2 += v.x * v.x + v.y * v.y + v.z * v.z + v.w * v.w;
    }
    float d2 = x2 - 2.0f * bv;
    g_pscore[row] = sqrtf(fmaxf(d2, 0.0f));
    g_ploc[row] = bi;
}

// ---------------- per-image argmax patch ----------------
__global__ void k_imgmax() {
    int b = blockIdx.x;
    int tid = threadIdx.x;
    __shared__ float sv[256];
    __shared__ int si[256];
    float bv = -FLT_MAX; int bi = INT_MAX;
    for (int p = tid; p < PPB; p += 256) {
        float v = g_pscore[b * PPB + p];
        if (v > bv || (v == bv && p < bi)) { bv = v; bi = p; }
    }
    sv[tid] = bv; si[tid] = bi;
    __syncthreads();
    for (int s = 128; s > 0; s >>= 1) {
        if (tid < s) {
            if (sv[tid + s] > sv[tid] || (sv[tid + s] == sv[tid] && si[tid + s] < si[tid])) {
                sv[tid] = sv[tid + s]; si[tid] = si[tid + s];
            }
        }
        __syncthreads();
    }
    if (tid == 0) {
        g_score[b] = sv[0];
        g_qrow[b] = b * PPB + si[0];
        g_nnidx[b] = g_ploc[b * PPB + si[0]];
    }
}

// ---------------- d_nn = dist(memory_bank[nn_idx[b]], memory_bank) ----------------
__global__ void k_dnn(const float* __restrict__ mb) {
    int b = blockIdx.y;
    int warp = threadIdx.x >> 5;
    int lane = threadIdx.x & 31;
    int row = blockIdx.x * 8 + warp;
    int nn = g_nnidx[b];
    float4 q = reinterpret_cast<const float4*>(mb + (size_t)nn * DDIM)[lane];
    float4 m = reinterpret_cast<const float4*>(mb + (size_t)row * DDIM)[lane];
    float dot = q.x * m.x + q.y * m.y + q.z * m.z + q.w * m.w;
    #pragma unroll
    for (int o = 16; o > 0; o >>= 1) dot += __shfl_xor_sync(0xFFFFFFFF, dot, o);
    if (lane == 0) {
        float d2 = g_y2[nn] - 2.0f * dot + g_y2[row];
        g_dnn[b * MROWS + row] = sqrtf(fmaxf(d2, 0.0f));
    }
}

// ---------------- top-9 selection + softmax reweight -> pred_score ----------------
__global__ void k_final(const float* __restrict__ emb, const float* __restrict__ mb,
                        float* __restrict__ out) {
    int b = blockIdx.x;
    int tid = threadIdx.x;
    __shared__ float sv[256];
    __shared__ int si[256];
    __shared__ int sel[KNEIGH];
    __shared__ float dists[KNEIGH];

    for (int it = 0; it < KNEIGH; it++) {
        float bv = FLT_MAX; int bi = INT_MAX;
        for (int m = tid; m < MROWS; m += 256) {
            bool skip = false;
            for (int s2 = 0; s2 < it; s2++) if (sel[s2] == m) skip = true;
            if (skip) continue;
            float v = g_dnn[b * MROWS + m];
            if (v < bv || (v == bv && m < bi)) { bv = v; bi = m; }
        }
        sv[tid] = bv; si[tid] = bi;
        __syncthreads();
        for (int s = 128; s > 0; s >>= 1) {
            if (tid < s) {
                if (sv[tid + s] < sv[tid] || (sv[tid + s] == sv[tid] && si[tid + s] < si[tid])) {
                    sv[tid] = sv[tid + s]; si[tid] = si[tid + s];
                }
            }
            __syncthreads();
        }
        if (tid == 0) sel[it] = si[0];
        __syncthreads();
    }

    if (tid < KNEIGH) {
        const float* q = emb + (size_t)g_qrow[b] * DDIM;
        const float* m = mb + (size_t)sel[tid] * DDIM;
        float dot = 0.0f, q2 = 0.0f;
        #pragma unroll 4
        for (int d = 0; d < DDIM; d++) { dot += q[d] * m[d]; q2 += q[d] * q[d]; }
        float d2 = q2 - 2.0f * dot + g_y2[sel[tid]];
        dists[tid] = sqrtf(fmaxf(d2, 0.0f));
    }
    __syncthreads();
    if (tid == 0) {
        float mx = dists[0];
        for (int j = 1; j < KNEIGH; j++) mx = fmaxf(mx, dists[j]);
        float sum = 0.0f, e0 = 0.0f;
        for (int j = 0; j < KNEIGH; j++) {
            float e = expf(dists[j] - mx);
            if (j == 0) e0 = e;
            sum += e;
        }
        out[b] = (1.0f - e0 / sum) * g_score[b];
    }
}

// ---------------- bilinear upsample 28x28 -> 224x224, align_corners=False ----------------
__global__ void k_upsample() {
    int o = blockIdx.x * 256 + threadIdx.x;
    if (o >= BATCH * OUTSZ * OUTSZ) return;
    int b = o / (OUTSZ * OUTSZ);
    int r = o % (OUTSZ * OUTSZ);
    int U = r / OUTSZ;
    int V = r % OUTSZ;
    float su = ((float)U + 0.5f) * 0.125f - 0.5f;
    float sv = ((float)V + 0.5f) * 0.125f - 0.5f;
    int u0 = (int)floorf(su);
    int v0 = (int)floorf(sv);
    float tu = su - (float)u0;
    float tv = sv - (float)v0;
    int u0c = min(max(u0, 0), WIO - 1);
    int u1c = min(max(u0 + 1, 0), WIO - 1);
    int v0c = min(max(v0, 0), WIO - 1);
    int v1c = min(max(v0 + 1, 0), WIO - 1);
    const float* p = g_pscore + b * PPB;
    float v00 = p[u0c * WIO + v0c];
    float v01 = p[u0c * WIO + v1c];
    float v10 = p[u1c * WIO + v0c];
    float v11 = p[u1c * WIO + v1c];
    float top = v00 + tv * (v01 - v00);
    float bot = v10 + tv * (v11 - v10);
    g_umap[o] = top + tu * (bot - top);
}

// ---------------- separable Gaussian blur, reflect padding ----------------
__global__ void k_vblur() {
    int o = blockIdx.x * 256 + threadIdx.x;
    if (o >= BATCH * OUTSZ * OUTSZ) return;
    int b = o / (OUTSZ * OUTSZ);
    int r = o % (OUTSZ * OUTSZ);
    int U = r / OUTSZ;
    int V = r % OUTSZ;
    const float* base = g_umap + b * OUTSZ * OUTSZ;
    float acc = 0.0f;
    #pragma unroll
    for (int k = 0; k < KSIZE; k++) {
        int i = U - KRAD + k;
        if (i < 0) i = -i;
        if (i > OUTSZ - 1) i = 2 * (OUTSZ - 1) - i;
        acc += g_gauss[k] * base[i * OUTSZ + V];
    }
    g_vtmp[o] = acc;
}

__global__ void k_hblur(float* __restrict__ out) {
    int o = blockIdx.x * 256 + threadIdx.x;
    if (o >= BATCH * OUTSZ * OUTSZ) return;
    int b = o / (OUTSZ * OUTSZ);
    int r = o % (OUTSZ * OUTSZ);
    int U = r / OUTSZ;
    int V = r % OUTSZ;
    const float* base = g_vtmp + b * OUTSZ * OUTSZ + U * OUTSZ;
    float acc = 0.0f;
    #pragma unroll
    for (int k = 0; k < KSIZE; k++) {
        int j = V - KRAD + k;
        if (j < 0) j = -j;
        if (j > OUTSZ - 1) j = 2 * (OUTSZ - 1) - j;
        acc += g_gauss[k] * base[j];
    }
    out[BATCH + o] = acc;   // anomaly map after pred_score[0..7]
}

// ---------------- launcher ----------------
extern "C" void kernel_launch(void* const* d_in, const int* in_sizes, int n_in,
                              void* d_out, int out_size) {
    const float* emb = (const float*)d_in[0];
    const float* mb = (const float*)d_in[1];
    float* out = (float*)d_out;

    const int dist_smem = 2 * DDIM * BNR * (int)sizeof(float);  // 131072

    static bool attr_set = false;
    if (!attr_set) {
        cudaFuncSetAttribute(k_dist, cudaFuncAttributeMaxDynamicSharedMemorySize, dist_smem);
        attr_set = true;
    }

    k_gauss_init<<<1, 32>>>();
    k_y2<<<MROWS / 8, 256>>>(mb);

    dim3 gdist(NROWS / BNR, NSPLIT);
    k_dist<<<gdist, 256, dist_smem>>>(emb, mb);

    k_reduce<<<(NROWS + 255) / 256, 256>>>(emb);
    k_imgmax<<<BATCH, 256>>>();

    dim3 gdnn(MROWS / 8, BATCH);
    k_dnn<<<gdnn, 256>>>(mb);

    k_final<<<BATCH, 256>>>(emb, mb, out);

    int nmap = BATCH * OUTSZ * OUTSZ;
    k_upsample<<<(nmap + 255) / 256, 256>>>();
    k_vblur<<<(nmap + 255) / 256, 256>>>();
    k_hblur<<<(nmap + 255) / 256, 256>>>(out);
}

// round 4
// speedup vs baseline: 3.3315x; 2.0760x over previous
#include <cuda_runtime.h>
#include <cuda_bf16.h>
#include <math.h>
#include <float.h>
#include <limits.h>
#include <stdint.h>

// ---------------- problem constants (fixed shapes) ----------------
#define NROWS 6272      // embedding rows
#define MROWS 32768     // memory bank rows
#define DDIM  128
#define BATCH 8
#define PPB   784
#define WIO   28
#define OUTSZ 224
#define KNEIGH 9
#define KSIZE 33
#define KRAD  16

#define NSPLIT 3
#define BNR 128                 // emb rows per CTA
#define BMC 128                 // mb cols per tile
#define NTILES (MROWS / BMC)    // 256
#define LDTB 272                // smem tile row stride in bytes (136 bf16)
#define TILE_BYTES (128 * LDTB) // 34816

// smem byte offsets
#define OFF_AHI   0
#define OFF_ALO   (OFF_AHI + TILE_BYTES)
#define OFF_B0HI  (OFF_ALO + TILE_BYTES)
#define OFF_B0LO  (OFF_B0HI + TILE_BYTES)
#define OFF_B1HI  (OFF_B0LO + TILE_BYTES)
#define OFF_B1LO  (OFF_B1HI + TILE_BYTES)
#define OFF_Y2    (OFF_B1LO + TILE_BYTES)      // 2 x 128 floats (halved y2)
#define OFF_RED   (OFF_Y2 + 1024)              // 128*4 floats + 128*4 ints
#define SMEM_TOTAL (OFF_RED + 4096)            // 214016 bytes

// ---------------- device scratch ----------------
__device__ float g_y2[MROWS];
__device__ float g_y2h[MROWS];                // 0.5 * y2
__device__ float g_pval[NSPLIT * NROWS];
__device__ int   g_pidx[NSPLIT * NROWS];
__device__ float g_pscore[NROWS];
__device__ int   g_ploc[NROWS];
__device__ int   g_qrow[BATCH];
__device__ float g_score[BATCH];
__device__ int   g_nnidx[BATCH];
__device__ float g_dnn[BATCH * MROWS];
__device__ float g_gauss[KSIZE];
__device__ float g_umap[BATCH * OUTSZ * OUTSZ];
__device__ float g_vtmp[BATCH * OUTSZ * OUTSZ];
// bf16 2-way splits
__device__ __nv_bfloat16 g_embhi[NROWS * DDIM];
__device__ __nv_bfloat16 g_emblo[NROWS * DDIM];
__device__ __nv_bfloat16 g_mbhi[MROWS * DDIM];
__device__ __nv_bfloat16 g_mblo[MROWS * DDIM];

// ---------------- small helpers ----------------
__device__ __forceinline__ uint32_t smem_u32(const void* p) {
    uint32_t a;
    asm("{ .reg .u64 t; cvta.to.shared.u64 t, %1; cvt.u32.u64 %0, t; }" : "=r"(a) : "l"(p));
    return a;
}
__device__ __forceinline__ void cp_async16(uint32_t dst, const void* src) {
    asm volatile("cp.async.cg.shared.global [%0], [%1], 16;" :: "r"(dst), "l"(src));
}
#define CP_COMMIT() asm volatile("cp.async.commit_group;" ::: "memory")
#define CP_WAIT0()  asm volatile("cp.async.wait_group 0;" ::: "memory")

__device__ __forceinline__ void ldm_x4(uint32_t addr, uint32_t& r0, uint32_t& r1,
                                       uint32_t& r2, uint32_t& r3) {
    asm volatile("ldmatrix.sync.aligned.m8n8.x4.shared.b16 {%0,%1,%2,%3}, [%4];"
                 : "=r"(r0), "=r"(r1), "=r"(r2), "=r"(r3) : "r"(addr));
}
__device__ __forceinline__ void mma16816(float* c, const uint32_t* a, const uint32_t* b) {
    asm volatile("mma.sync.aligned.m16n8k16.row.col.f32.bf16.bf16.f32 "
                 "{%0,%1,%2,%3}, {%4,%5,%6,%7}, {%8,%9}, {%0,%1,%2,%3};"
                 : "+f"(c[0]), "+f"(c[1]), "+f"(c[2]), "+f"(c[3])
                 : "r"(a[0]), "r"(a[1]), "r"(a[2]), "r"(a[3]), "r"(b[0]), "r"(b[1]));
}

// ---------------- misc small kernels ----------------
__global__ void k_gauss_init() {
    if (threadIdx.x == 0) {
        float tmp[KSIZE]; float s = 0.0f;
        for (int i = 0; i < KSIZE; i++) {
            float x = (float)i - (float)(KSIZE - 1) * 0.5f;
            float t = x / 4.0f;
            tmp[i] = expf(-0.5f * t * t); s += tmp[i];
        }
        for (int i = 0; i < KSIZE; i++) g_gauss[i] = tmp[i] / s;
    }
}

__global__ void k_y2(const float* __restrict__ mb) {
    int warp = threadIdx.x >> 5, lane = threadIdx.x & 31;
    int row = blockIdx.x * 8 + warp;
    if (row >= MROWS) return;
    float4 v = reinterpret_cast<const float4*>(mb + (size_t)row * DDIM)[lane];
    float s = v.x * v.x + v.y * v.y + v.z * v.z + v.w * v.w;
    #pragma unroll
    for (int o = 16; o > 0; o >>= 1) s += __shfl_xor_sync(0xFFFFFFFF, s, o);
    if (lane == 0) { g_y2[row] = s; g_y2h[row] = 0.5f * s; }
}

// fp32 -> (hi, lo) bf16 split for both tensors
__global__ void k_split(const float* __restrict__ emb, const float* __restrict__ mb) {
    int i = blockIdx.x * 256 + threadIdx.x;
    if (i < NROWS * DDIM) {
        float x = emb[i];
        __nv_bfloat16 h = __float2bfloat16_rn(x);
        g_embhi[i] = h;
        g_emblo[i] = __float2bfloat16_rn(x - __bfloat162float(h));
    }
    if (i < MROWS * DDIM) {
        float x = mb[i];
        __nv_bfloat16 h = __float2bfloat16_rn(x);
        g_mbhi[i] = h;
        g_mblo[i] = __float2bfloat16_rn(x - __bfloat162float(h));
    }
}

// ---------------- mma.sync fused distance GEMM + argmax ----------------
extern __shared__ char s_raw[];

__device__ __forceinline__ void load_tile_async(uint32_t sm_dst,
                                                const __nv_bfloat16* __restrict__ src,
                                                int row0, int tid) {
    #pragma unroll
    for (int k = 0; k < 8; k++) {
        int i = k * 256 + tid;      // 0..2047
        int r = i >> 4;             // 0..127
        int c = i & 15;             // 16B chunk within 256B row
        cp_async16(sm_dst + (uint32_t)(r * LDTB + c * 16),
                   (const char*)(src + (size_t)(row0 + r) * DDIM) + c * 16);
    }
}

__global__ void __launch_bounds__(256, 1) k_dist_mma() {
    char* smem = s_raw;
    const uint32_t sbase = smem_u32(smem);
    const int tid = threadIdx.x;
    const int wid = tid >> 5;
    const int lane = tid & 31;
    const int wm = wid & 1;          // M half (0/1): rows wm*64..+63
    const int wn = wid >> 1;         // N quarter (0..3): cols wn*32..+31
    const int rowBase = blockIdx.x * BNR;

    int tile0, tile1;
    if (blockIdx.y == 0)      { tile0 = 0;   tile1 = 86;  }
    else if (blockIdx.y == 1) { tile0 = 86;  tile1 = 171; }
    else                      { tile0 = 171; tile1 = NTILES; }

    const uint32_t Ahi = sbase + OFF_AHI;
    const uint32_t Alo = sbase + OFF_ALO;
    const uint32_t Bhi[2] = { sbase + OFF_B0HI, sbase + OFF_B1HI };
    const uint32_t Blo[2] = { sbase + OFF_B0LO, sbase + OFF_B1LO };
    float* y2s = reinterpret_cast<float*>(smem + OFF_Y2);

    // per-thread ldmatrix lane addressing offsets
    const int a_row = lane & 15;
    const int a_koff = (lane >> 4) << 3;
    const uint32_t aOff = (uint32_t)((wm * 64 + a_row) * LDTB + a_koff * 2);
    const int b_n = (lane & 7) + ((lane >> 4) << 3);
    const int b_koff = ((lane >> 3) & 1) << 3;
    const uint32_t bOff = (uint32_t)((wn * 32 + b_n) * LDTB + b_koff * 2);

    // prologue loads: A hi/lo, B tile0 hi/lo, y2 tile0
    load_tile_async(Ahi, g_embhi, rowBase, tid);
    load_tile_async(Alo, g_emblo, rowBase, tid);
    load_tile_async(Bhi[0], g_mbhi, tile0 * BMC, tid);
    load_tile_async(Blo[0], g_mblo, tile0 * BMC, tid);
    if (tid < 32)
        cp_async16(sbase + OFF_Y2 + tid * 16, (const char*)(g_y2h + tile0 * BMC) + tid * 16);
    CP_COMMIT();
    CP_WAIT0();
    __syncthreads();

    float bestV[8];
    int   bestI[8];
    #pragma unroll
    for (int i = 0; i < 8; i++) { bestV[i] = -FLT_MAX; bestI[i] = INT_MAX; }

    for (int t = tile0; t < tile1; t++) {
        const int buf = (t - tile0) & 1;

        // prefetch next B tile + y2
        if (t + 1 < tile1) {
            const int nb = buf ^ 1;
            load_tile_async(Bhi[nb], g_mbhi, (t + 1) * BMC, tid);
            load_tile_async(Blo[nb], g_mblo, (t + 1) * BMC, tid);
            if (tid < 32)
                cp_async16(sbase + OFF_Y2 + (uint32_t)(nb * 512 + tid * 16),
                           (const char*)(g_y2h + (size_t)(t + 1) * BMC) + tid * 16);
            CP_COMMIT();
        }

        // ---- compute: 3 passes x 8 k-chunks of the 128x128 tile ----
        float acc[4][4][4];
        #pragma unroll
        for (int mf = 0; mf < 4; mf++)
            #pragma unroll
            for (int nf = 0; nf < 4; nf++)
                #pragma unroll
                for (int r = 0; r < 4; r++) acc[mf][nf][r] = 0.0f;

        #pragma unroll
        for (int p = 0; p < 3; p++) {
            const uint32_t aB = ((p == 1) ? Alo : Ahi) + aOff;
            const uint32_t bB = ((p == 2) ? Blo[buf] : Bhi[buf]) + bOff;
            #pragma unroll
            for (int kc = 0; kc < 8; kc++) {
                const uint32_t kByte = (uint32_t)(kc << 5);   // kc*16 bf16 = 32B
                uint32_t af[4][4];
                #pragma unroll
                for (int mf = 0; mf < 4; mf++)
                    ldm_x4(aB + (uint32_t)(mf * 16 * LDTB) + kByte,
                           af[mf][0], af[mf][1], af[mf][2], af[mf][3]);
                uint32_t bf[4][2];
                #pragma unroll
                for (int q = 0; q < 2; q++) {
                    uint32_t r0, r1, r2, r3;
                    ldm_x4(bB + (uint32_t)(q * 16 * LDTB) + kByte, r0, r1, r2, r3);
                    bf[q * 2][0] = r0; bf[q * 2][1] = r1;
                    bf[q * 2 + 1][0] = r2; bf[q * 2 + 1][1] = r3;
                }
                #pragma unroll
                for (int mf = 0; mf < 4; mf++)
                    #pragma unroll
                    for (int nf = 0; nf < 4; nf++)
                        mma16816(acc[mf][nf], af[mf], bf[nf]);
            }
        }

        // ---- epilogue: s = dot - 0.5*y2, running argmax ----
        {
            const float* hy = y2s + buf * 128;
            float hv[4][2];
            #pragma unroll
            for (int nf = 0; nf < 4; nf++) {
                int cl = wn * 32 + nf * 8 + (lane & 3) * 2;
                hv[nf][0] = hy[cl];
                hv[nf][1] = hy[cl + 1];
            }
            const int cg0 = t * BMC + wn * 32 + (lane & 3) * 2;
            #pragma unroll
            for (int mf = 0; mf < 4; mf++) {
                #pragma unroll
                for (int h = 0; h < 2; h++) {
                    const int slot = mf * 2 + h;
                    float bv = bestV[slot]; int bi = bestI[slot];
                    #pragma unroll
                    for (int nf = 0; nf < 4; nf++) {
                        float s0 = acc[mf][nf][h * 2] - hv[nf][0];
                        float s1 = acc[mf][nf][h * 2 + 1] - hv[nf][1];
                        int c0 = cg0 + nf * 8;
                        if (s0 > bv) { bv = s0; bi = c0; }
                        if (s1 > bv) { bv = s1; bi = c0 + 1; }
                    }
                    bestV[slot] = bv; bestI[slot] = bi;
                }
            }
        }

        if (t + 1 < tile1) CP_WAIT0();
        __syncthreads();
    }

    // ---- reduce: quad lanes share rows, then across the 4 N-warps ----
    float* redV = reinterpret_cast<float*>(smem + OFF_RED);
    int*   redI = reinterpret_cast<int*>(smem + OFF_RED + 2048);
    #pragma unroll
    for (int slot = 0; slot < 8; slot++) {
        float v = bestV[slot]; int idx = bestI[slot];
        #pragma unroll
        for (int off = 1; off <= 2; off <<= 1) {
            float ov = __shfl_xor_sync(0xFFFFFFFF, v, off);
            int oi = __shfl_xor_sync(0xFFFFFFFF, idx, off);
            if (ov > v || (ov == v && oi < idx)) { v = ov; idx = oi; }
        }
        if ((lane & 3) == 0) {
            int mf = slot >> 1, h = slot & 1;
            int row = wm * 64 + mf * 16 + (lane >> 2) + h * 8;
            redV[row * 4 + wn] = v;
            redI[row * 4 + wn] = idx;
        }
    }
    __syncthreads();
    if (tid < BNR) {
        float bv = -FLT_MAX; int bi = INT_MAX;
        #pragma unroll
        for (int w = 0; w < 4; w++) {
            float v = redV[tid * 4 + w];
            int ii = redI[tid * 4 + w];
            if (v > bv || (v == bv && ii < bi)) { bv = v; bi = ii; }
        }
        g_pval[blockIdx.y * NROWS + rowBase + tid] = bv;
        g_pidx[blockIdx.y * NROWS + rowBase + tid] = bi;
    }
}

// ---------------- combine split partials -> patch scores ----------------
__global__ void k_reduce(const float* __restrict__ emb) {
    int row = blockIdx.x * 256 + threadIdx.x;
    if (row >= NROWS) return;
    float bv = -FLT_MAX; int bi = INT_MAX;
    #pragma unroll
    for (int s = 0; s < NSPLIT; s++) {
        float v = g_pval[s * NROWS + row];
        int ii = g_pidx[s * NROWS + row];
        if (v > bv || (v == bv && ii < bi)) { bv = v; bi = ii; }
    }
    float x2 = 0.0f;
    const float4* e = reinterpret_cast<const float4*>(emb + (size_t)row * DDIM);
    #pragma unroll
    for (int d = 0; d < DDIM / 4; d++) {
        float4 v = e[d];
        x2 += v.x * v.x + v.y * v.y + v.z * v.z + v.w * v.w;
    }
    float d2 = x2 - 2.0f * bv;
    g_pscore[row] = sqrtf(fmaxf(d2, 0.0f));
    g_ploc[row] = bi;
}

__global__ void k_imgmax() {
    int b = blockIdx.x, tid = threadIdx.x;
    __shared__ float sv[256]; __shared__ int si[256];
    float bv = -FLT_MAX; int bi = INT_MAX;
    for (int p = tid; p < PPB; p += 256) {
        float v = g_pscore[b * PPB + p];
        if (v > bv || (v == bv && p < bi)) { bv = v; bi = p; }
    }
    sv[tid] = bv; si[tid] = bi;
    __syncthreads();
    for (int s = 128; s > 0; s >>= 1) {
        if (tid < s) {
            if (sv[tid + s] > sv[tid] || (sv[tid + s] == sv[tid] && si[tid + s] < si[tid])) {
                sv[tid] = sv[tid + s]; si[tid] = si[tid + s];
            }
        }
        __syncthreads();
    }
    if (tid == 0) {
        g_score[b] = sv[0];
        g_qrow[b] = b * PPB + si[0];
        g_nnidx[b] = g_ploc[b * PPB + si[0]];
    }
}

__global__ void k_dnn(const float* __restrict__ mb) {
    int b = blockIdx.y;
    int warp = threadIdx.x >> 5, lane = threadIdx.x & 31;
    int row = blockIdx.x * 8 + warp;
    int nn = g_nnidx[b];
    float4 q = reinterpret_cast<const float4*>(mb + (size_t)nn * DDIM)[lane];
    float4 m = reinterpret_cast<const float4*>(mb + (size_t)row * DDIM)[lane];
    float dot = q.x * m.x + q.y * m.y + q.z * m.z + q.w * m.w;
    #pragma unroll
    for (int o = 16; o > 0; o >>= 1) dot += __shfl_xor_sync(0xFFFFFFFF, dot, o);
    if (lane == 0) {
        float d2 = g_y2[nn] - 2.0f * dot + g_y2[row];
        g_dnn[b * MROWS + row] = sqrtf(fmaxf(d2, 0.0f));
    }
}

__global__ void k_final(const float* __restrict__ emb, const float* __restrict__ mb,
                        float* __restrict__ out) {
    int b = blockIdx.x, tid = threadIdx.x;
    __shared__ float sv[256]; __shared__ int si[256];
    __shared__ int sel[KNEIGH]; __shared__ float dists[KNEIGH];

    for (int it = 0; it < KNEIGH; it++) {
        float bv = FLT_MAX; int bi = INT_MAX;
        for (int m = tid; m < MROWS; m += 256) {
            bool skip = false;
            for (int s2 = 0; s2 < it; s2++) if (sel[s2] == m) skip = true;
            if (skip) continue;
            float v = g_dnn[b * MROWS + m];
            if (v < bv || (v == bv && m < bi)) { bv = v; bi = m; }
        }
        sv[tid] = bv; si[tid] = bi;
        __syncthreads();
        for (int s = 128; s > 0; s >>= 1) {
            if (tid < s) {
                if (sv[tid + s] < sv[tid] || (sv[tid + s] == sv[tid] && si[tid + s] < si[tid])) {
                    sv[tid] = sv[tid + s]; si[tid] = si[tid + s];
                }
            }
            __syncthreads();
        }
        if (tid == 0) sel[it] = si[0];
        __syncthreads();
    }

    if (tid < KNEIGH) {
        const float* q = emb + (size_t)g_qrow[b] * DDIM;
        const float* m = mb + (size_t)sel[tid] * DDIM;
        float dot = 0.0f, q2 = 0.0f;
        #pragma unroll 4
        for (int d = 0; d < DDIM; d++) { dot += q[d] * m[d]; q2 += q[d] * q[d]; }
        float d2 = q2 - 2.0f * dot + g_y2[sel[tid]];
        dists[tid] = sqrtf(fmaxf(d2, 0.0f));
    }
    __syncthreads();
    if (tid == 0) {
        float mx = dists[0];
        for (int j = 1; j < KNEIGH; j++) mx = fmaxf(mx, dists[j]);
        float sum = 0.0f, e0 = 0.0f;
        for (int j = 0; j < KNEIGH; j++) {
            float e = expf(dists[j] - mx);
            if (j == 0) e0 = e;
            sum += e;
        }
        out[b] = (1.0f - e0 / sum) * g_score[b];
    }
}

__global__ void k_upsample() {
    int o = blockIdx.x * 256 + threadIdx.x;
    if (o >= BATCH * OUTSZ * OUTSZ) return;
    int b = o / (OUTSZ * OUTSZ), r = o % (OUTSZ * OUTSZ);
    int U = r / OUTSZ, V = r % OUTSZ;
    float su = ((float)U + 0.5f) * 0.125f - 0.5f;
    float sv = ((float)V + 0.5f) * 0.125f - 0.5f;
    int u0 = (int)floorf(su), v0 = (int)floorf(sv);
    float tu = su - (float)u0, tv = sv - (float)v0;
    int u0c = min(max(u0, 0), WIO - 1), u1c = min(max(u0 + 1, 0), WIO - 1);
    int v0c = min(max(v0, 0), WIO - 1), v1c = min(max(v0 + 1, 0), WIO - 1);
    const float* p = g_pscore + b * PPB;
    float v00 = p[u0c * WIO + v0c], v01 = p[u0c * WIO + v1c];
    float v10 = p[u1c * WIO + v0c], v11 = p[u1c * WIO + v1c];
    float top = v00 + tv * (v01 - v00);
    float bot = v10 + tv * (v11 - v10);
    g_umap[o] = top + tu * (bot - top);
}

__global__ void k_vblur() {
    int o = blockIdx.x * 256 + threadIdx.x;
    if (o >= BATCH * OUTSZ * OUTSZ) return;
    int b = o / (OUTSZ * OUTSZ), r = o % (OUTSZ * OUTSZ);
    int U = r / OUTSZ, V = r % OUTSZ;
    const float* base = g_umap + b * OUTSZ * OUTSZ;
    float acc = 0.0f;
    #pragma unroll
    for (int k = 0; k < KSIZE; k++) {
        int i = U - KRAD + k;
        if (i < 0) i = -i;
        if (i > OUTSZ - 1) i = 2 * (OUTSZ - 1) - i;
        acc += g_gauss[k] * base[i * OUTSZ + V];
    }
    g_vtmp[o] = acc;
}

__global__ void k_hblur(float* __restrict__ out) {
    int o = blockIdx.x * 256 + threadIdx.x;
    if (o >= BATCH * OUTSZ * OUTSZ) return;
    int b = o / (OUTSZ * OUTSZ), r = o % (OUTSZ * OUTSZ);
    int U = r / OUTSZ, V = r % OUTSZ;
    const float* base = g_vtmp + b * OUTSZ * OUTSZ + U * OUTSZ;
    float acc = 0.0f;
    #pragma unroll
    for (int k = 0; k < KSIZE; k++) {
        int j = V - KRAD + k;
        if (j < 0) j = -j;
        if (j > OUTSZ - 1) j = 2 * (OUTSZ - 1) - j;
        acc += g_gauss[k] * base[j];
    }
    out[BATCH + o] = acc;
}

// ---------------- launcher ----------------
extern "C" void kernel_launch(void* const* d_in, const int* in_sizes, int n_in,
                              void* d_out, int out_size) {
    const float* emb = (const float*)d_in[0];
    const float* mb = (const float*)d_in[1];
    float* out = (float*)d_out;

    static bool attr_set = false;
    if (!attr_set) {
        cudaFuncSetAttribute(k_dist_mma, cudaFuncAttributeMaxDynamicSharedMemorySize, SMEM_TOTAL);
        attr_set = true;
    }

    k_gauss_init<<<1, 32>>>();
    k_y2<<<MROWS / 8, 256>>>(mb);
    k_split<<<(MROWS * DDIM + 255) / 256, 256>>>(emb, mb);

    dim3 gdist(NROWS / BNR, NSPLIT);
    k_dist_mma<<<gdist, 256, SMEM_TOTAL>>>();

    k_reduce<<<(NROWS + 255) / 256, 256>>>(emb);
    k_imgmax<<<BATCH, 256>>>();

    dim3 gdnn(MROWS / 8, BATCH);
    k_dnn<<<gdnn, 256>>>(mb);

    k_final<<<BATCH, 256>>>(emb, mb, out);

    int nmap = BATCH * OUTSZ * OUTSZ;
    k_upsample<<<(nmap + 255) / 256, 256>>>();
    k_vblur<<<(nmap + 255) / 256, 256>>>();
    k_hblur<<<(nmap + 255) / 256, 256>>>(out);
}

// round 5
// speedup vs baseline: 4.9003x; 1.4709x over previous
#include <cuda_runtime.h>
#include <cuda_bf16.h>
#include <math.h>
#include <float.h>
#include <limits.h>
#include <stdint.h>

// ---------------- problem constants (fixed shapes) ----------------
#define NROWS 6272      // embedding rows
#define MROWS 32768     // memory bank rows
#define DDIM  128
#define KDIM  256       // concatenated hi||lo
#define BATCH 8
#define PPB   784
#define WIO   28
#define OUTSZ 224
#define KNEIGH 9
#define KSIZE 33
#define KRAD  16

#define NSPLIT 3
#define BNR 128                 // emb rows per CTA
#define BMC 128                 // mb cols per tile
#define NTILES (MROWS / BMC)    // 256
#define LDTB 528                // smem tile row stride bytes (264 bf16; 132 words ≡ 4 mod 32)
#define TILE_BYTES (128 * LDTB) // 67584

// smem byte offsets
#define OFF_A     0
#define OFF_B0    (OFF_A + TILE_BYTES)
#define OFF_B1    (OFF_B0 + TILE_BYTES)
#define OFF_Y2    (OFF_B1 + TILE_BYTES)        // 2 x 128 floats (halved y2)
#define OFF_RED   (OFF_Y2 + 1024)              // 128*4 floats + 128*4 ints
#define SMEM_TOTAL (OFF_RED + 4096)            // 207872 bytes

// ---------------- device scratch ----------------
__device__ float g_y2[MROWS];
__device__ float g_y2h[MROWS];                // 0.5 * y2
__device__ float g_pval[NSPLIT * NROWS];
__device__ int   g_pidx[NSPLIT * NROWS];
__device__ float g_pscore[NROWS];
__device__ int   g_ploc[NROWS];
__device__ int   g_qrow[BATCH];
__device__ float g_score[BATCH];
__device__ int   g_nnidx[BATCH];
__device__ float g_dnn[BATCH * MROWS];
__device__ float g_gauss[KSIZE];
__device__ float g_umap[BATCH * OUTSZ * OUTSZ];
__device__ float g_vtmp[BATCH * OUTSZ * OUTSZ];
// bf16 split, K-concatenated: row = [hi(128) || lo(128)]
__device__ __nv_bfloat16 g_embcat[NROWS * KDIM];
__device__ __nv_bfloat16 g_mbcat[MROWS * KDIM];

// ---------------- small helpers ----------------
__device__ __forceinline__ uint32_t smem_u32(const void* p) {
    uint32_t a;
    asm("{ .reg .u64 t; cvta.to.shared.u64 t, %1; cvt.u32.u64 %0, t; }" : "=r"(a) : "l"(p));
    return a;
}
__device__ __forceinline__ void cp_async16(uint32_t dst, const void* src) {
    asm volatile("cp.async.cg.shared.global [%0], [%1], 16;" :: "r"(dst), "l"(src));
}
#define CP_COMMIT() asm volatile("cp.async.commit_group;" ::: "memory")
#define CP_WAIT0()  asm volatile("cp.async.wait_group 0;" ::: "memory")

__device__ __forceinline__ void ldm_x4(uint32_t addr, uint32_t& r0, uint32_t& r1,
                                       uint32_t& r2, uint32_t& r3) {
    asm volatile("ldmatrix.sync.aligned.m8n8.x4.shared.b16 {%0,%1,%2,%3}, [%4];"
                 : "=r"(r0), "=r"(r1), "=r"(r2), "=r"(r3) : "r"(addr));
}
__device__ __forceinline__ void mma16816(float* c, const uint32_t* a, const uint32_t* b) {
    asm volatile("mma.sync.aligned.m16n8k16.row.col.f32.bf16.bf16.f32 "
                 "{%0,%1,%2,%3}, {%4,%5,%6,%7}, {%8,%9}, {%0,%1,%2,%3};"
                 : "+f"(c[0]), "+f"(c[1]), "+f"(c[2]), "+f"(c[3])
                 : "r"(a[0]), "r"(a[1]), "r"(a[2]), "r"(a[3]), "r"(b[0]), "r"(b[1]));
}

// ---------------- misc small kernels ----------------
__global__ void k_gauss_init() {
    if (threadIdx.x == 0) {
        float tmp[KSIZE]; float s = 0.0f;
        for (int i = 0; i < KSIZE; i++) {
            float x = (float)i - (float)(KSIZE - 1) * 0.5f;
            float t = x / 4.0f;
            tmp[i] = expf(-0.5f * t * t); s += tmp[i];
        }
        for (int i = 0; i < KSIZE; i++) g_gauss[i] = tmp[i] / s;
    }
}

__global__ void k_y2(const float* __restrict__ mb) {
    int warp = threadIdx.x >> 5, lane = threadIdx.x & 31;
    int row = blockIdx.x * 8 + warp;
    if (row >= MROWS) return;
    float4 v = reinterpret_cast<const float4*>(mb + (size_t)row * DDIM)[lane];
    float s = v.x * v.x + v.y * v.y + v.z * v.z + v.w * v.w;
    #pragma unroll
    for (int o = 16; o > 0; o >>= 1) s += __shfl_xor_sync(0xFFFFFFFF, s, o);
    if (lane == 0) { g_y2[row] = s; g_y2h[row] = 0.5f * s; }
}

// fp32 -> [hi || lo] bf16 concat rows
__global__ void k_split(const float* __restrict__ emb, const float* __restrict__ mb) {
    int i = blockIdx.x * 256 + threadIdx.x;
    if (i < NROWS * DDIM) {
        int r = i >> 7, c = i & 127;
        float x = emb[i];
        __nv_bfloat16 h = __float2bfloat16_rn(x);
        g_embcat[(size_t)r * KDIM + c] = h;
        g_embcat[(size_t)r * KDIM + 128 + c] = __float2bfloat16_rn(x - __bfloat162float(h));
    }
    if (i < MROWS * DDIM) {
        int r = i >> 7, c = i & 127;
        float x = mb[i];
        __nv_bfloat16 h = __float2bfloat16_rn(x);
        g_mbcat[(size_t)r * KDIM + c] = h;
        g_mbcat[(size_t)r * KDIM + 128 + c] = __float2bfloat16_rn(x - __bfloat162float(h));
    }
}

// ---------------- mma.sync fused distance GEMM (K=256) + argmax ----------------
extern __shared__ char s_raw[];

__device__ __forceinline__ void load_tile_async(uint32_t sm_dst,
                                                const __nv_bfloat16* __restrict__ src,
                                                int row0, int tid) {
    // 128 rows x 512 bytes each, 16B chunks: 4096 chunks, 16 per thread
    #pragma unroll
    for (int k = 0; k < 16; k++) {
        int i = k * 256 + tid;
        int r = i >> 5;             // 0..127
        int c = i & 31;             // 16B chunk within 512B row
        cp_async16(sm_dst + (uint32_t)(r * LDTB + c * 16),
                   (const char*)(src + (size_t)(row0 + r) * KDIM) + c * 16);
    }
}

__global__ void __launch_bounds__(256, 1) k_dist_mma() {
    char* smem = s_raw;
    const uint32_t sbase = smem_u32(smem);
    const int tid = threadIdx.x;
    const int wid = tid >> 5;
    const int lane = tid & 31;
    const int wm = wid & 1;          // M half (0/1): rows wm*64..+63
    const int wn = wid >> 1;         // N quarter (0..3): cols wn*32..+31
    const int rowBase = blockIdx.x * BNR;

    int tile0, tile1;
    if (blockIdx.y == 0)      { tile0 = 0;   tile1 = 86;  }
    else if (blockIdx.y == 1) { tile0 = 86;  tile1 = 171; }
    else                      { tile0 = 171; tile1 = NTILES; }

    const uint32_t A = sbase + OFF_A;
    const uint32_t B[2] = { sbase + OFF_B0, sbase + OFF_B1 };
    float* y2s = reinterpret_cast<float*>(smem + OFF_Y2);

    // per-thread ldmatrix lane addressing offsets
    const int a_row = lane & 15;
    const int a_koff = (lane >> 4) << 3;
    const uint32_t aOff = (uint32_t)((wm * 64 + a_row) * LDTB + a_koff * 2);
    const int b_n = (lane & 7) + ((lane >> 4) << 3);
    const int b_koff = ((lane >> 3) & 1) << 3;
    const uint32_t bOff = (uint32_t)((wn * 32 + b_n) * LDTB + b_koff * 2);

    // prologue loads: A, B tile0, y2 tile0
    load_tile_async(A, g_embcat, rowBase, tid);
    load_tile_async(B[0], g_mbcat, tile0 * BMC, tid);
    if (tid < 32)
        cp_async16(sbase + OFF_Y2 + tid * 16, (const char*)(g_y2h + tile0 * BMC) + tid * 16);
    CP_COMMIT();
    CP_WAIT0();
    __syncthreads();

    float bestV[8];
    int   bestI[8];
    #pragma unroll
    for (int i = 0; i < 8; i++) { bestV[i] = -FLT_MAX; bestI[i] = INT_MAX; }

    for (int t = tile0; t < tile1; t++) {
        const int buf = (t - tile0) & 1;

        // prefetch next B tile + y2
        if (t + 1 < tile1) {
            const int nb = buf ^ 1;
            load_tile_async(B[nb], g_mbcat, (t + 1) * BMC, tid);
            if (tid < 32)
                cp_async16(sbase + OFF_Y2 + (uint32_t)(nb * 512 + tid * 16),
                           (const char*)(g_y2h + (size_t)(t + 1) * BMC) + tid * 16);
            CP_COMMIT();
        }

        // ---- compute: 16 k-chunks of the 128x128 tile (K=256) ----
        float acc[4][4][4];
        #pragma unroll
        for (int mf = 0; mf < 4; mf++)
            #pragma unroll
            for (int nf = 0; nf < 4; nf++)
                #pragma unroll
                for (int r = 0; r < 4; r++) acc[mf][nf][r] = 0.0f;

        const uint32_t aB = A + aOff;
        const uint32_t bB = B[buf] + bOff;
        #pragma unroll
        for (int kc = 0; kc < 16; kc++) {
            const uint32_t kByte = (uint32_t)(kc << 5);   // 16 bf16 = 32B
            uint32_t af[4][4];
            #pragma unroll
            for (int mf = 0; mf < 4; mf++)
                ldm_x4(aB + (uint32_t)(mf * 16 * LDTB) + kByte,
                       af[mf][0], af[mf][1], af[mf][2], af[mf][3]);
            uint32_t bf[4][2];
            #pragma unroll
            for (int q = 0; q < 2; q++) {
                uint32_t r0, r1, r2, r3;
                ldm_x4(bB + (uint32_t)(q * 16 * LDTB) + kByte, r0, r1, r2, r3);
                bf[q * 2][0] = r0; bf[q * 2][1] = r1;
                bf[q * 2 + 1][0] = r2; bf[q * 2 + 1][1] = r3;
            }
            #pragma unroll
            for (int mf = 0; mf < 4; mf++)
                #pragma unroll
                for (int nf = 0; nf < 4; nf++)
                    mma16816(acc[mf][nf], af[mf], bf[nf]);
        }

        // ---- epilogue: s = dot - 0.5*y2, running argmax ----
        {
            const float* hy = y2s + buf * 128;
            float hv[4][2];
            #pragma unroll
            for (int nf = 0; nf < 4; nf++) {
                int cl = wn * 32 + nf * 8 + (lane & 3) * 2;
                hv[nf][0] = hy[cl];
                hv[nf][1] = hy[cl + 1];
            }
            const int cg0 = t * BMC + wn * 32 + (lane & 3) * 2;
            #pragma unroll
            for (int mf = 0; mf < 4; mf++) {
                #pragma unroll
                for (int h = 0; h < 2; h++) {
                    const int slot = mf * 2 + h;
                    float bv = bestV[slot]; int bi = bestI[slot];
                    #pragma unroll
                    for (int nf = 0; nf < 4; nf++) {
                        float s0 = acc[mf][nf][h * 2] - hv[nf][0];
                        float s1 = acc[mf][nf][h * 2 + 1] - hv[nf][1];
                        int c0 = cg0 + nf * 8;
                        if (s0 > bv) { bv = s0; bi = c0; }
                        if (s1 > bv) { bv = s1; bi = c0 + 1; }
                    }
                    bestV[slot] = bv; bestI[slot] = bi;
                }
            }
        }

        if (t + 1 < tile1) CP_WAIT0();
        __syncthreads();
    }

    // ---- reduce: quad lanes share rows, then across the 4 N-warps ----
    float* redV = reinterpret_cast<float*>(smem + OFF_RED);
    int*   redI = reinterpret_cast<int*>(smem + OFF_RED + 2048);
    #pragma unroll
    for (int slot = 0; slot < 8; slot++) {
        float v = bestV[slot]; int idx = bestI[slot];
        #pragma unroll
        for (int off = 1; off <= 2; off <<= 1) {
            float ov = __shfl_xor_sync(0xFFFFFFFF, v, off);
            int oi = __shfl_xor_sync(0xFFFFFFFF, idx, off);
            if (ov > v || (ov == v && oi < idx)) { v = ov; idx = oi; }
        }
        if ((lane & 3) == 0) {
            int mf = slot >> 1, h = slot & 1;
            int row = wm * 64 + mf * 16 + (lane >> 2) + h * 8;
            redV[row * 4 + wn] = v;
            redI[row * 4 + wn] = idx;
        }
    }
    __syncthreads();
    if (tid < BNR) {
        float bv = -FLT_MAX; int bi = INT_MAX;
        #pragma unroll
        for (int w = 0; w < 4; w++) {
            float v = redV[tid * 4 + w];
            int ii = redI[tid * 4 + w];
            if (v > bv || (v == bv && ii < bi)) { bv = v; bi = ii; }
        }
        g_pval[blockIdx.y * NROWS + rowBase + tid] = bv;
        g_pidx[blockIdx.y * NROWS + rowBase + tid] = bi;
    }
}

// ---------------- combine split partials -> patch scores ----------------
__global__ void k_reduce(const float* __restrict__ emb) {
    int row = blockIdx.x * 256 + threadIdx.x;
    if (row >= NROWS) return;
    float bv = -FLT_MAX; int bi = INT_MAX;
    #pragma unroll
    for (int s = 0; s < NSPLIT; s++) {
        float v = g_pval[s * NROWS + row];
        int ii = g_pidx[s * NROWS + row];
        if (v > bv || (v == bv && ii < bi)) { bv = v; bi = ii; }
    }
    float x2 = 0.0f;
    const float4* e = reinterpret_cast<const float4*>(emb + (size_t)row * DDIM);
    #pragma unroll
    for (int d = 0; d < DDIM / 4; d++) {
        float4 v = e[d];
        x2 += v.x * v.x + v.y * v.y + v.z * v.z + v.w * v.w;
    }
    float d2 = x2 - 2.0f * bv;
    g_pscore[row] = sqrtf(fmaxf(d2, 0.0f));
    g_ploc[row] = bi;
}

__global__ void k_imgmax() {
    int b = blockIdx.x, tid = threadIdx.x;
    __shared__ float sv[256]; __shared__ int si[256];
    float bv = -FLT_MAX; int bi = INT_MAX;
    for (int p = tid; p < PPB; p += 256) {
        float v = g_pscore[b * PPB + p];
        if (v > bv || (v == bv && p < bi)) { bv = v; bi = p; }
    }
    sv[tid] = bv; si[tid] = bi;
    __syncthreads();
    for (int s = 128; s > 0; s >>= 1) {
        if (tid < s) {
            if (sv[tid + s] > sv[tid] || (sv[tid + s] == sv[tid] && si[tid + s] < si[tid])) {
                sv[tid] = sv[tid + s]; si[tid] = si[tid + s];
            }
        }
        __syncthreads();
    }
    if (tid == 0) {
        g_score[b] = sv[0];
        g_qrow[b] = b * PPB + si[0];
        g_nnidx[b] = g_ploc[b * PPB + si[0]];
    }
}

__global__ void k_dnn(const float* __restrict__ mb) {
    int b = blockIdx.y;
    int warp = threadIdx.x >> 5, lane = threadIdx.x & 31;
    int row = blockIdx.x * 8 + warp;
    int nn = g_nnidx[b];
    float4 q = reinterpret_cast<const float4*>(mb + (size_t)nn * DDIM)[lane];
    float4 m = reinterpret_cast<const float4*>(mb + (size_t)row * DDIM)[lane];
    float dot = q.x * m.x + q.y * m.y + q.z * m.z + q.w * m.w;
    #pragma unroll
    for (int o = 16; o > 0; o >>= 1) dot += __shfl_xor_sync(0xFFFFFFFF, dot, o);
    if (lane == 0) {
        float d2 = g_y2[nn] - 2.0f * dot + g_y2[row];
        g_dnn[b * MROWS + row] = sqrtf(fmaxf(d2, 0.0f));
    }
}

// ---------------- single-pass top-9 + softmax reweight -> pred_score ----------------
__global__ void k_final(const float* __restrict__ emb, const float* __restrict__ mb,
                        float* __restrict__ out) {
    int b = blockIdx.x, tid = threadIdx.x;
    __shared__ float hv[256];
    __shared__ int hidx[256];
    __shared__ int hthr[256];
    __shared__ int sel[KNEIGH];
    __shared__ float dists[KNEIGH];

    // per-thread sorted top-9 over its strided slice (m ascending => strict < keeps first index)
    float tv[KNEIGH]; int ti9[KNEIGH];
    #pragma unroll
    for (int j = 0; j < KNEIGH; j++) { tv[j] = FLT_MAX; ti9[j] = INT_MAX; }
    for (int m = tid; m < MROWS; m += 256) {
        float v = g_dnn[b * MROWS + m];
        if (v < tv[KNEIGH - 1]) {
            int pos = KNEIGH - 1;
            while (pos > 0 && v < tv[pos - 1]) {
                tv[pos] = tv[pos - 1]; ti9[pos] = ti9[pos - 1]; pos--;
            }
            tv[pos] = v; ti9[pos] = m;
        }
    }

    // 9-round 256-way merge (each thread's list is sorted; winner advances its cursor)
    int cur = 0;
    for (int it = 0; it < KNEIGH; it++) {
        hv[tid] = (cur < KNEIGH) ? tv[cur] : FLT_MAX;
        hidx[tid] = (cur < KNEIGH) ? ti9[cur] : INT_MAX;
        hthr[tid] = tid;
        __syncthreads();
        for (int s = 128; s > 0; s >>= 1) {
            if (tid < s) {
                if (hv[tid + s] < hv[tid] ||
                    (hv[tid + s] == hv[tid] && hidx[tid + s] < hidx[tid])) {
                    hv[tid] = hv[tid + s]; hidx[tid] = hidx[tid + s]; hthr[tid] = hthr[tid + s];
                }
            }
            __syncthreads();
        }
        if (tid == 0) sel[it] = hidx[0];
        int win = hthr[0];
        __syncthreads();
        if (tid == win) cur++;
    }

    if (tid < KNEIGH) {
        const float* q = emb + (size_t)g_qrow[b] * DDIM;
        const float* m = mb + (size_t)sel[tid] * DDIM;
        float dot = 0.0f, q2 = 0.0f;
        #pragma unroll 4
        for (int d = 0; d < DDIM; d++) { dot += q[d] * m[d]; q2 += q[d] * q[d]; }
        float d2 = q2 - 2.0f * dot + g_y2[sel[tid]];
        dists[tid] = sqrtf(fmaxf(d2, 0.0f));
    }
    __syncthreads();
    if (tid == 0) {
        float mx = dists[0];
        for (int j = 1; j < KNEIGH; j++) mx = fmaxf(mx, dists[j]);
        float sum = 0.0f, e0 = 0.0f;
        for (int j = 0; j < KNEIGH; j++) {
            float e = expf(dists[j] - mx);
            if (j == 0) e0 = e;
            sum += e;
        }
        out[b] = (1.0f - e0 / sum) * g_score[b];
    }
}

__global__ void k_upsample() {
    int o = blockIdx.x * 256 + threadIdx.x;
    if (o >= BATCH * OUTSZ * OUTSZ) return;
    int b = o / (OUTSZ * OUTSZ), r = o % (OUTSZ * OUTSZ);
    int U = r / OUTSZ, V = r % OUTSZ;
    float su = ((float)U + 0.5f) * 0.125f - 0.5f;
    float sv = ((float)V + 0.5f) * 0.125f - 0.5f;
    int u0 = (int)floorf(su), v0 = (int)floorf(sv);
    float tu = su - (float)u0, tv = sv - (float)v0;
    int u0c = min(max(u0, 0), WIO - 1), u1c = min(max(u0 + 1, 0), WIO - 1);
    int v0c = min(max(v0, 0), WIO - 1), v1c = min(max(v0 + 1, 0), WIO - 1);
    const float* p = g_pscore + b * PPB;
    float v00 = p[u0c * WIO + v0c], v01 = p[u0c * WIO + v1c];
    float v10 = p[u1c * WIO + v0c], v11 = p[u1c * WIO + v1c];
    float top = v00 + tv * (v01 - v00);
    float bot = v10 + tv * (v11 - v10);
    g_umap[o] = top + tu * (bot - top);
}

__global__ void k_vblur() {
    int o = blockIdx.x * 256 + threadIdx.x;
    if (o >= BATCH * OUTSZ * OUTSZ) return;
    int b = o / (OUTSZ * OUTSZ), r = o % (OUTSZ * OUTSZ);
    int U = r / OUTSZ, V = r % OUTSZ;
    const float* base = g_umap + b * OUTSZ * OUTSZ;
    float acc = 0.0f;
    #pragma unroll
    for (int k = 0; k < KSIZE; k++) {
        int i = U - KRAD + k;
        if (i < 0) i = -i;
        if (i > OUTSZ - 1) i = 2 * (OUTSZ - 1) - i;
        acc += g_gauss[k] * base[i * OUTSZ + V];
    }
    g_vtmp[o] = acc;
}

__global__ void k_hblur(float* __restrict__ out) {
    int o = blockIdx.x * 256 + threadIdx.x;
    if (o >= BATCH * OUTSZ * OUTSZ) return;
    int b = o / (OUTSZ * OUTSZ), r = o % (OUTSZ * OUTSZ);
    int U = r / OUTSZ, V = r % OUTSZ;
    const float* base = g_vtmp + b * OUTSZ * OUTSZ + U * OUTSZ;
    float acc = 0.0f;
    #pragma unroll
    for (int k = 0; k < KSIZE; k++) {
        int j = V - KRAD + k;
        if (j < 0) j = -j;
        if (j > OUTSZ - 1) j = 2 * (OUTSZ - 1) - j;
        acc += g_gauss[k] * base[j];
    }
    out[BATCH + o] = acc;
}

// ---------------- launcher ----------------
extern "C" void kernel_launch(void* const* d_in, const int* in_sizes, int n_in,
                              void* d_out, int out_size) {
    const float* emb = (const float*)d_in[0];
    const float* mb = (const float*)d_in[1];
    float* out = (float*)d_out;

    static bool attr_set = false;
    if (!attr_set) {
        cudaFuncSetAttribute(k_dist_mma, cudaFuncAttributeMaxDynamicSharedMemorySize, SMEM_TOTAL);
        attr_set = true;
    }

    k_gauss_init<<<1, 32>>>();
    k_y2<<<MROWS / 8, 256>>>(mb);
    k_split<<<(MROWS * DDIM + 255) / 256, 256>>>(emb, mb);

    dim3 gdist(NROWS / BNR, NSPLIT);
    k_dist_mma<<<gdist, 256, SMEM_TOTAL>>>();

    k_reduce<<<(NROWS + 255) / 256, 256>>>(emb);
    k_imgmax<<<BATCH, 256>>>();

    dim3 gdnn(MROWS / 8, BATCH);
    k_dnn<<<gdnn, 256>>>(mb);

    k_final<<<BATCH, 256>>>(emb, mb, out);

    int nmap = BATCH * OUTSZ * OUTSZ;
    k_upsample<<<(nmap + 255) / 256, 256>>>();
    k_vblur<<<(nmap + 255) / 256, 256>>>();
    k_hblur<<<(nmap + 255) / 256, 256>>>(out);
}

// round 7
// speedup vs baseline: 4.9334x; 1.0068x over previous
#include <cuda_runtime.h>
#include <cuda_bf16.h>
#include <math.h>
#include <float.h>
#include <limits.h>
#include <stdint.h>

// ---------------- problem constants (fixed shapes) ----------------
#define NROWS 6272      // embedding rows
#define MROWS 32768     // memory bank rows
#define DDIM  128
#define KDIM  256       // concatenated hi||lo
#define BATCH 8
#define PPB   784
#define WIO   28
#define OUTSZ 224
#define KNEIGH 9
#define KSIZE 33
#define KRAD  16

#define NSPLIT 3
#define BNR 128                 // emb rows per CTA
#define BMC 128                 // mb cols per tile
#define NTILES (MROWS / BMC)    // 256
#define LDTB 528                // smem tile row stride bytes (264 bf16)
#define TILE_BYTES (128 * LDTB) // 67584

// k_dist smem byte offsets
#define OFF_A     0
#define OFF_B0    (OFF_A + TILE_BYTES)
#define OFF_B1    (OFF_B0 + TILE_BYTES)
#define OFF_Y2    (OFF_B1 + TILE_BYTES)        // 2 x 128 floats (halved y2)
#define OFF_RED   (OFF_Y2 + 1024)              // 128*2 floats
#define SMEM_TOTAL (OFF_RED + 1024)            // 204800 bytes

// k_map smem layout
#define MAP_PM    0                            // 784 floats
#define MAP_GS    3136                         // 33 floats
#define MAP_UP    3280                         // 48*224 floats
#define MAP_VT    (MAP_UP + 48*224*4)          // 16*224 floats
#define MAP_SMEM  (MAP_VT + 16*224*4)          // 60624 bytes

// ---------------- device scratch ----------------
__device__ float g_y2[MROWS];
__device__ float g_y2h[MROWS];                // 0.5 * y2
__device__ float g_pval[NSPLIT * NROWS];
__device__ float g_pscore[NROWS];
__device__ int   g_qrow[BATCH];
__device__ float g_score[BATCH];
__device__ int   g_nnidx[BATCH];
__device__ float g_qpv[BATCH * 128];          // argmin partials for 8 query rows
__device__ int   g_qpi[BATCH * 128];
__device__ float g_dnn[BATCH * MROWS];
__device__ float g_gauss[KSIZE];
// bf16 split, K-concatenated: row = [hi(128) || lo(128)]
__device__ __nv_bfloat16 g_embcat[NROWS * KDIM];
__device__ __nv_bfloat16 g_mbcat[MROWS * KDIM];

// ---------------- small helpers ----------------
__device__ __forceinline__ uint32_t smem_u32(const void* p) {
    uint32_t a;
    asm("{ .reg .u64 t; cvta.to.shared.u64 t, %1; cvt.u32.u64 %0, t; }" : "=r"(a) : "l"(p));
    return a;
}
__device__ __forceinline__ void cp_async16(uint32_t dst, const void* src) {
    asm volatile("cp.async.cg.shared.global [%0], [%1], 16;" :: "r"(dst), "l"(src));
}
#define CP_COMMIT() asm volatile("cp.async.commit_group;" ::: "memory")
#define CP_WAIT0()  asm volatile("cp.async.wait_group 0;" ::: "memory")

__device__ __forceinline__ void ldm_x4(uint32_t addr, uint32_t& r0, uint32_t& r1,
                                       uint32_t& r2, uint32_t& r3) {
    asm volatile("ldmatrix.sync.aligned.m8n8.x4.shared.b16 {%0,%1,%2,%3}, [%4];"
                 : "=r"(r0), "=r"(r1), "=r"(r2), "=r"(r3) : "r"(addr));
}
__device__ __forceinline__ void mma16816(float* c, const uint32_t* a, const uint32_t* b) {
    asm volatile("mma.sync.aligned.m16n8k16.row.col.f32.bf16.bf16.f32 "
                 "{%0,%1,%2,%3}, {%4,%5,%6,%7}, {%8,%9}, {%0,%1,%2,%3};"
                 : "+f"(c[0]), "+f"(c[1]), "+f"(c[2]), "+f"(c[3])
                 : "r"(a[0]), "r"(a[1]), "r"(a[2]), "r"(a[3]), "r"(b[0]), "r"(b[1]));
}

// ---------------- misc small kernels ----------------
__global__ void k_gauss_init() {
    if (threadIdx.x == 0) {
        float tmp[KSIZE]; float s = 0.0f;
        for (int i = 0; i < KSIZE; i++) {
            float x = (float)i - (float)(KSIZE - 1) * 0.5f;
            float t = x / 4.0f;
            tmp[i] = expf(-0.5f * t * t); s += tmp[i];
        }
        for (int i = 0; i < KSIZE; i++) g_gauss[i] = tmp[i] / s;
    }
}

__global__ void k_y2(const float* __restrict__ mb) {
    int warp = threadIdx.x >> 5, lane = threadIdx.x & 31;
    int row = blockIdx.x * 8 + warp;
    if (row >= MROWS) return;
    float4 v = reinterpret_cast<const float4*>(mb + (size_t)row * DDIM)[lane];
    float s = v.x * v.x + v.y * v.y + v.z * v.z + v.w * v.w;
    #pragma unroll
    for (int o = 16; o > 0; o >>= 1) s += __shfl_xor_sync(0xFFFFFFFF, s, o);
    if (lane == 0) { g_y2[row] = s; g_y2h[row] = 0.5f * s; }
}

// fp32 -> [hi || lo] bf16 concat rows
__global__ void k_split(const float* __restrict__ emb, const float* __restrict__ mb) {
    int i = blockIdx.x * 256 + threadIdx.x;
    if (i < NROWS * DDIM) {
        int r = i >> 7, c = i & 127;
        float x = emb[i];
        __nv_bfloat16 h = __float2bfloat16_rn(x);
        g_embcat[(size_t)r * KDIM + c] = h;
        g_embcat[(size_t)r * KDIM + 128 + c] = __float2bfloat16_rn(x - __bfloat162float(h));
    }
    if (i < MROWS * DDIM) {
        int r = i >> 7, c = i & 127;
        float x = mb[i];
        __nv_bfloat16 h = __float2bfloat16_rn(x);
        g_mbcat[(size_t)r * KDIM + c] = h;
        g_mbcat[(size_t)r * KDIM + 128 + c] = __float2bfloat16_rn(x - __bfloat162float(h));
    }
}

// ---------------- mma.sync fused distance GEMM (K=256) + max (value-only) ----------------
extern __shared__ char s_raw[];

__device__ __forceinline__ void load_tile_async(uint32_t sm_dst,
                                                const __nv_bfloat16* __restrict__ src,
                                                int row0, int tid) {
    // 128 rows x 512 bytes each, 16B chunks: 4096 chunks, 32 per thread (128 thr)
    #pragma unroll
    for (int k = 0; k < 32; k++) {
        int i = k * 128 + tid;
        int r = i >> 5;             // 0..127
        int c = i & 31;             // 16B chunk within 512B row
        cp_async16(sm_dst + (uint32_t)(r * LDTB + c * 16),
                   (const char*)(src + (size_t)(row0 + r) * KDIM) + c * 16);
    }
}

__global__ void __launch_bounds__(128, 1) k_dist_mma() {
    char* smem = s_raw;
    const uint32_t sbase = smem_u32(smem);
    const int tid = threadIdx.x;
    const int wid = tid >> 5;
    const int lane = tid & 31;
    const int wm = wid & 1;          // M half (0/1): rows wm*64..+63
    const int wn = wid >> 1;         // N half (0/1): cols wn*64..+63
    const int rowBase = blockIdx.x * BNR;

    int tile0, tile1;
    if (blockIdx.y == 0)      { tile0 = 0;   tile1 = 86;  }
    else if (blockIdx.y == 1) { tile0 = 86;  tile1 = 171; }
    else                      { tile0 = 171; tile1 = NTILES; }

    const uint32_t A = sbase + OFF_A;
    const uint32_t B[2] = { sbase + OFF_B0, sbase + OFF_B1 };
    float* y2s = reinterpret_cast<float*>(smem + OFF_Y2);

    // per-thread ldmatrix lane addressing offsets
    const int a_row = lane & 15;
    const int a_koff = (lane >> 4) << 3;
    const uint32_t aOff = (uint32_t)((wm * 64 + a_row) * LDTB + a_koff * 2);
    const int b_n = (lane & 7) + ((lane >> 4) << 3);
    const int b_koff = ((lane >> 3) & 1) << 3;
    const uint32_t bOff = (uint32_t)((wn * 64 + b_n) * LDTB + b_koff * 2);

    // prologue loads: A, B tile0, y2 tile0
    load_tile_async(A, g_embcat, rowBase, tid);
    load_tile_async(B[0], g_mbcat, tile0 * BMC, tid);
    if (tid < 32)
        cp_async16(sbase + OFF_Y2 + tid * 16, (const char*)(g_y2h + tile0 * BMC) + tid * 16);
    CP_COMMIT();
    CP_WAIT0();
    __syncthreads();

    float bestV[8];
    #pragma unroll
    for (int i = 0; i < 8; i++) bestV[i] = -FLT_MAX;

    for (int t = tile0; t < tile1; t++) {
        const int buf = (t - tile0) & 1;

        // prefetch next B tile + y2
        if (t + 1 < tile1) {
            const int nb = buf ^ 1;
            load_tile_async(B[nb], g_mbcat, (t + 1) * BMC, tid);
            if (tid < 32)
                cp_async16(sbase + OFF_Y2 + (uint32_t)(nb * 512 + tid * 16),
                           (const char*)(g_y2h + (size_t)(t + 1) * BMC) + tid * 16);
            CP_COMMIT();
        }

        // ---- compute: 16 k-chunks, warp tile 64x64 ----
        float acc[4][8][4];
        #pragma unroll
        for (int mf = 0; mf < 4; mf++)
            #pragma unroll
            for (int nf = 0; nf < 8; nf++)
                #pragma unroll
                for (int r = 0; r < 4; r++) acc[mf][nf][r] = 0.0f;

        const uint32_t aB = A + aOff;
        const uint32_t bB = B[buf] + bOff;
        #pragma unroll
        for (int kc = 0; kc < 16; kc++) {
            const uint32_t kByte = (uint32_t)(kc << 5);   // 16 bf16 = 32B
            uint32_t af[4][4];
            #pragma unroll
            for (int mf = 0; mf < 4; mf++)
                ldm_x4(aB + (uint32_t)(mf * 16 * LDTB) + kByte,
                       af[mf][0], af[mf][1], af[mf][2], af[mf][3]);
            uint32_t bf[8][2];
            #pragma unroll
            for (int q = 0; q < 4; q++) {
                uint32_t r0, r1, r2, r3;
                ldm_x4(bB + (uint32_t)(q * 16 * LDTB) + kByte, r0, r1, r2, r3);
                bf[q * 2][0] = r0; bf[q * 2][1] = r1;
                bf[q * 2 + 1][0] = r2; bf[q * 2 + 1][1] = r3;
            }
            #pragma unroll
            for (int mf = 0; mf < 4; mf++)
                #pragma unroll
                for (int nf = 0; nf < 8; nf++)
                    mma16816(acc[mf][nf], af[mf], bf[nf]);
        }

        // ---- epilogue: s = dot - 0.5*y2, running max (no index) ----
        {
            const float* hy = y2s + buf * 128;
            float hv[8][2];
            #pragma unroll
            for (int nf = 0; nf < 8; nf++) {
                int cl = wn * 64 + nf * 8 + (lane & 3) * 2;
                hv[nf][0] = hy[cl];
                hv[nf][1] = hy[cl + 1];
            }
            #pragma unroll
            for (int mf = 0; mf < 4; mf++) {
                #pragma unroll
                for (int h = 0; h < 2; h++) {
                    const int slot = mf * 2 + h;
                    float bv = bestV[slot];
                    #pragma unroll
                    for (int nf = 0; nf < 8; nf++) {
                        float s0 = acc[mf][nf][h * 2] - hv[nf][0];
                        float s1 = acc[mf][nf][h * 2 + 1] - hv[nf][1];
                        bv = fmaxf(bv, fmaxf(s0, s1));
                    }
                    bestV[slot] = bv;
                }
            }
        }

        if (t + 1 < tile1) CP_WAIT0();
        __syncthreads();
    }

    // ---- reduce: quad lanes share rows, then across the 2 N-warps ----
    float* redV = reinterpret_cast<float*>(smem + OFF_RED);
    #pragma unroll
    for (int slot = 0; slot < 8; slot++) {
        float v = bestV[slot];
        v = fmaxf(v, __shfl_xor_sync(0xFFFFFFFF, v, 1));
        v = fmaxf(v, __shfl_xor_sync(0xFFFFFFFF, v, 2));
        if ((lane & 3) == 0) {
            int mf = slot >> 1, h = slot & 1;
            int row = wm * 64 + mf * 16 + (lane >> 2) + h * 8;
            redV[row * 2 + wn] = v;
        }
    }
    __syncthreads();
    if (tid < BNR) {
        float bv = fmaxf(redV[tid * 2], redV[tid * 2 + 1]);
        g_pval[blockIdx.y * NROWS + rowBase + tid] = bv;
    }
}

// ---------------- combine split partials -> patch scores ----------------
__global__ void k_reduce(const float* __restrict__ emb) {
    int row = blockIdx.x * 256 + threadIdx.x;
    if (row >= NROWS) return;
    float bv = -FLT_MAX;
    #pragma unroll
    for (int s = 0; s < NSPLIT; s++) bv = fmaxf(bv, g_pval[s * NROWS + row]);
    float x2 = 0.0f;
    const float4* e = reinterpret_cast<const float4*>(emb + (size_t)row * DDIM);
    #pragma unroll
    for (int d = 0; d < DDIM / 4; d++) {
        float4 v = e[d];
        x2 += v.x * v.x + v.y * v.y + v.z * v.z + v.w * v.w;
    }
    float d2 = x2 - 2.0f * bv;
    g_pscore[row] = sqrtf(fmaxf(d2, 0.0f));
}

// ---------------- per-image argmax patch (values only) ----------------
__global__ void k_imgmax() {
    int b = blockIdx.x, tid = threadIdx.x;
    __shared__ float sv[256]; __shared__ int si[256];
    float bv = -FLT_MAX; int bi = INT_MAX;
    for (int p = tid; p < PPB; p += 256) {
        float v = g_pscore[b * PPB + p];
        if (v > bv || (v == bv && p < bi)) { bv = v; bi = p; }
    }
    sv[tid] = bv; si[tid] = bi;
    __syncthreads();
    for (int s = 128; s > 0; s >>= 1) {
        if (tid < s) {
            if (sv[tid + s] > sv[tid] || (sv[tid + s] == sv[tid] && si[tid + s] < si[tid])) {
                sv[tid] = sv[tid + s]; si[tid] = si[tid + s];
            }
        }
        __syncthreads();
    }
    if (tid == 0) {
        g_score[b] = sv[0];
        g_qrow[b] = b * PPB + si[0];
    }
}

// ---------------- exact fp32 argmin recovery for the 8 selected rows ----------------
// grid (128, 8), block 256 (8 warps x 32 rows each)
__global__ void k_qpart(const float* __restrict__ emb, const float* __restrict__ mb) {
    int b = blockIdx.y;
    int warp = threadIdx.x >> 5, lane = threadIdx.x & 31;
    int qrow = g_qrow[b];
    float4 q = reinterpret_cast<const float4*>(emb + (size_t)qrow * DDIM)[lane];
    float bv = FLT_MAX; int bi = INT_MAX;
    int base = blockIdx.x * 256 + warp * 32;
    for (int i = 0; i < 32; i++) {
        int row = base + i;
        float4 m = reinterpret_cast<const float4*>(mb + (size_t)row * DDIM)[lane];
        float dot = q.x * m.x + q.y * m.y + q.z * m.z + q.w * m.w;
        #pragma unroll
        for (int o = 16; o > 0; o >>= 1) dot += __shfl_xor_sync(0xFFFFFFFF, dot, o);
        float d2 = g_y2[row] - 2.0f * dot;   // + ||q||^2 constant: argmin-invariant
        if (d2 < bv) { bv = d2; bi = row; }  // ascending rows: strict < keeps first
    }
    __shared__ float sv[8]; __shared__ int si[8];
    if (lane == 0) { sv[warp] = bv; si[warp] = bi; }
    __syncthreads();
    if (threadIdx.x == 0) {
        float v = sv[0]; int ix = si[0];
        for (int w = 1; w < 8; w++)
            if (sv[w] < v || (sv[w] == v && si[w] < ix)) { v = sv[w]; ix = si[w]; }
        g_qpv[b * 128 + blockIdx.x] = v;
        g_qpi[b * 128 + blockIdx.x] = ix;
    }
}

__global__ void k_qfin() {
    int b = blockIdx.x, tid = threadIdx.x;
    __shared__ float sv[128]; __shared__ int si[128];
    sv[tid] = g_qpv[b * 128 + tid];
    si[tid] = g_qpi[b * 128 + tid];
    __syncthreads();
    for (int s = 64; s > 0; s >>= 1) {
        if (tid < s) {
            if (sv[tid + s] < sv[tid] || (sv[tid + s] == sv[tid] && si[tid + s] < si[tid])) {
                sv[tid] = sv[tid + s]; si[tid] = si[tid + s];
            }
        }
        __syncthreads();
    }
    if (tid == 0) g_nnidx[b] = si[0];
}

// ---------------- d_nn = dist(memory_bank[nn_idx[b]], memory_bank) ----------------
__global__ void k_dnn(const float* __restrict__ mb) {
    int b = blockIdx.y;
    int warp = threadIdx.x >> 5, lane = threadIdx.x & 31;
    int row = blockIdx.x * 8 + warp;
    int nn = g_nnidx[b];
    float4 q = reinterpret_cast<const float4*>(mb + (size_t)nn * DDIM)[lane];
    float4 m = reinterpret_cast<const float4*>(mb + (size_t)row * DDIM)[lane];
    float dot = q.x * m.x + q.y * m.y + q.z * m.z + q.w * m.w;
    #pragma unroll
    for (int o = 16; o > 0; o >>= 1) dot += __shfl_xor_sync(0xFFFFFFFF, dot, o);
    if (lane == 0) {
        float d2 = g_y2[nn] - 2.0f * dot + g_y2[row];
        g_dnn[b * MROWS + row] = sqrtf(fmaxf(d2, 0.0f));
    }
}

// ---------------- single-pass top-9 + softmax reweight -> pred_score ----------------
__global__ void k_final(const float* __restrict__ emb, const float* __restrict__ mb,
                        float* __restrict__ out) {
    int b = blockIdx.x, tid = threadIdx.x;
    __shared__ float hv[256];
    __shared__ int hidx[256];
    __shared__ int hthr[256];
    __shared__ int sel[KNEIGH];
    __shared__ float dists[KNEIGH];

    float tv[KNEIGH]; int ti9[KNEIGH];
    #pragma unroll
    for (int j = 0; j < KNEIGH; j++) { tv[j] = FLT_MAX; ti9[j] = INT_MAX; }
    for (int m = tid; m < MROWS; m += 256) {
        float v = g_dnn[b * MROWS + m];
        if (v < tv[KNEIGH - 1]) {
            int pos = KNEIGH - 1;
            while (pos > 0 && v < tv[pos - 1]) {
                tv[pos] = tv[pos - 1]; ti9[pos] = ti9[pos - 1]; pos--;
            }
            tv[pos] = v; ti9[pos] = m;
        }
    }

    int cur = 0;
    for (int it = 0; it < KNEIGH; it++) {
        hv[tid] = (cur < KNEIGH) ? tv[cur] : FLT_MAX;
        hidx[tid] = (cur < KNEIGH) ? ti9[cur] : INT_MAX;
        hthr[tid] = tid;
        __syncthreads();
        for (int s = 128; s > 0; s >>= 1) {
            if (tid < s) {
                if (hv[tid + s] < hv[tid] ||
                    (hv[tid + s] == hv[tid] && hidx[tid + s] < hidx[tid])) {
                    hv[tid] = hv[tid + s]; hidx[tid] = hidx[tid + s]; hthr[tid] = hthr[tid + s];
                }
            }
            __syncthreads();
        }
        if (tid == 0) sel[it] = hidx[0];
        int win = hthr[0];
        __syncthreads();
        if (tid == win) cur++;
    }

    if (tid < KNEIGH) {
        const float* q = emb + (size_t)g_qrow[b] * DDIM;
        const float* m = mb + (size_t)sel[tid] * DDIM;
        float dot = 0.0f, q2 = 0.0f;
        #pragma unroll 4
        for (int d = 0; d < DDIM; d++) { dot += q[d] * m[d]; q2 += q[d] * q[d]; }
        float d2 = q2 - 2.0f * dot + g_y2[sel[tid]];
        dists[tid] = sqrtf(fmaxf(d2, 0.0f));
    }
    __syncthreads();
    if (tid == 0) {
        float mx = dists[0];
        for (int j = 1; j < KNEIGH; j++) mx = fmaxf(mx, dists[j]);
        float sum = 0.0f, e0 = 0.0f;
        for (int j = 0; j < KNEIGH; j++) {
            float e = expf(dists[j] - mx);
            if (j == 0) e0 = e;
            sum += e;
        }
        out[b] = (1.0f - e0 / sum) * g_score[b];
    }
}

// ---------------- fused upsample + separable Gaussian blur ----------------
// grid (14 bands, 8 images), 256 threads, dynamic smem MAP_SMEM
__global__ void k_map(float* __restrict__ out) {
    char* smem = s_raw;
    float* pm = reinterpret_cast<float*>(smem + MAP_PM);
    float* gs = reinterpret_cast<float*>(smem + MAP_GS);
    float* up = reinterpret_cast<float*>(smem + MAP_UP);   // [48][224]
    float* vt = reinterpret_cast<float*>(smem + MAP_VT);   // [16][224]
    const int band = blockIdx.x, b = blockIdx.y;
    const int tid = threadIdx.x;
    const int r0 = band * 16;

    for (int i = tid; i < PPB; i += 256) pm[i] = g_pscore[b * PPB + i];
    if (tid < KSIZE) gs[tid] = g_gauss[tid];
    __syncthreads();

    // upsampled rows r0-16 .. r0+31 (reflected), bilinear align_corners=False
    for (int i = tid; i < 48 * 224; i += 256) {
        int j = i / 224, V = i % 224;
        int U = r0 - 16 + j;
        if (U < 0) U = -U;
        if (U > OUTSZ - 1) U = 2 * (OUTSZ - 1) - U;
        float su = ((float)U + 0.5f) * 0.125f - 0.5f;
        float sv = ((float)V + 0.5f) * 0.125f - 0.5f;
        int u0 = (int)floorf(su), v0 = (int)floorf(sv);
        float tu = su - (float)u0, tv = sv - (float)v0;
        int u0c = min(max(u0, 0), WIO - 1), u1c = min(max(u0 + 1, 0), WIO - 1);
        int v0c = min(max(v0, 0), WIO - 1), v1c = min(max(v0 + 1, 0), WIO - 1);
        float v00 = pm[u0c * WIO + v0c], v01 = pm[u0c * WIO + v1c];
        float v10 = pm[u1c * WIO + v0c], v11 = pm[u1c * WIO + v1c];
        float top = v00 + tv * (v01 - v00);
        float bot = v10 + tv * (v11 - v10);
        up[i] = top + tu * (bot - top);
    }
    __syncthreads();

    // vertical blur into vt (rows r0..r0+15)
    for (int i = tid; i < 16 * 224; i += 256) {
        int du = i / 224, V = i % 224;
        float acc = 0.0f;
        #pragma unroll
        for (int k = 0; k < KSIZE; k++) acc += gs[k] * up[(du + k) * 224 + V];
        vt[i] = acc;
    }
    __syncthreads();

    // horizontal blur, reflect on V, write out
    for (int i = tid; i < 16 * 224; i += 256) {
        int du = i / 224, V = i % 224;
        float acc = 0.0f;
        #pragma unroll
        for (int k = 0; k < KSIZE; k++) {
            int jv = V - KRAD + k;
            if (jv < 0) jv = -jv;
            if (jv > OUTSZ - 1) jv = 2 * (OUTSZ - 1) - jv;
            acc += gs[k] * vt[du * 224 + jv];
        }
        out[BATCH + (b * OUTSZ + r0 + du) * OUTSZ + V] = acc;
    }
}

// ---------------- launcher ----------------
extern "C" void kernel_launch(void* const* d_in, const int* in_sizes, int n_in,
                              void* d_out, int out_size) {
    const float* emb = (const float*)d_in[0];
    const float* mb = (const float*)d_in[1];
    float* out = (float*)d_out;

    static bool attr_set = false;
    if (!attr_set) {
        cudaFuncSetAttribute(k_dist_mma, cudaFuncAttributeMaxDynamicSharedMemorySize, SMEM_TOTAL);
        cudaFuncSetAttribute(k_map, cudaFuncAttributeMaxDynamicSharedMemorySize, MAP_SMEM);
        attr_set = true;
    }

    k_gauss_init<<<1, 32>>>();
    k_y2<<<MROWS / 8, 256>>>(mb);
    k_split<<<(MROWS * DDIM + 255) / 256, 256>>>(emb, mb);

    dim3 gdist(NROWS / BNR, NSPLIT);
    k_dist_mma<<<gdist, 128, SMEM_TOTAL>>>();

    k_reduce<<<(NROWS + 255) / 256, 256>>>(emb);
    k_imgmax<<<BATCH, 256>>>();

    dim3 gq(128, BATCH);
    k_qpart<<<gq, 256>>>(emb, mb);
    k_qfin<<<BATCH, 128>>>();

    dim3 gdnn(MROWS / 8, BATCH);
    k_dnn<<<gdnn, 256>>>(mb);

    k_final<<<BATCH, 256>>>(emb, mb, out);

    dim3 gmap(14, BATCH);
    k_map<<<gmap, 256, MAP_SMEM>>>(out);
}

// round 10
// speedup vs baseline: 6.6205x; 1.3420x over previous
#include <cuda_runtime.h>
#include <cuda_bf16.h>
#include <math.h>
#include <float.h>
#include <limits.h>
#include <stdint.h>

// ---------------- problem constants (fixed shapes) ----------------
#define NROWS 6272      // embedding rows
#define MROWS 32768     // memory bank rows
#define DDIM  128
#define BATCH 8
#define PPB   784
#define WIO   28
#define OUTSZ 224
#define KNEIGH 9
#define KSIZE 33
#define KRAD  16

#define NSPLIT 6
#define BNR 128                 // emb rows per CTA
#define BMC 128                 // mb cols per tile
#define NTILES (MROWS / BMC)    // 256
#define LDTB 272                // smem tile row stride bytes (136 bf16)
#define TILE_BYTES (128 * LDTB) // 34816

// k_dist smem byte offsets
#define OFF_A     0
#define OFF_B0    (OFF_A + TILE_BYTES)
#define OFF_B1    (OFF_B0 + TILE_BYTES)
#define OFF_Y2    (OFF_B1 + TILE_BYTES)        // 2 x 128 floats (halved y2)
#define OFF_RED   (OFF_Y2 + 1024)              // 128*2 floats
#define SMEM_TOTAL (OFF_RED + 1024)            // 106496 bytes -> 2 CTAs/SM

// k_map smem layout
#define MAP_PM    0                            // 784 floats
#define MAP_GS    3136                         // 33 floats
#define MAP_UP    3280                         // 48*224 floats
#define MAP_VT    (MAP_UP + 48*224*4)          // 16*224 floats
#define MAP_SMEM  (MAP_VT + 16*224*4)          // 60624 bytes

// ---------------- device scratch ----------------
__device__ float g_y2[MROWS];
__device__ float g_y2h[MROWS];                // 0.5 * y2
__device__ float g_pval[NSPLIT * NROWS];
__device__ float g_pscore[NROWS];
__device__ int   g_qrow[BATCH];
__device__ float g_score[BATCH];
__device__ int   g_nnidx[BATCH];
__device__ float g_qpv[BATCH * 128];          // exact argmin partials (d^2 - q^2)
__device__ int   g_qpi[BATCH * 128];
__device__ float g_dnn[BATCH * MROWS];
__device__ float g_gauss[KSIZE];
// bf16 hi parts
__device__ __nv_bfloat16 g_embh[NROWS * DDIM];
__device__ __nv_bfloat16 g_mbh[MROWS * DDIM];

// ---------------- small helpers ----------------
__device__ __forceinline__ uint32_t smem_u32(const void* p) {
    uint32_t a;
    asm("{ .reg .u64 t; cvta.to.shared.u64 t, %1; cvt.u32.u64 %0, t; }" : "=r"(a) : "l"(p));
    return a;
}
__device__ __forceinline__ void cp_async16(uint32_t dst, const void* src) {
    asm volatile("cp.async.cg.shared.global [%0], [%1], 16;" :: "r"(dst), "l"(src));
}
#define CP_COMMIT() asm volatile("cp.async.commit_group;" ::: "memory")
#define CP_WAIT0()  asm volatile("cp.async.wait_group 0;" ::: "memory")

__device__ __forceinline__ void ldm_x4(uint32_t addr, uint32_t& r0, uint32_t& r1,
                                       uint32_t& r2, uint32_t& r3) {
    asm volatile("ldmatrix.sync.aligned.m8n8.x4.shared.b16 {%0,%1,%2,%3}, [%4];"
                 : "=r"(r0), "=r"(r1), "=r"(r2), "=r"(r3) : "r"(addr));
}
__device__ __forceinline__ void mma16816(float* c, const uint32_t* a, const uint32_t* b) {
    asm volatile("mma.sync.aligned.m16n8k16.row.col.f32.bf16.bf16.f32 "
                 "{%0,%1,%2,%3}, {%4,%5,%6,%7}, {%8,%9}, {%0,%1,%2,%3};"
                 : "+f"(c[0]), "+f"(c[1]), "+f"(c[2]), "+f"(c[3])
                 : "r"(a[0]), "r"(a[1]), "r"(a[2]), "r"(a[3]), "r"(b[0]), "r"(b[1]));
}

// ---------------- misc small kernels ----------------
__global__ void k_gauss_init() {
    if (threadIdx.x == 0) {
        float tmp[KSIZE]; float s = 0.0f;
        for (int i = 0; i < KSIZE; i++) {
            float x = (float)i - (float)(KSIZE - 1) * 0.5f;
            float t = x / 4.0f;
            tmp[i] = expf(-0.5f * t * t); s += tmp[i];
        }
        for (int i = 0; i < KSIZE; i++) g_gauss[i] = tmp[i] / s;
    }
}

__global__ void k_y2(const float* __restrict__ mb) {
    int warp = threadIdx.x >> 5, lane = threadIdx.x & 31;
    int row = blockIdx.x * 8 + warp;
    if (row >= MROWS) return;
    float4 v = reinterpret_cast<const float4*>(mb + (size_t)row * DDIM)[lane];
    float s = v.x * v.x + v.y * v.y + v.z * v.z + v.w * v.w;
    #pragma unroll
    for (int o = 16; o > 0; o >>= 1) s += __shfl_xor_sync(0xFFFFFFFF, s, o);
    if (lane == 0) { g_y2[row] = s; g_y2h[row] = 0.5f * s; }
}

// fp32 -> bf16 (hi only)
__global__ void k_split(const float* __restrict__ emb, const float* __restrict__ mb) {
    int i = blockIdx.x * 256 + threadIdx.x;
    if (i < NROWS * DDIM) g_embh[i] = __float2bfloat16_rn(emb[i]);
    if (i < MROWS * DDIM) g_mbh[i]  = __float2bfloat16_rn(mb[i]);
}

// ---------------- mma.sync fused distance GEMM (K=128, bf16-hi) + max ----------------
extern __shared__ char s_raw[];

__device__ __forceinline__ void load_tile_async(uint32_t sm_dst,
                                                const __nv_bfloat16* __restrict__ src,
                                                int row0, int tid) {
    // 128 rows x 256 bytes, 16B chunks: 2048 chunks, 16 per thread (128 thr)
    #pragma unroll
    for (int k = 0; k < 16; k++) {
        int i = k * 128 + tid;
        int r = i >> 4;             // 0..127
        int c = i & 15;             // 16B chunk within 256B row
        cp_async16(sm_dst + (uint32_t)(r * LDTB + c * 16),
                   (const char*)(src + (size_t)(row0 + r) * DDIM) + c * 16);
    }
}

__global__ void __launch_bounds__(128, 2) k_dist_mma() {
    char* smem = s_raw;
    const uint32_t sbase = smem_u32(smem);
    const int tid = threadIdx.x;
    const int wid = tid >> 5;
    const int lane = tid & 31;
    const int wm = wid & 1;          // M half: rows wm*64..+63
    const int wn = wid >> 1;         // N half: cols wn*64..+63
    const int rowBase = blockIdx.x * BNR;

    const int tile0 = (blockIdx.y * NTILES) / NSPLIT;
    const int tile1 = ((blockIdx.y + 1) * NTILES) / NSPLIT;

    const uint32_t A = sbase + OFF_A;
    const uint32_t B[2] = { sbase + OFF_B0, sbase + OFF_B1 };
    float* y2s = reinterpret_cast<float*>(smem + OFF_Y2);

    // per-thread ldmatrix lane addressing offsets
    const int a_row = lane & 15;
    const int a_koff = (lane >> 4) << 3;
    const uint32_t aOff = (uint32_t)((wm * 64 + a_row) * LDTB + a_koff * 2);
    const int b_n = (lane & 7) + ((lane >> 4) << 3);
    const int b_koff = ((lane >> 3) & 1) << 3;
    const uint32_t bOff = (uint32_t)((wn * 64 + b_n) * LDTB + b_koff * 2);

    // prologue loads: A, B tile0, y2 tile0
    load_tile_async(A, g_embh, rowBase, tid);
    load_tile_async(B[0], g_mbh, tile0 * BMC, tid);
    if (tid < 32)
        cp_async16(sbase + OFF_Y2 + tid * 16, (const char*)(g_y2h + tile0 * BMC) + tid * 16);
    CP_COMMIT();
    CP_WAIT0();
    __syncthreads();

    float bestV[8];
    #pragma unroll
    for (int i = 0; i < 8; i++) bestV[i] = -FLT_MAX;

    for (int t = tile0; t < tile1; t++) {
        const int buf = (t - tile0) & 1;

        // prefetch next B tile + y2
        if (t + 1 < tile1) {
            const int nb = buf ^ 1;
            load_tile_async(B[nb], g_mbh, (t + 1) * BMC, tid);
            if (tid < 32)
                cp_async16(sbase + OFF_Y2 + (uint32_t)(nb * 512 + tid * 16),
                           (const char*)(g_y2h + (size_t)(t + 1) * BMC) + tid * 16);
            CP_COMMIT();
        }

        // ---- compute: 8 k-chunks, warp tile 64x64 ----
        float acc[4][8][4];
        #pragma unroll
        for (int mf = 0; mf < 4; mf++)
            #pragma unroll
            for (int nf = 0; nf < 8; nf++)
                #pragma unroll
                for (int r = 0; r < 4; r++) acc[mf][nf][r] = 0.0f;

        const uint32_t aB = A + aOff;
        const uint32_t bB = B[buf] + bOff;
        #pragma unroll
        for (int kc = 0; kc < 8; kc++) {
            const uint32_t kByte = (uint32_t)(kc << 5);   // 16 bf16 = 32B
            uint32_t af[4][4];
            #pragma unroll
            for (int mf = 0; mf < 4; mf++)
                ldm_x4(aB + (uint32_t)(mf * 16 * LDTB) + kByte,
                       af[mf][0], af[mf][1], af[mf][2], af[mf][3]);
            uint32_t bf[8][2];
            #pragma unroll
            for (int q = 0; q < 4; q++) {
                uint32_t r0, r1, r2, r3;
                ldm_x4(bB + (uint32_t)(q * 16 * LDTB) + kByte, r0, r1, r2, r3);
                bf[q * 2][0] = r0; bf[q * 2][1] = r1;
                bf[q * 2 + 1][0] = r2; bf[q * 2 + 1][1] = r3;
            }
            #pragma unroll
            for (int mf = 0; mf < 4; mf++)
                #pragma unroll
                for (int nf = 0; nf < 8; nf++)
                    mma16816(acc[mf][nf], af[mf], bf[nf]);
        }

        // ---- epilogue: s = dot - 0.5*y2, running max (no index) ----
        {
            const float* hy = y2s + buf * 128;
            float hv[8][2];
            #pragma unroll
            for (int nf = 0; nf < 8; nf++) {
                int cl = wn * 64 + nf * 8 + (lane & 3) * 2;
                hv[nf][0] = hy[cl];
                hv[nf][1] = hy[cl + 1];
            }
            #pragma unroll
            for (int mf = 0; mf < 4; mf++) {
                #pragma unroll
                for (int h = 0; h < 2; h++) {
                    const int slot = mf * 2 + h;
                    float bv = bestV[slot];
                    #pragma unroll
                    for (int nf = 0; nf < 8; nf++) {
                        float s0 = acc[mf][nf][h * 2] - hv[nf][0];
                        float s1 = acc[mf][nf][h * 2 + 1] - hv[nf][1];
                        bv = fmaxf(bv, fmaxf(s0, s1));
                    }
                    bestV[slot] = bv;
                }
            }
        }

        if (t + 1 < tile1) CP_WAIT0();
        __syncthreads();
    }

    // ---- reduce: quad lanes share rows, then across the 2 N-warps ----
    float* redV = reinterpret_cast<float*>(smem + OFF_RED);
    #pragma unroll
    for (int slot = 0; slot < 8; slot++) {
        float v = bestV[slot];
        v = fmaxf(v, __shfl_xor_sync(0xFFFFFFFF, v, 1));
        v = fmaxf(v, __shfl_xor_sync(0xFFFFFFFF, v, 2));
        if ((lane & 3) == 0) {
            int mf = slot >> 1, h = slot & 1;
            int row = wm * 64 + mf * 16 + (lane >> 2) + h * 8;
            redV[row * 2 + wn] = v;
        }
    }
    __syncthreads();
    if (tid < BNR) {
        float bv = fmaxf(redV[tid * 2], redV[tid * 2 + 1]);
        g_pval[blockIdx.y * NROWS + rowBase + tid] = bv;
    }
}

// ---------------- combine split partials -> patch scores ----------------
__global__ void k_reduce(const float* __restrict__ emb) {
    int row = blockIdx.x * 256 + threadIdx.x;
    if (row >= NROWS) return;
    float bv = -FLT_MAX;
    #pragma unroll
    for (int s = 0; s < NSPLIT; s++) bv = fmaxf(bv, g_pval[s * NROWS + row]);
    float x2 = 0.0f;
    const float4* e = reinterpret_cast<const float4*>(emb + (size_t)row * DDIM);
    #pragma unroll
    for (int d = 0; d < DDIM / 4; d++) {
        float4 v = e[d];
        x2 += v.x * v.x + v.y * v.y + v.z * v.z + v.w * v.w;
    }
    float d2 = x2 - 2.0f * bv;
    g_pscore[row] = sqrtf(fmaxf(d2, 0.0f));
}

// ---------------- per-image argmax patch ----------------
__global__ void k_imgmax() {
    int b = blockIdx.x, tid = threadIdx.x;
    __shared__ float sv[256]; __shared__ int si[256];
    float bv = -FLT_MAX; int bi = INT_MAX;
    for (int p = tid; p < PPB; p += 256) {
        float v = g_pscore[b * PPB + p];
        if (v > bv || (v == bv && p < bi)) { bv = v; bi = p; }
    }
    sv[tid] = bv; si[tid] = bi;
    __syncthreads();
    for (int s = 128; s > 0; s >>= 1) {
        if (tid < s) {
            if (sv[tid + s] > sv[tid] || (sv[tid + s] == sv[tid] && si[tid + s] < si[tid])) {
                sv[tid] = sv[tid + s]; si[tid] = si[tid + s];
            }
        }
        __syncthreads();
    }
    if (tid == 0) g_qrow[b] = b * PPB + si[0];
}

// ---------------- exact fp32 argmin over mb for the 8 query rows (batched) ----------------
// grid 128, block 256 = 8 warps x 32 rows; each warp dots its rows against all 8 queries
__global__ void k_qpart(const float* __restrict__ emb, const float* __restrict__ mb) {
    int warp = threadIdx.x >> 5, lane = threadIdx.x & 31;
    float4 q[BATCH];
    #pragma unroll
    for (int b = 0; b < BATCH; b++)
        q[b] = reinterpret_cast<const float4*>(emb + (size_t)g_qrow[b] * DDIM)[lane];

    float bv[BATCH]; int bi[BATCH];
    #pragma unroll
    for (int b = 0; b < BATCH; b++) { bv[b] = FLT_MAX; bi[b] = INT_MAX; }

    int base = blockIdx.x * 256 + warp * 32;
    for (int i = 0; i < 32; i++) {
        int row = base + i;
        float4 m = reinterpret_cast<const float4*>(mb + (size_t)row * DDIM)[lane];
        float y2r = g_y2[row];
        #pragma unroll
        for (int b = 0; b < BATCH; b++) {
            float dot = q[b].x * m.x + q[b].y * m.y + q[b].z * m.z + q[b].w * m.w;
            #pragma unroll
            for (int o = 16; o > 0; o >>= 1) dot += __shfl_xor_sync(0xFFFFFFFF, dot, o);
            float d2 = y2r - 2.0f * dot;        // +q^2 constant: argmin-invariant
            if (d2 < bv[b]) { bv[b] = d2; bi[b] = row; }
        }
    }
    __shared__ float sv[BATCH][8]; __shared__ int si[BATCH][8];
    if (lane == 0)
        #pragma unroll
        for (int b = 0; b < BATCH; b++) { sv[b][warp] = bv[b]; si[b][warp] = bi[b]; }
    __syncthreads();
    if (threadIdx.x < BATCH) {
        int b = threadIdx.x;
        float v = sv[b][0]; int ix = si[b][0];
        for (int w = 1; w < 8; w++)
            if (sv[b][w] < v || (sv[b][w] == v && si[b][w] < ix)) { v = sv[b][w]; ix = si[b][w]; }
        g_qpv[b * 128 + blockIdx.x] = v;
        g_qpi[b * 128 + blockIdx.x] = ix;
    }
}

// final exact reduce + exact score = sqrt(q^2 + min(d^2 - q^2))
__global__ void k_qfin(const float* __restrict__ emb) {
    int b = blockIdx.x, tid = threadIdx.x;   // 128 threads
    __shared__ float sv[128]; __shared__ int si[128];
    __shared__ float sq[128];
    sv[tid] = g_qpv[b * 128 + tid];
    si[tid] = g_qpi[b * 128 + tid];
    float e = emb[(size_t)g_qrow[b] * DDIM + tid];
    sq[tid] = e * e;
    __syncthreads();
    for (int s = 64; s > 0; s >>= 1) {
        if (tid < s) {
            if (sv[tid + s] < sv[tid] || (sv[tid + s] == sv[tid] && si[tid + s] < si[tid])) {
                sv[tid] = sv[tid + s]; si[tid] = si[tid + s];
            }
            sq[tid] += sq[tid + s];
        }
        __syncthreads();
    }
    if (tid == 0) {
        g_nnidx[b] = si[0];
        g_score[b] = sqrtf(fmaxf(sq[0] + sv[0], 0.0f));
    }
}

// ---------------- d_nn = dist(mb[nn_b], mb) for all 8 b in one mb pass ----------------
__global__ void k_dnn(const float* __restrict__ mb) {
    int warp = threadIdx.x >> 5, lane = threadIdx.x & 31;
    float4 q[BATCH]; float y2q[BATCH];
    #pragma unroll
    for (int b = 0; b < BATCH; b++) {
        int nn = g_nnidx[b];
        q[b] = reinterpret_cast<const float4*>(mb + (size_t)nn * DDIM)[lane];
        y2q[b] = g_y2[nn];
    }
    int base = blockIdx.x * 256 + warp * 32;
    for (int i = 0; i < 32; i++) {
        int row = base + i;
        float4 m = reinterpret_cast<const float4*>(mb + (size_t)row * DDIM)[lane];
        float y2r = g_y2[row];
        #pragma unroll
        for (int b = 0; b < BATCH; b++) {
            float dot = q[b].x * m.x + q[b].y * m.y + q[b].z * m.z + q[b].w * m.w;
            #pragma unroll
            for (int o = 16; o > 0; o >>= 1) dot += __shfl_xor_sync(0xFFFFFFFF, dot, o);
            if (lane == 0)
                g_dnn[b * MROWS + row] = sqrtf(fmaxf(y2q[b] - 2.0f * dot + y2r, 0.0f));
        }
    }
}

// ---------------- single-pass top-9 + softmax reweight -> pred_score ----------------
__global__ void k_final(const float* __restrict__ emb, const float* __restrict__ mb,
                        float* __restrict__ out) {
    int b = blockIdx.x, tid = threadIdx.x;
    __shared__ float hv[256];
    __shared__ int hidx[256];
    __shared__ int hthr[256];
    __shared__ int sel[KNEIGH];
    __shared__ float dists[KNEIGH];

    float tv[KNEIGH]; int ti9[KNEIGH];
    #pragma unroll
    for (int j = 0; j < KNEIGH; j++) { tv[j] = FLT_MAX; ti9[j] = INT_MAX; }
    for (int m = tid; m < MROWS; m += 256) {
        float v = g_dnn[b * MROWS + m];
        if (v < tv[KNEIGH - 1]) {
            int pos = KNEIGH - 1;
            while (pos > 0 && v < tv[pos - 1]) {
                tv[pos] = tv[pos - 1]; ti9[pos] = ti9[pos - 1]; pos--;
            }
            tv[pos] = v; ti9[pos] = m;
        }
    }

    int cur = 0;
    for (int it = 0; it < KNEIGH; it++) {
        hv[tid] = (cur < KNEIGH) ? tv[cur] : FLT_MAX;
        hidx[tid] = (cur < KNEIGH) ? ti9[cur] : INT_MAX;
        hthr[tid] = tid;
        __syncthreads();
        for (int s = 128; s > 0; s >>= 1) {
            if (tid < s) {
                if (hv[tid + s] < hv[tid] ||
                    (hv[tid + s] == hv[tid] && hidx[tid + s] < hidx[tid])) {
                    hv[tid] = hv[tid + s]; hidx[tid] = hidx[tid + s]; hthr[tid] = hthr[tid + s];
                }
            }
            __syncthreads();
        }
        if (tid == 0) sel[it] = hidx[0];
        int win = hthr[0];
        __syncthreads();
        if (tid == win) cur++;
    }

    if (tid < KNEIGH) {
        const float* q = emb + (size_t)g_qrow[b] * DDIM;
        const float* m = mb + (size_t)sel[tid] * DDIM;
        float dot = 0.0f, q2 = 0.0f;
        #pragma unroll 4
        for (int d = 0; d < DDIM; d++) { dot += q[d] * m[d]; q2 += q[d] * q[d]; }
        float d2 = q2 - 2.0f * dot + g_y2[sel[tid]];
        dists[tid] = sqrtf(fmaxf(d2, 0.0f));
    }
    __syncthreads();
    if (tid == 0) {
        float mx = dists[0];
        for (int j = 1; j < KNEIGH; j++) mx = fmaxf(mx, dists[j]);
        float sum = 0.0f, e0 = 0.0f;
        for (int j = 0; j < KNEIGH; j++) {
            float e = expf(dists[j] - mx);
            if (j == 0) e0 = e;
            sum += e;
        }
        out[b] = (1.0f - e0 / sum) * g_score[b];
    }
}

// ---------------- fused upsample + separable Gaussian blur ----------------
__global__ void k_map(float* __restrict__ out) {
    char* smem = s_raw;
    float* pm = reinterpret_cast<float*>(smem + MAP_PM);
    float* gs = reinterpret_cast<float*>(smem + MAP_GS);
    float* up = reinterpret_cast<float*>(smem + MAP_UP);   // [48][224]
    float* vt = reinterpret_cast<float*>(smem + MAP_VT);   // [16][224]
    const int band = blockIdx.x, b = blockIdx.y;
    const int tid = threadIdx.x;
    const int r0 = band * 16;

    for (int i = tid; i < PPB; i += 256) pm[i] = g_pscore[b * PPB + i];
    if (tid < KSIZE) gs[tid] = g_gauss[tid];
    __syncthreads();

    for (int i = tid; i < 48 * 224; i += 256) {
        int j = i / 224, V = i % 224;
        int U = r0 - 16 + j;
        if (U < 0) U = -U;
        if (U > OUTSZ - 1) U = 2 * (OUTSZ - 1) - U;
        float su = ((float)U + 0.5f) * 0.125f - 0.5f;
        float sv = ((float)V + 0.5f) * 0.125f - 0.5f;
        int u0 = (int)floorf(su), v0 = (int)floorf(sv);
        float tu = su - (float)u0, tv = sv - (float)v0;
        int u0c = min(max(u0, 0), WIO - 1), u1c = min(max(u0 + 1, 0), WIO - 1);
        int v0c = min(max(v0, 0), WIO - 1), v1c = min(max(v0 + 1, 0), WIO - 1);
        float v00 = pm[u0c * WIO + v0c], v01 = pm[u0c * WIO + v1c];
        float v10 = pm[u1c * WIO + v0c], v11 = pm[u1c * WIO + v1c];
        float top = v00 + tv * (v01 - v00);
        float bot = v10 + tv * (v11 - v10);
        up[i] = top + tu * (bot - top);
    }
    __syncthreads();

    for (int i = tid; i < 16 * 224; i += 256) {
        int du = i / 224, V = i % 224;
        float acc = 0.0f;
        #pragma unroll
        for (int k = 0; k < KSIZE; k++) acc += gs[k] * up[(du + k) * 224 + V];
        vt[i] = acc;
    }
    __syncthreads();

    for (int i = tid; i < 16 * 224; i += 256) {
        int du = i / 224, V = i % 224;
        float acc = 0.0f;
        #pragma unroll
        for (int k = 0; k < KSIZE; k++) {
            int jv = V - KRAD + k;
            if (jv < 0) jv = -jv;
            if (jv > OUTSZ - 1) jv = 2 * (OUTSZ - 1) - jv;
            acc += gs[k] * vt[du * 224 + jv];
        }
        out[BATCH + (b * OUTSZ + r0 + du) * OUTSZ + V] = acc;
    }
}

// ---------------- launcher ----------------
extern "C" void kernel_launch(void* const* d_in, const int* in_sizes, int n_in,
                              void* d_out, int out_size) {
    const float* emb = (const float*)d_in[0];
    const float* mb = (const float*)d_in[1];
    float* out = (float*)d_out;

    static bool attr_set = false;
    if (!attr_set) {
        cudaFuncSetAttribute(k_dist_mma, cudaFuncAttributeMaxDynamicSharedMemorySize, SMEM_TOTAL);
        cudaFuncSetAttribute(k_map, cudaFuncAttributeMaxDynamicSharedMemorySize, MAP_SMEM);
        attr_set = true;
    }

    k_gauss_init<<<1, 32>>>();
    k_y2<<<MROWS / 8, 256>>>(mb);
    k_split<<<(MROWS * DDIM + 255) / 256, 256>>>(emb, mb);

    dim3 gdist(NROWS / BNR, NSPLIT);
    k_dist_mma<<<gdist, 128, SMEM_TOTAL>>>();

    k_reduce<<<(NROWS + 255) / 256, 256>>>(emb);
    k_imgmax<<<BATCH, 256>>>();

    k_qpart<<<128, 256>>>(emb, mb);
    k_qfin<<<BATCH, 128>>>(emb);
    k_dnn<<<128, 256>>>(mb);

    k_final<<<BATCH, 256>>>(emb, mb, out);

    dim3 gmap(14, BATCH);
    k_map<<<gmap, 256, MAP_SMEM>>>(out);
}

// round 11
// speedup vs baseline: 7.7169x; 1.1656x over previous
#include <cuda_runtime.h>
#include <cuda_bf16.h>
#include <math.h>
#include <float.h>
#include <limits.h>
#include <stdint.h>

// ---------------- problem constants (fixed shapes) ----------------
#define NROWS 6272      // embedding rows
#define MROWS 32768     // memory bank rows
#define DDIM  128
#define BATCH 8
#define PPB   784
#define WIO   28
#define OUTSZ 224
#define KNEIGH 9
#define KSIZE 33
#define KRAD  16

#define NSPLIT 6
#define BNR 128                 // emb rows per CTA
#define BMC 128                 // mb cols per tile
#define NTILES (MROWS / BMC)    // 256
#define LDTB 272                // smem tile row stride bytes (136 bf16)
#define TILE_BYTES (128 * LDTB) // 34816

// k_dist smem byte offsets
#define OFF_A     0
#define OFF_B0    (OFF_A + TILE_BYTES)
#define OFF_B1    (OFF_B0 + TILE_BYTES)
#define OFF_Y2    (OFF_B1 + TILE_BYTES)        // 2 x 128 floats (halved y2)
#define OFF_RED   (OFF_Y2 + 1024)              // 128*2 floats
#define SMEM_TOTAL (OFF_RED + 1024)            // 106496 bytes -> 2 CTAs/SM

// k_map smem layout
#define MAP_PM    0                            // 784 floats
#define MAP_GS    3136                         // 33 floats
#define MAP_UP    3280                         // 48*224 floats
#define MAP_VT    (MAP_UP + 48*224*4)          // 16*224 floats
#define MAP_SMEM  (MAP_VT + 16*224*4)          // 60624 bytes

#define NDNN 9216                              // per-image dnn top9 partials (128 blk * 8 warps * 9)

// ---------------- device scratch ----------------
__device__ float g_y2[MROWS];
__device__ float g_y2h[MROWS];                // 0.5 * y2
__device__ float g_x2[NROWS];                 // ||emb row||^2
__device__ float g_pval[NSPLIT * NROWS];
__device__ float g_pscore[NROWS];
__device__ int   g_qrow[BATCH];
__device__ float g_score[BATCH];
__device__ int   g_nnidx[BATCH];
__device__ float g_qpv[BATCH * 128];          // exact argmin partials (d^2 - q^2)
__device__ int   g_qpi[BATCH * 128];
__device__ float g_d9v[BATCH * NDNN];         // dnn top9 partial values
__device__ int   g_d9i[BATCH * NDNN];         // dnn top9 partial indices
__device__ float g_gauss[KSIZE];
// bf16 hi parts
__device__ __nv_bfloat16 g_embh[NROWS * DDIM];
__device__ __nv_bfloat16 g_mbh[MROWS * DDIM];

// ---------------- small helpers ----------------
__device__ __forceinline__ uint32_t smem_u32(const void* p) {
    uint32_t a;
    asm("{ .reg .u64 t; cvta.to.shared.u64 t, %1; cvt.u32.u64 %0, t; }" : "=r"(a) : "l"(p));
    return a;
}
__device__ __forceinline__ void cp_async16(uint32_t dst, const void* src) {
    asm volatile("cp.async.cg.shared.global [%0], [%1], 16;" :: "r"(dst), "l"(src));
}
#define CP_COMMIT() asm volatile("cp.async.commit_group;" ::: "memory")
#define CP_WAIT0()  asm volatile("cp.async.wait_group 0;" ::: "memory")

__device__ __forceinline__ void ldm_x4(uint32_t addr, uint32_t& r0, uint32_t& r1,
                                       uint32_t& r2, uint32_t& r3) {
    asm volatile("ldmatrix.sync.aligned.m8n8.x4.shared.b16 {%0,%1,%2,%3}, [%4];"
                 : "=r"(r0), "=r"(r1), "=r"(r2), "=r"(r3) : "r"(addr));
}
__device__ __forceinline__ void mma16816(float* c, const uint32_t* a, const uint32_t* b) {
    asm volatile("mma.sync.aligned.m16n8k16.row.col.f32.bf16.bf16.f32 "
                 "{%0,%1,%2,%3}, {%4,%5,%6,%7}, {%8,%9}, {%0,%1,%2,%3};"
                 : "+f"(c[0]), "+f"(c[1]), "+f"(c[2]), "+f"(c[3])
                 : "r"(a[0]), "r"(a[1]), "r"(a[2]), "r"(a[3]), "r"(b[0]), "r"(b[1]));
}

// ---------------- k_prep: gauss + y2 + x2 + bf16 split, warp-per-row ----------------
// grid (MROWS+NROWS)/8 = 4880 blocks, 256 threads (8 warps)
__global__ void k_prep(const float* __restrict__ emb, const float* __restrict__ mb) {
    if (blockIdx.x == 0 && threadIdx.x == 0) {
        float tmp[KSIZE]; float s = 0.0f;
        for (int i = 0; i < KSIZE; i++) {
            float x = (float)i - (float)(KSIZE - 1) * 0.5f;
            float t = x / 4.0f;
            tmp[i] = expf(-0.5f * t * t); s += tmp[i];
        }
        for (int i = 0; i < KSIZE; i++) g_gauss[i] = tmp[i] / s;
    }
    int warp = threadIdx.x >> 5, lane = threadIdx.x & 31;
    int row = blockIdx.x * 8 + warp;
    const float* src;
    __nv_bfloat16* dst;
    int r;
    if (row < MROWS) { src = mb; dst = g_mbh; r = row; }
    else             { src = emb; dst = g_embh; r = row - MROWS; }
    float4 v = reinterpret_cast<const float4*>(src + (size_t)r * DDIM)[lane];
    float s = v.x * v.x + v.y * v.y + v.z * v.z + v.w * v.w;
    #pragma unroll
    for (int o = 16; o > 0; o >>= 1) s += __shfl_xor_sync(0xFFFFFFFF, s, o);
    // write bf16 hi (4 values = 8 bytes per lane)
    __nv_bfloat162 h0, h1;
    h0.x = __float2bfloat16_rn(v.x); h0.y = __float2bfloat16_rn(v.y);
    h1.x = __float2bfloat16_rn(v.z); h1.y = __float2bfloat16_rn(v.w);
    uint2 packed;
    packed.x = *reinterpret_cast<uint32_t*>(&h0);
    packed.y = *reinterpret_cast<uint32_t*>(&h1);
    reinterpret_cast<uint2*>(dst + (size_t)r * DDIM)[lane] = packed;
    if (lane == 0) {
        if (row < MROWS) { g_y2[r] = s; g_y2h[r] = 0.5f * s; }
        else             { g_x2[r] = s; }
    }
}

// ---------------- mma.sync fused distance GEMM (K=128, bf16-hi) + max ----------------
extern __shared__ char s_raw[];

__device__ __forceinline__ void load_tile_async(uint32_t sm_dst,
                                                const __nv_bfloat16* __restrict__ src,
                                                int row0, int tid) {
    #pragma unroll
    for (int k = 0; k < 16; k++) {
        int i = k * 128 + tid;
        int r = i >> 4;             // 0..127
        int c = i & 15;             // 16B chunk within 256B row
        cp_async16(sm_dst + (uint32_t)(r * LDTB + c * 16),
                   (const char*)(src + (size_t)(row0 + r) * DDIM) + c * 16);
    }
}

__global__ void __launch_bounds__(128, 2) k_dist_mma() {
    char* smem = s_raw;
    const uint32_t sbase = smem_u32(smem);
    const int tid = threadIdx.x;
    const int wid = tid >> 5;
    const int lane = tid & 31;
    const int wm = wid & 1;          // M half: rows wm*64..+63
    const int wn = wid >> 1;         // N half: cols wn*64..+63
    const int rowBase = blockIdx.x * BNR;

    const int tile0 = (blockIdx.y * NTILES) / NSPLIT;
    const int tile1 = ((blockIdx.y + 1) * NTILES) / NSPLIT;

    const uint32_t A = sbase + OFF_A;
    const uint32_t B[2] = { sbase + OFF_B0, sbase + OFF_B1 };
    float* y2s = reinterpret_cast<float*>(smem + OFF_Y2);

    const int a_row = lane & 15;
    const int a_koff = (lane >> 4) << 3;
    const uint32_t aOff = (uint32_t)((wm * 64 + a_row) * LDTB + a_koff * 2);
    const int b_n = (lane & 7) + ((lane >> 4) << 3);
    const int b_koff = ((lane >> 3) & 1) << 3;
    const uint32_t bOff = (uint32_t)((wn * 64 + b_n) * LDTB + b_koff * 2);

    load_tile_async(A, g_embh, rowBase, tid);
    load_tile_async(B[0], g_mbh, tile0 * BMC, tid);
    if (tid < 32)
        cp_async16(sbase + OFF_Y2 + tid * 16, (const char*)(g_y2h + tile0 * BMC) + tid * 16);
    CP_COMMIT();
    CP_WAIT0();
    __syncthreads();

    float bestV[8];
    #pragma unroll
    for (int i = 0; i < 8; i++) bestV[i] = -FLT_MAX;

    for (int t = tile0; t < tile1; t++) {
        const int buf = (t - tile0) & 1;

        if (t + 1 < tile1) {
            const int nb = buf ^ 1;
            load_tile_async(B[nb], g_mbh, (t + 1) * BMC, tid);
            if (tid < 32)
                cp_async16(sbase + OFF_Y2 + (uint32_t)(nb * 512 + tid * 16),
                           (const char*)(g_y2h + (size_t)(t + 1) * BMC) + tid * 16);
            CP_COMMIT();
        }

        float acc[4][8][4];
        #pragma unroll
        for (int mf = 0; mf < 4; mf++)
            #pragma unroll
            for (int nf = 0; nf < 8; nf++)
                #pragma unroll
                for (int r = 0; r < 4; r++) acc[mf][nf][r] = 0.0f;

        const uint32_t aB = A + aOff;
        const uint32_t bB = B[buf] + bOff;
        #pragma unroll
        for (int kc = 0; kc < 8; kc++) {
            const uint32_t kByte = (uint32_t)(kc << 5);
            uint32_t af[4][4];
            #pragma unroll
            for (int mf = 0; mf < 4; mf++)
                ldm_x4(aB + (uint32_t)(mf * 16 * LDTB) + kByte,
                       af[mf][0], af[mf][1], af[mf][2], af[mf][3]);
            uint32_t bf[8][2];
            #pragma unroll
            for (int q = 0; q < 4; q++) {
                uint32_t r0, r1, r2, r3;
                ldm_x4(bB + (uint32_t)(q * 16 * LDTB) + kByte, r0, r1, r2, r3);
                bf[q * 2][0] = r0; bf[q * 2][1] = r1;
                bf[q * 2 + 1][0] = r2; bf[q * 2 + 1][1] = r3;
            }
            #pragma unroll
            for (int mf = 0; mf < 4; mf++)
                #pragma unroll
                for (int nf = 0; nf < 8; nf++)
                    mma16816(acc[mf][nf], af[mf], bf[nf]);
        }

        // ---- epilogue: s = dot - 0.5*y2, running max (value only) ----
        {
            const float2* hy2 = reinterpret_cast<const float2*>(y2s + buf * 128);
            float2 hv[8];
            #pragma unroll
            for (int nf = 0; nf < 8; nf++)
                hv[nf] = hy2[(wn * 64 + nf * 8 + (lane & 3) * 2) >> 1];
            #pragma unroll
            for (int mf = 0; mf < 4; mf++) {
                #pragma unroll
                for (int h = 0; h < 2; h++) {
                    const int slot = mf * 2 + h;
                    float bv = bestV[slot];
                    #pragma unroll
                    for (int nf = 0; nf < 8; nf++) {
                        float s0 = acc[mf][nf][h * 2] - hv[nf].x;
                        float s1 = acc[mf][nf][h * 2 + 1] - hv[nf].y;
                        bv = fmaxf(bv, fmaxf(s0, s1));
                    }
                    bestV[slot] = bv;
                }
            }
        }

        if (t + 1 < tile1) CP_WAIT0();
        __syncthreads();
    }

    float* redV = reinterpret_cast<float*>(smem + OFF_RED);
    #pragma unroll
    for (int slot = 0; slot < 8; slot++) {
        float v = bestV[slot];
        v = fmaxf(v, __shfl_xor_sync(0xFFFFFFFF, v, 1));
        v = fmaxf(v, __shfl_xor_sync(0xFFFFFFFF, v, 2));
        if ((lane & 3) == 0) {
            int mf = slot >> 1, h = slot & 1;
            int row = wm * 64 + mf * 16 + (lane >> 2) + h * 8;
            redV[row * 2 + wn] = v;
        }
    }
    __syncthreads();
    if (tid < BNR) {
        float bv = fmaxf(redV[tid * 2], redV[tid * 2 + 1]);
        g_pval[blockIdx.y * NROWS + rowBase + tid] = bv;
    }
}

// ---------------- fused: patch scores + per-image argmax ----------------
// grid BATCH, 256 threads; block b handles rows b*784..+783
__global__ void k_score() {
    int b = blockIdx.x, tid = threadIdx.x;
    __shared__ float sv[256]; __shared__ int si[256];
    float bmax = -FLT_MAX; int bi = INT_MAX;
    for (int p = tid; p < PPB; p += 256) {
        int row = b * PPB + p;
        float bv = -FLT_MAX;
        #pragma unroll
        for (int s = 0; s < NSPLIT; s++) bv = fmaxf(bv, g_pval[s * NROWS + row]);
        float d2 = g_x2[row] - 2.0f * bv;
        float sc = sqrtf(fmaxf(d2, 0.0f));
        g_pscore[row] = sc;
        if (sc > bmax || (sc == bmax && p < bi)) { bmax = sc; bi = p; }
    }
    sv[tid] = bmax; si[tid] = bi;
    __syncthreads();
    for (int s = 128; s > 0; s >>= 1) {
        if (tid < s) {
            if (sv[tid + s] > sv[tid] || (sv[tid + s] == sv[tid] && si[tid + s] < si[tid])) {
                sv[tid] = sv[tid + s]; si[tid] = si[tid + s];
            }
        }
        __syncthreads();
    }
    if (tid == 0) g_qrow[b] = b * PPB + si[0];
}

// ---------------- exact fp32 argmin over mb for query row b (per-image) ----------------
// grid (128, 8), block 256 = 8 warps x 32 rows
__global__ void k_qpart(const float* __restrict__ emb, const float* __restrict__ mb) {
    int b = blockIdx.y;
    int warp = threadIdx.x >> 5, lane = threadIdx.x & 31;
    float4 q = reinterpret_cast<const float4*>(emb + (size_t)g_qrow[b] * DDIM)[lane];
    float bv = FLT_MAX; int bi = INT_MAX;
    int base = blockIdx.x * 256 + warp * 32;
    for (int i = 0; i < 32; i++) {
        int row = base + i;
        float4 m = reinterpret_cast<const float4*>(mb + (size_t)row * DDIM)[lane];
        float dot = q.x * m.x + q.y * m.y + q.z * m.z + q.w * m.w;
        #pragma unroll
        for (int o = 16; o > 0; o >>= 1) dot += __shfl_xor_sync(0xFFFFFFFF, dot, o);
        float d2 = g_y2[row] - 2.0f * dot;   // +q^2 constant: argmin-invariant
        if (d2 < bv) { bv = d2; bi = row; }
    }
    __shared__ float sv[8]; __shared__ int si[8];
    if (lane == 0) { sv[warp] = bv; si[warp] = bi; }
    __syncthreads();
    if (threadIdx.x == 0) {
        float v = sv[0]; int ix = si[0];
        for (int w = 1; w < 8; w++)
            if (sv[w] < v || (sv[w] == v && si[w] < ix)) { v = sv[w]; ix = si[w]; }
        g_qpv[b * 128 + blockIdx.x] = v;
        g_qpi[b * 128 + blockIdx.x] = ix;
    }
}

// final exact reduce + exact score = sqrt(q^2 + min(d^2 - q^2))
__global__ void k_qfin() {
    int b = blockIdx.x, tid = threadIdx.x;   // 128 threads
    __shared__ float sv[128]; __shared__ int si[128];
    sv[tid] = g_qpv[b * 128 + tid];
    si[tid] = g_qpi[b * 128 + tid];
    __syncthreads();
    for (int s = 64; s > 0; s >>= 1) {
        if (tid < s) {
            if (sv[tid + s] < sv[tid] || (sv[tid + s] == sv[tid] && si[tid + s] < si[tid])) {
                sv[tid] = sv[tid + s]; si[tid] = si[tid + s];
            }
        }
        __syncthreads();
    }
    if (tid == 0) {
        g_nnidx[b] = si[0];
        g_score[b] = sqrtf(fmaxf(g_x2[g_qrow[b]] + sv[0], 0.0f));
    }
}

// ---------------- dnn distances + per-warp top-9 partials (per-image) ----------------
// grid (128, 8), block 256 = 8 warps x 32 rows
__global__ void k_dnn9(const float* __restrict__ mb) {
    int b = blockIdx.y;
    int warp = threadIdx.x >> 5, lane = threadIdx.x & 31;
    int nn = g_nnidx[b];
    float4 q = reinterpret_cast<const float4*>(mb + (size_t)nn * DDIM)[lane];
    float y2q = g_y2[nn];

    float tv[KNEIGH]; int ti9[KNEIGH];
    #pragma unroll
    for (int j = 0; j < KNEIGH; j++) { tv[j] = FLT_MAX; ti9[j] = INT_MAX; }

    int base = blockIdx.x * 256 + warp * 32;
    for (int i = 0; i < 32; i++) {
        int row = base + i;
        float4 m = reinterpret_cast<const float4*>(mb + (size_t)row * DDIM)[lane];
        float dot = q.x * m.x + q.y * m.y + q.z * m.z + q.w * m.w;
        #pragma unroll
        for (int o = 16; o > 0; o >>= 1) dot += __shfl_xor_sync(0xFFFFFFFF, dot, o);
        if (lane == 0) {
            float v = sqrtf(fmaxf(y2q - 2.0f * dot + g_y2[row], 0.0f));
            if (v < tv[KNEIGH - 1]) {
                int pos = KNEIGH - 1;
                while (pos > 0 && v < tv[pos - 1]) {
                    tv[pos] = tv[pos - 1]; ti9[pos] = ti9[pos - 1]; pos--;
                }
                tv[pos] = v; ti9[pos] = row;
            }
        }
    }
    if (lane == 0) {
        int off = b * NDNN + (blockIdx.x * 8 + warp) * KNEIGH;
        #pragma unroll
        for (int j = 0; j < KNEIGH; j++) { g_d9v[off + j] = tv[j]; g_d9i[off + j] = ti9[j]; }
    }
}

// ---------------- merge partials -> top-9 -> softmax reweight -> pred_score ----------------
__global__ void k_final(const float* __restrict__ emb, const float* __restrict__ mb,
                        float* __restrict__ out) {
    int b = blockIdx.x, tid = threadIdx.x;
    __shared__ float hv[256];
    __shared__ int hidx[256];
    __shared__ int hthr[256];
    __shared__ int sel[KNEIGH];
    __shared__ float dists[KNEIGH];

    // per-thread sorted top-9 over strided subset of the 9216 partials
    float tv[KNEIGH]; int ti9[KNEIGH];
    #pragma unroll
    for (int j = 0; j < KNEIGH; j++) { tv[j] = FLT_MAX; ti9[j] = INT_MAX; }
    for (int m = tid; m < NDNN; m += 256) {
        float v = g_d9v[b * NDNN + m];
        int ix = g_d9i[b * NDNN + m];
        if (v < tv[KNEIGH - 1] || (v == tv[KNEIGH - 1] && ix < ti9[KNEIGH - 1])) {
            int pos = KNEIGH - 1;
            while (pos > 0 && (v < tv[pos - 1] || (v == tv[pos - 1] && ix < ti9[pos - 1]))) {
                tv[pos] = tv[pos - 1]; ti9[pos] = ti9[pos - 1]; pos--;
            }
            tv[pos] = v; ti9[pos] = ix;
        }
    }

    // 9-round 256-way merge
    int cur = 0;
    for (int it = 0; it < KNEIGH; it++) {
        hv[tid] = (cur < KNEIGH) ? tv[cur] : FLT_MAX;
        hidx[tid] = (cur < KNEIGH) ? ti9[cur] : INT_MAX;
        hthr[tid] = tid;
        __syncthreads();
        for (int s = 128; s > 0; s >>= 1) {
            if (tid < s) {
                if (hv[tid + s] < hv[tid] ||
                    (hv[tid + s] == hv[tid] && hidx[tid + s] < hidx[tid])) {
                    hv[tid] = hv[tid + s]; hidx[tid] = hidx[tid + s]; hthr[tid] = hthr[tid + s];
                }
            }
            __syncthreads();
        }
        if (tid == 0) sel[it] = hidx[0];
        int win = hthr[0];
        __syncthreads();
        if (tid == win) cur++;
    }

    if (tid < KNEIGH) {
        const float* q = emb + (size_t)g_qrow[b] * DDIM;
        const float* m = mb + (size_t)sel[tid] * DDIM;
        float dot = 0.0f, q2 = 0.0f;
        #pragma unroll 4
        for (int d = 0; d < DDIM; d++) { dot += q[d] * m[d]; q2 += q[d] * q[d]; }
        float d2 = q2 - 2.0f * dot + g_y2[sel[tid]];
        dists[tid] = sqrtf(fmaxf(d2, 0.0f));
    }
    __syncthreads();
    if (tid == 0) {
        float mx = dists[0];
        for (int j = 1; j < KNEIGH; j++) mx = fmaxf(mx, dists[j]);
        float sum = 0.0f, e0 = 0.0f;
        for (int j = 0; j < KNEIGH; j++) {
            float e = expf(dists[j] - mx);
            if (j == 0) e0 = e;
            sum += e;
        }
        out[b] = (1.0f - e0 / sum) * g_score[b];
    }
}

// ---------------- fused upsample + separable Gaussian blur ----------------
__global__ void k_map(float* __restrict__ out) {
    char* smem = s_raw;
    float* pm = reinterpret_cast<float*>(smem + MAP_PM);
    float* gs = reinterpret_cast<float*>(smem + MAP_GS);
    float* up = reinterpret_cast<float*>(smem + MAP_UP);   // [48][224]
    float* vt = reinterpret_cast<float*>(smem + MAP_VT);   // [16][224]
    const int band = blockIdx.x, b = blockIdx.y;
    const int tid = threadIdx.x;
    const int r0 = band * 16;

    for (int i = tid; i < PPB; i += 256) pm[i] = g_pscore[b * PPB + i];
    if (tid < KSIZE) gs[tid] = g_gauss[tid];
    __syncthreads();

    for (int i = tid; i < 48 * 224; i += 256) {
        int j = i / 224, V = i % 224;
        int U = r0 - 16 + j;
        if (U < 0) U = -U;
        if (U > OUTSZ - 1) U = 2 * (OUTSZ - 1) - U;
        float su = ((float)U + 0.5f) * 0.125f - 0.5f;
        float sv = ((float)V + 0.5f) * 0.125f - 0.5f;
        int u0 = (int)floorf(su), v0 = (int)floorf(sv);
        float tu = su - (float)u0, tvv = sv - (float)v0;
        int u0c = min(max(u0, 0), WIO - 1), u1c = min(max(u0 + 1, 0), WIO - 1);
        int v0c = min(max(v0, 0), WIO - 1), v1c = min(max(v0 + 1, 0), WIO - 1);
        float v00 = pm[u0c * WIO + v0c], v01 = pm[u0c * WIO + v1c];
        float v10 = pm[u1c * WIO + v0c], v11 = pm[u1c * WIO + v1c];
        float top = v00 + tvv * (v01 - v00);
        float bot = v10 + tvv * (v11 - v10);
        up[i] = top + tu * (bot - top);
    }
    __syncthreads();

    for (int i = tid; i < 16 * 224; i += 256) {
        int du = i / 224, V = i % 224;
        float acc = 0.0f;
        #pragma unroll
        for (int k = 0; k < KSIZE; k++) acc += gs[k] * up[(du + k) * 224 + V];
        vt[i] = acc;
    }
    __syncthreads();

    for (int i = tid; i < 16 * 224; i += 256) {
        int du = i / 224, V = i % 224;
        float acc = 0.0f;
        #pragma unroll
        for (int k = 0; k < KSIZE; k++) {
            int jv = V - KRAD + k;
            if (jv < 0) jv = -jv;
            if (jv > OUTSZ - 1) jv = 2 * (OUTSZ - 1) - jv;
            acc += gs[k] * vt[du * 224 + jv];
        }
        out[BATCH + (b * OUTSZ + r0 + du) * OUTSZ + V] = acc;
    }
}

// ---------------- launcher ----------------
extern "C" void kernel_launch(void* const* d_in, const int* in_sizes, int n_in,
                              void* d_out, int out_size) {
    const float* emb = (const float*)d_in[0];
    const float* mb = (const float*)d_in[1];
    float* out = (float*)d_out;

    static bool attr_set = false;
    if (!attr_set) {
        cudaFuncSetAttribute(k_dist_mma, cudaFuncAttributeMaxDynamicSharedMemorySize, SMEM_TOTAL);
        cudaFuncSetAttribute(k_map, cudaFuncAttributeMaxDynamicSharedMemorySize, MAP_SMEM);
        attr_set = true;
    }

    k_prep<<<(MROWS + NROWS) / 8, 256>>>(emb, mb);

    dim3 gdist(NROWS / BNR, NSPLIT);
    k_dist_mma<<<gdist, 128, SMEM_TOTAL>>>();

    k_score<<<BATCH, 256>>>();

    dim3 gq(128, BATCH);
    k_qpart<<<gq, 256>>>(emb, mb);
    k_qfin<<<BATCH, 128>>>();

    dim3 gd9(128, BATCH);
    k_dnn9<<<gd9, 256>>>(mb);

    k_final<<<BATCH, 256>>>(emb, mb, out);

    dim3 gmap(14, BATCH);
    k_map<<<gmap, 256, MAP_SMEM>>>(out);
}

// round 12
// speedup vs baseline: 7.7734x; 1.0073x over previous
#include <cuda_runtime.h>
#include <cuda_bf16.h>
#include <math.h>
#include <float.h>
#include <limits.h>
#include <stdint.h>

// ---------------- problem constants (fixed shapes) ----------------
#define NROWS 6272      // embedding rows
#define MROWS 32768     // memory bank rows
#define DDIM  128
#define BATCH 8
#define PPB   784
#define WIO   28
#define OUTSZ 224
#define KNEIGH 9
#define KSIZE 33
#define KRAD  16

#define NSPLIT 9
#define BNR 128                 // emb rows per CTA
#define BMC 64                  // mb cols per tile step
#define NTILES (MROWS / BMC)    // 512
#define LDTB 272                // smem tile row stride bytes (136 bf16)
#define TILE_A (128 * LDTB)     // 34816
#define TILE_B (64 * LDTB)      // 17408

// k_dist smem byte offsets
#define OFF_A     0
#define OFF_B0    (OFF_A + TILE_A)
#define OFF_B1    (OFF_B0 + TILE_B)
#define OFF_Y2    (OFF_B1 + TILE_B)            // 2 x 64 floats (halved y2)
#define OFF_RED   (OFF_Y2 + 512)               // 128*2 floats
#define SMEM_TOTAL (OFF_RED + 1024)            // 71680 bytes -> 3 CTAs/SM

// k_map smem layout
#define MAP_PM    0                            // 784 floats
#define MAP_GS    3136                         // 33 floats
#define MAP_UP    3280                         // 48*224 floats
#define MAP_VT    (MAP_UP + 48*224*4)          // 16*224 floats
#define MAP_SMEM  (MAP_VT + 16*224*4)          // 60624 bytes

#define NDNN 9216                              // per-image dnn top9 partials

// ---------------- device scratch ----------------
__device__ float g_y2[MROWS];
__device__ float g_y2h[MROWS];                // 0.5 * y2
__device__ float g_x2[NROWS];                 // ||emb row||^2
__device__ float g_pval[NSPLIT * NROWS];
__device__ float g_pscore[NROWS];
__device__ int   g_qrow[BATCH];
__device__ unsigned long long g_nnkey[BATCH]; // packed (ordered d2-q2 | idx)
__device__ float g_d9v[BATCH * NDNN];
__device__ int   g_d9i[BATCH * NDNN];
__device__ float g_gauss[KSIZE];
__device__ __nv_bfloat16 g_embh[NROWS * DDIM];
__device__ __nv_bfloat16 g_mbh[MROWS * DDIM];

// ---------------- small helpers ----------------
__device__ __forceinline__ uint32_t smem_u32(const void* p) {
    uint32_t a;
    asm("{ .reg .u64 t; cvta.to.shared.u64 t, %1; cvt.u32.u64 %0, t; }" : "=r"(a) : "l"(p));
    return a;
}
__device__ __forceinline__ void cp_async16(uint32_t dst, const void* src) {
    asm volatile("cp.async.cg.shared.global [%0], [%1], 16;" :: "r"(dst), "l"(src));
}
#define CP_COMMIT() asm volatile("cp.async.commit_group;" ::: "memory")
#define CP_WAIT0()  asm volatile("cp.async.wait_group 0;" ::: "memory")

__device__ __forceinline__ void ldm_x4(uint32_t addr, uint32_t& r0, uint32_t& r1,
                                       uint32_t& r2, uint32_t& r3) {
    asm volatile("ldmatrix.sync.aligned.m8n8.x4.shared.b16 {%0,%1,%2,%3}, [%4];"
                 : "=r"(r0), "=r"(r1), "=r"(r2), "=r"(r3) : "r"(addr));
}
__device__ __forceinline__ void mma16816(float* c, const uint32_t* a, const uint32_t* b) {
    asm volatile("mma.sync.aligned.m16n8k16.row.col.f32.bf16.bf16.f32 "
                 "{%0,%1,%2,%3}, {%4,%5,%6,%7}, {%8,%9}, {%0,%1,%2,%3};"
                 : "+f"(c[0]), "+f"(c[1]), "+f"(c[2]), "+f"(c[3])
                 : "r"(a[0]), "r"(a[1]), "r"(a[2]), "r"(a[3]), "r"(b[0]), "r"(b[1]));
}
// order-preserving float->uint map and inverse
__device__ __forceinline__ uint32_t f2ord(float f) {
    uint32_t u = __float_as_uint(f);
    return (u & 0x80000000u) ? ~u : (u | 0x80000000u);
}
__device__ __forceinline__ float ord2f(uint32_t u) {
    uint32_t b = (u & 0x80000000u) ? (u & 0x7FFFFFFFu) : ~u;
    return __uint_as_float(b);
}

// ---------------- k_prep: gauss + y2 + x2 + bf16 split, warp-per-row ----------------
__global__ void k_prep(const float* __restrict__ emb, const float* __restrict__ mb) {
    if (blockIdx.x == 0 && threadIdx.x == 0) {
        float tmp[KSIZE]; float s = 0.0f;
        for (int i = 0; i < KSIZE; i++) {
            float x = (float)i - (float)(KSIZE - 1) * 0.5f;
            float t = x / 4.0f;
            tmp[i] = expf(-0.5f * t * t); s += tmp[i];
        }
        for (int i = 0; i < KSIZE; i++) g_gauss[i] = tmp[i] / s;
    }
    int warp = threadIdx.x >> 5, lane = threadIdx.x & 31;
    int row = blockIdx.x * 8 + warp;
    const float* src;
    __nv_bfloat16* dst;
    int r;
    if (row < MROWS) { src = mb; dst = g_mbh; r = row; }
    else             { src = emb; dst = g_embh; r = row - MROWS; }
    float4 v = reinterpret_cast<const float4*>(src + (size_t)r * DDIM)[lane];
    float s = v.x * v.x + v.y * v.y + v.z * v.z + v.w * v.w;
    #pragma unroll
    for (int o = 16; o > 0; o >>= 1) s += __shfl_xor_sync(0xFFFFFFFF, s, o);
    __nv_bfloat162 h0, h1;
    h0.x = __float2bfloat16_rn(v.x); h0.y = __float2bfloat16_rn(v.y);
    h1.x = __float2bfloat16_rn(v.z); h1.y = __float2bfloat16_rn(v.w);
    uint2 packed;
    packed.x = *reinterpret_cast<uint32_t*>(&h0);
    packed.y = *reinterpret_cast<uint32_t*>(&h1);
    reinterpret_cast<uint2*>(dst + (size_t)r * DDIM)[lane] = packed;
    if (lane == 0) {
        if (row < MROWS) { g_y2[r] = s; g_y2h[r] = 0.5f * s; }
        else             { g_x2[r] = s; }
    }
}

// ---------------- mma.sync fused distance GEMM (K=128, bf16-hi) + max ----------------
extern __shared__ char s_raw[];

__device__ __forceinline__ void load_tileA_async(uint32_t sm_dst,
                                                 const __nv_bfloat16* __restrict__ src,
                                                 int row0, int tid) {
    #pragma unroll
    for (int k = 0; k < 16; k++) {
        int i = k * 128 + tid;
        int r = i >> 4, c = i & 15;
        cp_async16(sm_dst + (uint32_t)(r * LDTB + c * 16),
                   (const char*)(src + (size_t)(row0 + r) * DDIM) + c * 16);
    }
}
__device__ __forceinline__ void load_tileB_async(uint32_t sm_dst,
                                                 const __nv_bfloat16* __restrict__ src,
                                                 int row0, int tid) {
    #pragma unroll
    for (int k = 0; k < 8; k++) {
        int i = k * 128 + tid;
        int r = i >> 4, c = i & 15;
        cp_async16(sm_dst + (uint32_t)(r * LDTB + c * 16),
                   (const char*)(src + (size_t)(row0 + r) * DDIM) + c * 16);
    }
}

__global__ void __launch_bounds__(128, 3) k_dist_mma() {
    char* smem = s_raw;
    const uint32_t sbase = smem_u32(smem);
    const int tid = threadIdx.x;
    const int wid = tid >> 5;
    const int lane = tid & 31;
    const int wm = wid & 1;          // M half: rows wm*64..+63
    const int wn = wid >> 1;         // N half: cols wn*32..+31
    const int rowBase = blockIdx.x * BNR;

    const int tile0 = (blockIdx.y * NTILES) / NSPLIT;
    const int tile1 = ((blockIdx.y + 1) * NTILES) / NSPLIT;

    const uint32_t A = sbase + OFF_A;
    const uint32_t B[2] = { sbase + OFF_B0, sbase + OFF_B1 };
    float* y2s = reinterpret_cast<float*>(smem + OFF_Y2);

    const int a_row = lane & 15;
    const int a_koff = (lane >> 4) << 3;
    const uint32_t aOff = (uint32_t)((wm * 64 + a_row) * LDTB + a_koff * 2);
    const int b_n = (lane & 7) + ((lane >> 4) << 3);
    const int b_koff = ((lane >> 3) & 1) << 3;
    const uint32_t bOff = (uint32_t)((wn * 32 + b_n) * LDTB + b_koff * 2);

    load_tileA_async(A, g_embh, rowBase, tid);
    load_tileB_async(B[0], g_mbh, tile0 * BMC, tid);
    if (tid < 16)
        cp_async16(sbase + OFF_Y2 + tid * 16, (const char*)(g_y2h + tile0 * BMC) + tid * 16);
    CP_COMMIT();
    CP_WAIT0();
    __syncthreads();

    float bestV[8];
    #pragma unroll
    for (int i = 0; i < 8; i++) bestV[i] = -FLT_MAX;

    for (int t = tile0; t < tile1; t++) {
        const int buf = (t - tile0) & 1;

        if (t + 1 < tile1) {
            const int nb = buf ^ 1;
            load_tileB_async(B[nb], g_mbh, (t + 1) * BMC, tid);
            if (tid < 16)
                cp_async16(sbase + OFF_Y2 + (uint32_t)(nb * 256 + tid * 16),
                           (const char*)(g_y2h + (size_t)(t + 1) * BMC) + tid * 16);
            CP_COMMIT();
        }

        float acc[4][4][4];
        #pragma unroll
        for (int mf = 0; mf < 4; mf++)
            #pragma unroll
            for (int nf = 0; nf < 4; nf++)
                #pragma unroll
                for (int r = 0; r < 4; r++) acc[mf][nf][r] = 0.0f;

        const uint32_t aB = A + aOff;
        const uint32_t bB = B[buf] + bOff;
        #pragma unroll
        for (int kc = 0; kc < 8; kc++) {
            const uint32_t kByte = (uint32_t)(kc << 5);
            uint32_t af[4][4];
            #pragma unroll
            for (int mf = 0; mf < 4; mf++)
                ldm_x4(aB + (uint32_t)(mf * 16 * LDTB) + kByte,
                       af[mf][0], af[mf][1], af[mf][2], af[mf][3]);
            uint32_t bf[4][2];
            #pragma unroll
            for (int q = 0; q < 2; q++) {
                uint32_t r0, r1, r2, r3;
                ldm_x4(bB + (uint32_t)(q * 16 * LDTB) + kByte, r0, r1, r2, r3);
                bf[q * 2][0] = r0; bf[q * 2][1] = r1;
                bf[q * 2 + 1][0] = r2; bf[q * 2 + 1][1] = r3;
            }
            #pragma unroll
            for (int mf = 0; mf < 4; mf++)
                #pragma unroll
                for (int nf = 0; nf < 4; nf++)
                    mma16816(acc[mf][nf], af[mf], bf[nf]);
        }

        // ---- epilogue: s = dot - 0.5*y2, running max (value only) ----
        {
            const float2* hy2 = reinterpret_cast<const float2*>(y2s + buf * 64);
            float2 hv[4];
            #pragma unroll
            for (int nf = 0; nf < 4; nf++)
                hv[nf] = hy2[(wn * 32 + nf * 8 + (lane & 3) * 2) >> 1];
            #pragma unroll
            for (int mf = 0; mf < 4; mf++) {
                #pragma unroll
                for (int h = 0; h < 2; h++) {
                    const int slot = mf * 2 + h;
                    float bv = bestV[slot];
                    #pragma unroll
                    for (int nf = 0; nf < 4; nf++) {
                        float s0 = acc[mf][nf][h * 2] - hv[nf].x;
                        float s1 = acc[mf][nf][h * 2 + 1] - hv[nf].y;
                        bv = fmaxf(bv, fmaxf(s0, s1));
                    }
                    bestV[slot] = bv;
                }
            }
        }

        if (t + 1 < tile1) CP_WAIT0();
        __syncthreads();
    }

    float* redV = reinterpret_cast<float*>(smem + OFF_RED);
    #pragma unroll
    for (int slot = 0; slot < 8; slot++) {
        float v = bestV[slot];
        v = fmaxf(v, __shfl_xor_sync(0xFFFFFFFF, v, 1));
        v = fmaxf(v, __shfl_xor_sync(0xFFFFFFFF, v, 2));
        if ((lane & 3) == 0) {
            int mf = slot >> 1, h = slot & 1;
            int row = wm * 64 + mf * 16 + (lane >> 2) + h * 8;
            redV[row * 2 + wn] = v;
        }
    }
    __syncthreads();
    if (tid < BNR) {
        float bv = fmaxf(redV[tid * 2], redV[tid * 2 + 1]);
        g_pval[blockIdx.y * NROWS + rowBase + tid] = bv;
    }
}

// ---------------- fused: patch scores + per-image argmax (+init nnkey) ----------------
__global__ void k_score() {
    int b = blockIdx.x, tid = threadIdx.x;
    __shared__ float sv[256]; __shared__ int si[256];
    if (tid == 0) g_nnkey[b] = 0xFFFFFFFFFFFFFFFFull;
    float bmax = -FLT_MAX; int bi = INT_MAX;
    for (int p = tid; p < PPB; p += 256) {
        int row = b * PPB + p;
        float bv = -FLT_MAX;
        #pragma unroll
        for (int s = 0; s < NSPLIT; s++) bv = fmaxf(bv, g_pval[s * NROWS + row]);
        float d2 = g_x2[row] - 2.0f * bv;
        float sc = sqrtf(fmaxf(d2, 0.0f));
        g_pscore[row] = sc;
        if (sc > bmax || (sc == bmax && p < bi)) { bmax = sc; bi = p; }
    }
    sv[tid] = bmax; si[tid] = bi;
    __syncthreads();
    for (int s = 128; s > 0; s >>= 1) {
        if (tid < s) {
            if (sv[tid + s] > sv[tid] || (sv[tid + s] == sv[tid] && si[tid + s] < si[tid])) {
                sv[tid] = sv[tid + s]; si[tid] = si[tid + s];
            }
        }
        __syncthreads();
    }
    if (tid == 0) g_qrow[b] = b * PPB + si[0];
}

// ---------------- exact fp32 argmin over mb, atomic-merged ----------------
// grid (128, 8), block 256 = 8 warps x 32 rows
__global__ void k_qpart(const float* __restrict__ emb, const float* __restrict__ mb) {
    int b = blockIdx.y;
    int warp = threadIdx.x >> 5, lane = threadIdx.x & 31;
    float4 q = reinterpret_cast<const float4*>(emb + (size_t)g_qrow[b] * DDIM)[lane];
    float bv = FLT_MAX; int bi = INT_MAX;
    int base = blockIdx.x * 256 + warp * 32;
    for (int i = 0; i < 32; i++) {
        int row = base + i;
        float4 m = reinterpret_cast<const float4*>(mb + (size_t)row * DDIM)[lane];
        float dot = q.x * m.x + q.y * m.y + q.z * m.z + q.w * m.w;
        #pragma unroll
        for (int o = 16; o > 0; o >>= 1) dot += __shfl_xor_sync(0xFFFFFFFF, dot, o);
        float d2 = g_y2[row] - 2.0f * dot;   // +q^2 constant: argmin-invariant
        if (d2 < bv) { bv = d2; bi = row; }
    }
    __shared__ float sv[8]; __shared__ int si[8];
    if (lane == 0) { sv[warp] = bv; si[warp] = bi; }
    __syncthreads();
    if (threadIdx.x == 0) {
        float v = sv[0]; int ix = si[0];
        for (int w = 1; w < 8; w++)
            if (sv[w] < v || (sv[w] == v && si[w] < ix)) { v = sv[w]; ix = si[w]; }
        unsigned long long key = ((unsigned long long)f2ord(v) << 32) | (unsigned)ix;
        atomicMin(&g_nnkey[b], key);
    }
}

// ---------------- dnn distances + per-warp top-9 partials (per-image) ----------------
__global__ void k_dnn9(const float* __restrict__ mb) {
    int b = blockIdx.y;
    int warp = threadIdx.x >> 5, lane = threadIdx.x & 31;
    int nn = (int)(g_nnkey[b] & 0xFFFFFFFFull);
    float4 q = reinterpret_cast<const float4*>(mb + (size_t)nn * DDIM)[lane];
    float y2q = g_y2[nn];

    float tv[KNEIGH]; int ti9[KNEIGH];
    #pragma unroll
    for (int j = 0; j < KNEIGH; j++) { tv[j] = FLT_MAX; ti9[j] = INT_MAX; }

    int base = blockIdx.x * 256 + warp * 32;
    for (int i = 0; i < 32; i++) {
        int row = base + i;
        float4 m = reinterpret_cast<const float4*>(mb + (size_t)row * DDIM)[lane];
        float dot = q.x * m.x + q.y * m.y + q.z * m.z + q.w * m.w;
        #pragma unroll
        for (int o = 16; o > 0; o >>= 1) dot += __shfl_xor_sync(0xFFFFFFFF, dot, o);
        if (lane == 0) {
            float v = sqrtf(fmaxf(y2q - 2.0f * dot + g_y2[row], 0.0f));
            if (v < tv[KNEIGH - 1]) {
                int pos = KNEIGH - 1;
                while (pos > 0 && v < tv[pos - 1]) {
                    tv[pos] = tv[pos - 1]; ti9[pos] = ti9[pos - 1]; pos--;
                }
                tv[pos] = v; ti9[pos] = row;
            }
        }
    }
    if (lane == 0) {
        int off = b * NDNN + (blockIdx.x * 8 + warp) * KNEIGH;
        #pragma unroll
        for (int j = 0; j < KNEIGH; j++) { g_d9v[off + j] = tv[j]; g_d9i[off + j] = ti9[j]; }
    }
}

// ---------------- merge partials -> top-9 -> softmax reweight -> pred_score ----------------
__global__ void k_final(const float* __restrict__ emb, const float* __restrict__ mb,
                        float* __restrict__ out) {
    int b = blockIdx.x, tid = threadIdx.x;
    __shared__ float hv[256];
    __shared__ int hidx[256];
    __shared__ int hthr[256];
    __shared__ int sel[KNEIGH];
    __shared__ float dists[KNEIGH];

    float tv[KNEIGH]; int ti9[KNEIGH];
    #pragma unroll
    for (int j = 0; j < KNEIGH; j++) { tv[j] = FLT_MAX; ti9[j] = INT_MAX; }
    for (int m = tid; m < NDNN; m += 256) {
        float v = g_d9v[b * NDNN + m];
        int ix = g_d9i[b * NDNN + m];
        if (v < tv[KNEIGH - 1] || (v == tv[KNEIGH - 1] && ix < ti9[KNEIGH - 1])) {
            int pos = KNEIGH - 1;
            while (pos > 0 && (v < tv[pos - 1] || (v == tv[pos - 1] && ix < ti9[pos - 1]))) {
                tv[pos] = tv[pos - 1]; ti9[pos] = ti9[pos - 1]; pos--;
            }
            tv[pos] = v; ti9[pos] = ix;
        }
    }

    int cur = 0;
    for (int it = 0; it < KNEIGH; it++) {
        hv[tid] = (cur < KNEIGH) ? tv[cur] : FLT_MAX;
        hidx[tid] = (cur < KNEIGH) ? ti9[cur] : INT_MAX;
        hthr[tid] = tid;
        __syncthreads();
        for (int s = 128; s > 0; s >>= 1) {
            if (tid < s) {
                if (hv[tid + s] < hv[tid] ||
                    (hv[tid + s] == hv[tid] && hidx[tid + s] < hidx[tid])) {
                    hv[tid] = hv[tid + s]; hidx[tid] = hidx[tid + s]; hthr[tid] = hthr[tid + s];
                }
            }
            __syncthreads();
        }
        if (tid == 0) sel[it] = hidx[0];
        int win = hthr[0];
        __syncthreads();
        if (tid == win) cur++;
    }

    if (tid < KNEIGH) {
        const float* q = emb + (size_t)g_qrow[b] * DDIM;
        const float* m = mb + (size_t)sel[tid] * DDIM;
        float dot = 0.0f, q2 = 0.0f;
        #pragma unroll 4
        for (int d = 0; d < DDIM; d++) { dot += q[d] * m[d]; q2 += q[d] * q[d]; }
        float d2 = q2 - 2.0f * dot + g_y2[sel[tid]];
        dists[tid] = sqrtf(fmaxf(d2, 0.0f));
    }
    __syncthreads();
    if (tid == 0) {
        float mx = dists[0];
        for (int j = 1; j < KNEIGH; j++) mx = fmaxf(mx, dists[j]);
        float sum = 0.0f, e0 = 0.0f;
        for (int j = 0; j < KNEIGH; j++) {
            float e = expf(dists[j] - mx);
            if (j == 0) e0 = e;
            sum += e;
        }
        float d2m = ord2f((uint32_t)(g_nnkey[b] >> 32));
        float score = sqrtf(fmaxf(g_x2[g_qrow[b]] + d2m, 0.0f));
        out[b] = (1.0f - e0 / sum) * score;
    }
}

// ---------------- fused upsample + separable Gaussian blur ----------------
__global__ void k_map(float* __restrict__ out) {
    char* smem = s_raw;
    float* pm = reinterpret_cast<float*>(smem + MAP_PM);
    float* gs = reinterpret_cast<float*>(smem + MAP_GS);
    float* up = reinterpret_cast<float*>(smem + MAP_UP);   // [48][224]
    float* vt = reinterpret_cast<float*>(smem + MAP_VT);   // [16][224]
    const int band = blockIdx.x, b = blockIdx.y;
    const int tid = threadIdx.x;
    const int r0 = band * 16;

    for (int i = tid; i < PPB; i += 256) pm[i] = g_pscore[b * PPB + i];
    if (tid < KSIZE) gs[tid] = g_gauss[tid];
    __syncthreads();

    for (int i = tid; i < 48 * 224; i += 256) {
        int j = i / 224, V = i % 224;
        int U = r0 - 16 + j;
        if (U < 0) U = -U;
        if (U > OUTSZ - 1) U = 2 * (OUTSZ - 1) - U;
        float su = ((float)U + 0.5f) * 0.125f - 0.5f;
        float sv = ((float)V + 0.5f) * 0.125f - 0.5f;
        int u0 = (int)floorf(su), v0 = (int)floorf(sv);
        float tu = su - (float)u0, tvv = sv - (float)v0;
        int u0c = min(max(u0, 0), WIO - 1), u1c = min(max(u0 + 1, 0), WIO - 1);
        int v0c = min(max(v0, 0), WIO - 1), v1c = min(max(v0 + 1, 0), WIO - 1);
        float v00 = pm[u0c * WIO + v0c], v01 = pm[u0c * WIO + v1c];
        float v10 = pm[u1c * WIO + v0c], v11 = pm[u1c * WIO + v1c];
        float top = v00 + tvv * (v01 - v00);
        float bot = v10 + tvv * (v11 - v10);
        up[i] = top + tu * (bot - top);
    }
    __syncthreads();

    for (int i = tid; i < 16 * 224; i += 256) {
        int du = i / 224, V = i % 224;
        float acc = 0.0f;
        #pragma unroll
        for (int k = 0; k < KSIZE; k++) acc += gs[k] * up[(du + k) * 224 + V];
        vt[i] = acc;
    }
    __syncthreads();

    for (int i = tid; i < 16 * 224; i += 256) {
        int du = i / 224, V = i % 224;
        float acc = 0.0f;
        #pragma unroll
        for (int k = 0; k < KSIZE; k++) {
            int jv = V - KRAD + k;
            if (jv < 0) jv = -jv;
            if (jv > OUTSZ - 1) jv = 2 * (OUTSZ - 1) - jv;
            acc += gs[k] * vt[du * 224 + jv];
        }
        out[BATCH + (b * OUTSZ + r0 + du) * OUTSZ + V] = acc;
    }
}

// ---------------- launcher ----------------
extern "C" void kernel_launch(void* const* d_in, const int* in_sizes, int n_in,
                              void* d_out, int out_size) {
    const float* emb = (const float*)d_in[0];
    const float* mb = (const float*)d_in[1];
    float* out = (float*)d_out;

    static bool attr_set = false;
    if (!attr_set) {
        cudaFuncSetAttribute(k_dist_mma, cudaFuncAttributeMaxDynamicSharedMemorySize, SMEM_TOTAL);
        cudaFuncSetAttribute(k_map, cudaFuncAttributeMaxDynamicSharedMemorySize, MAP_SMEM);
        attr_set = true;
    }

    k_prep<<<(MROWS + NROWS) / 8, 256>>>(emb, mb);

    dim3 gdist(NROWS / BNR, NSPLIT);
    k_dist_mma<<<gdist, 128, SMEM_TOTAL>>>();

    k_score<<<BATCH, 256>>>();

    dim3 gq(128, BATCH);
    k_qpart<<<gq, 256>>>(emb, mb);

    dim3 gd9(128, BATCH);
    k_dnn9<<<gd9, 256>>>(mb);

    k_final<<<BATCH, 256>>>(emb, mb, out);

    dim3 gmap(14, BATCH);
    k_map<<<gmap, 256, MAP_SMEM>>>(out);
}

// round 13
// speedup vs baseline: 7.9752x; 1.0260x over previous
#include <cuda_runtime.h>
#include <cuda_bf16.h>
#include <math.h>
#include <float.h>
#include <limits.h>
#include <stdint.h>

// ---------------- problem constants (fixed shapes) ----------------
#define NROWS 6272      // embedding rows
#define MROWS 32768     // memory bank rows
#define DDIM  128
#define BATCH 8
#define PPB   784
#define WIO   28
#define OUTSZ 224
#define KNEIGH 9
#define KSIZE 33
#define KRAD  16

#define NSPLIT 9
#define BNR 128                 // emb rows per CTA
#define BMC 64                  // mb cols per tile step
#define NTILES (MROWS / BMC)    // 512
#define LDTB 272                // smem tile row stride bytes (136 bf16)
#define TILE_A (128 * LDTB)     // 34816
#define TILE_B (64 * LDTB)      // 17408

// k_dist smem byte offsets
#define OFF_A     0
#define OFF_B0    (OFF_A + TILE_A)
#define OFF_B1    (OFF_B0 + TILE_B)
#define OFF_Y2    (OFF_B1 + TILE_B)            // 2 x 64 floats (halved y2)
#define OFF_RED   (OFF_Y2 + 512)               // 128*2 floats
#define SMEM_TOTAL (OFF_RED + 1024)            // 71680 bytes -> 3 CTAs/SM

// k_map smem layout
#define MAP_PM    0
#define MAP_GS    3136
#define MAP_UP    3280
#define MAP_VT    (MAP_UP + 48*224*4)
#define MAP_SMEM  (MAP_VT + 16*224*4)          // 60624 bytes

#define NDNN 9216                              // per-image dnn top9 partials (128 blk * 8 warps * 9)

// ---------------- device scratch ----------------
__device__ float g_y2[MROWS];
__device__ float g_y2h[MROWS];
__device__ float g_x2[NROWS];
__device__ float g_pval[NSPLIT * NROWS];
__device__ float g_pscore[NROWS];
__device__ int   g_qrow[BATCH];
__device__ unsigned long long g_nnkey[BATCH]; // packed (ordered d2-q2 | idx)
__device__ int   g_done[BATCH];
__device__ float g_d9v[BATCH * NDNN];         // d^2 partials
__device__ int   g_d9i[BATCH * NDNN];
__device__ float g_gauss[KSIZE];
__device__ __nv_bfloat16 g_embh[NROWS * DDIM];
__device__ __nv_bfloat16 g_mbh[MROWS * DDIM];

// ---------------- small helpers ----------------
__device__ __forceinline__ uint32_t smem_u32(const void* p) {
    uint32_t a;
    asm("{ .reg .u64 t; cvta.to.shared.u64 t, %1; cvt.u32.u64 %0, t; }" : "=r"(a) : "l"(p));
    return a;
}
__device__ __forceinline__ void cp_async16(uint32_t dst, const void* src) {
    asm volatile("cp.async.cg.shared.global [%0], [%1], 16;" :: "r"(dst), "l"(src));
}
#define CP_COMMIT() asm volatile("cp.async.commit_group;" ::: "memory")
#define CP_WAIT0()  asm volatile("cp.async.wait_group 0;" ::: "memory")

__device__ __forceinline__ void ldm_x4(uint32_t addr, uint32_t& r0, uint32_t& r1,
                                       uint32_t& r2, uint32_t& r3) {
    asm volatile("ldmatrix.sync.aligned.m8n8.x4.shared.b16 {%0,%1,%2,%3}, [%4];"
                 : "=r"(r0), "=r"(r1), "=r"(r2), "=r"(r3) : "r"(addr));
}
__device__ __forceinline__ void mma16816(float* c, const uint32_t* a, const uint32_t* b) {
    asm volatile("mma.sync.aligned.m16n8k16.row.col.f32.bf16.bf16.f32 "
                 "{%0,%1,%2,%3}, {%4,%5,%6,%7}, {%8,%9}, {%0,%1,%2,%3};"
                 : "+f"(c[0]), "+f"(c[1]), "+f"(c[2]), "+f"(c[3])
                 : "r"(a[0]), "r"(a[1]), "r"(a[2]), "r"(a[3]), "r"(b[0]), "r"(b[1]));
}
__device__ __forceinline__ uint32_t f2ord(float f) {
    uint32_t u = __float_as_uint(f);
    return (u & 0x80000000u) ? ~u : (u | 0x80000000u);
}
__device__ __forceinline__ float ord2f(uint32_t u) {
    uint32_t b = (u & 0x80000000u) ? (u & 0x7FFFFFFFu) : ~u;
    return __uint_as_float(b);
}

// ---------------- k_prep: gauss + y2 + x2 + bf16 split ----------------
// block = 256 (8 warps), each warp handles 4 rows; blocks 0..1023 -> mb, rest -> emb
__global__ void k_prep(const float* __restrict__ emb, const float* __restrict__ mb) {
    if (blockIdx.x == 0 && threadIdx.x == 0) {
        float tmp[KSIZE]; float s = 0.0f;
        for (int i = 0; i < KSIZE; i++) {
            float x = (float)i - (float)(KSIZE - 1) * 0.5f;
            float t = x / 4.0f;
            tmp[i] = expf(-0.5f * t * t); s += tmp[i];
        }
        for (int i = 0; i < KSIZE; i++) g_gauss[i] = tmp[i] / s;
    }
    const int warp = threadIdx.x >> 5, lane = threadIdx.x & 31;
    const int r = lane >> 3, c = lane & 7;
    const int grow = blockIdx.x * 32 + warp * 4 + r;   // global row (mb then emb)
    const float4* src4;
    uint2* dst2;
    int row;
    bool is_mb = (grow < MROWS);
    if (is_mb) { src4 = reinterpret_cast<const float4*>(mb); dst2 = reinterpret_cast<uint2*>(g_mbh); row = grow; }
    else       { src4 = reinterpret_cast<const float4*>(emb); dst2 = reinterpret_cast<uint2*>(g_embh); row = grow - MROWS; }

    float s = 0.0f;
    #pragma unroll
    for (int k = 0; k < 4; k++) {
        int idx = row * 32 + k * 8 + c;
        float4 v = src4[idx];
        s += v.x * v.x + v.y * v.y + v.z * v.z + v.w * v.w;
        __nv_bfloat162 h0, h1;
        h0.x = __float2bfloat16_rn(v.x); h0.y = __float2bfloat16_rn(v.y);
        h1.x = __float2bfloat16_rn(v.z); h1.y = __float2bfloat16_rn(v.w);
        uint2 p;
        p.x = *reinterpret_cast<uint32_t*>(&h0);
        p.y = *reinterpret_cast<uint32_t*>(&h1);
        dst2[idx] = p;
    }
    #pragma unroll
    for (int o = 1; o <= 4; o <<= 1) s += __shfl_xor_sync(0xFFFFFFFF, s, o);
    if (c == 0) {
        if (is_mb) { g_y2[row] = s; g_y2h[row] = 0.5f * s; }
        else       { g_x2[row] = s; }
    }
}

// ---------------- mma.sync fused distance GEMM (K=128, bf16-hi) + max ----------------
extern __shared__ char s_raw[];

__device__ __forceinline__ void load_tileA_async(uint32_t sm_dst,
                                                 const __nv_bfloat16* __restrict__ src,
                                                 int row0, int tid) {
    #pragma unroll
    for (int k = 0; k < 16; k++) {
        int i = k * 128 + tid;
        int r = i >> 4, c = i & 15;
        cp_async16(sm_dst + (uint32_t)(r * LDTB + c * 16),
                   (const char*)(src + (size_t)(row0 + r) * DDIM) + c * 16);
    }
}
__device__ __forceinline__ void load_tileB_async(uint32_t sm_dst,
                                                 const __nv_bfloat16* __restrict__ src,
                                                 int row0, int tid) {
    #pragma unroll
    for (int k = 0; k < 8; k++) {
        int i = k * 128 + tid;
        int r = i >> 4, c = i & 15;
        cp_async16(sm_dst + (uint32_t)(r * LDTB + c * 16),
                   (const char*)(src + (size_t)(row0 + r) * DDIM) + c * 16);
    }
}

__global__ void __launch_bounds__(128, 3) k_dist_mma() {
    char* smem = s_raw;
    const uint32_t sbase = smem_u32(smem);
    const int tid = threadIdx.x;
    const int wid = tid >> 5;
    const int lane = tid & 31;
    const int wm = wid & 1;
    const int wn = wid >> 1;
    const int rowBase = blockIdx.x * BNR;

    const int tile0 = (blockIdx.y * NTILES) / NSPLIT;
    const int tile1 = ((blockIdx.y + 1) * NTILES) / NSPLIT;

    const uint32_t A = sbase + OFF_A;
    const uint32_t B[2] = { sbase + OFF_B0, sbase + OFF_B1 };
    float* y2s = reinterpret_cast<float*>(smem + OFF_Y2);

    const int a_row = lane & 15;
    const int a_koff = (lane >> 4) << 3;
    const uint32_t aOff = (uint32_t)((wm * 64 + a_row) * LDTB + a_koff * 2);
    const int b_n = (lane & 7) + ((lane >> 4) << 3);
    const int b_koff = ((lane >> 3) & 1) << 3;
    const uint32_t bOff = (uint32_t)((wn * 32 + b_n) * LDTB + b_koff * 2);

    load_tileA_async(A, g_embh, rowBase, tid);
    load_tileB_async(B[0], g_mbh, tile0 * BMC, tid);
    if (tid < 16)
        cp_async16(sbase + OFF_Y2 + tid * 16, (const char*)(g_y2h + tile0 * BMC) + tid * 16);
    CP_COMMIT();
    CP_WAIT0();
    __syncthreads();

    float bestV[8];
    #pragma unroll
    for (int i = 0; i < 8; i++) bestV[i] = -FLT_MAX;

    for (int t = tile0; t < tile1; t++) {
        const int buf = (t - tile0) & 1;

        if (t + 1 < tile1) {
            const int nb = buf ^ 1;
            load_tileB_async(B[nb], g_mbh, (t + 1) * BMC, tid);
            if (tid < 16)
                cp_async16(sbase + OFF_Y2 + (uint32_t)(nb * 256 + tid * 16),
                           (const char*)(g_y2h + (size_t)(t + 1) * BMC) + tid * 16);
            CP_COMMIT();
        }

        float acc[4][4][4];
        #pragma unroll
        for (int mf = 0; mf < 4; mf++)
            #pragma unroll
            for (int nf = 0; nf < 4; nf++)
                #pragma unroll
                for (int r = 0; r < 4; r++) acc[mf][nf][r] = 0.0f;

        const uint32_t aB = A + aOff;
        const uint32_t bB = B[buf] + bOff;
        #pragma unroll
        for (int kc = 0; kc < 8; kc++) {
            const uint32_t kByte = (uint32_t)(kc << 5);
            uint32_t af[4][4];
            #pragma unroll
            for (int mf = 0; mf < 4; mf++)
                ldm_x4(aB + (uint32_t)(mf * 16 * LDTB) + kByte,
                       af[mf][0], af[mf][1], af[mf][2], af[mf][3]);
            uint32_t bf[4][2];
            #pragma unroll
            for (int q = 0; q < 2; q++) {
                uint32_t r0, r1, r2, r3;
                ldm_x4(bB + (uint32_t)(q * 16 * LDTB) + kByte, r0, r1, r2, r3);
                bf[q * 2][0] = r0; bf[q * 2][1] = r1;
                bf[q * 2 + 1][0] = r2; bf[q * 2 + 1][1] = r3;
            }
            #pragma unroll
            for (int mf = 0; mf < 4; mf++)
                #pragma unroll
                for (int nf = 0; nf < 4; nf++)
                    mma16816(acc[mf][nf], af[mf], bf[nf]);
        }

        {
            const float2* hy2 = reinterpret_cast<const float2*>(y2s + buf * 64);
            float2 hv[4];
            #pragma unroll
            for (int nf = 0; nf < 4; nf++)
                hv[nf] = hy2[(wn * 32 + nf * 8 + (lane & 3) * 2) >> 1];
            #pragma unroll
            for (int mf = 0; mf < 4; mf++) {
                #pragma unroll
                for (int h = 0; h < 2; h++) {
                    const int slot = mf * 2 + h;
                    float bv = bestV[slot];
                    #pragma unroll
                    for (int nf = 0; nf < 4; nf++) {
                        float s0 = acc[mf][nf][h * 2] - hv[nf].x;
                        float s1 = acc[mf][nf][h * 2 + 1] - hv[nf].y;
                        bv = fmaxf(bv, fmaxf(s0, s1));
                    }
                    bestV[slot] = bv;
                }
            }
        }

        if (t + 1 < tile1) CP_WAIT0();
        __syncthreads();
    }

    float* redV = reinterpret_cast<float*>(smem + OFF_RED);
    #pragma unroll
    for (int slot = 0; slot < 8; slot++) {
        float v = bestV[slot];
        v = fmaxf(v, __shfl_xor_sync(0xFFFFFFFF, v, 1));
        v = fmaxf(v, __shfl_xor_sync(0xFFFFFFFF, v, 2));
        if ((lane & 3) == 0) {
            int mf = slot >> 1, h = slot & 1;
            int row = wm * 64 + mf * 16 + (lane >> 2) + h * 8;
            redV[row * 2 + wn] = v;
        }
    }
    __syncthreads();
    if (tid < BNR) {
        float bv = fmaxf(redV[tid * 2], redV[tid * 2 + 1]);
        g_pval[blockIdx.y * NROWS + rowBase + tid] = bv;
    }
}

// ---------------- fused: patch scores + per-image argmax (+reset keys) ----------------
__global__ void k_score() {
    int b = blockIdx.x, tid = threadIdx.x;
    __shared__ float sv[256]; __shared__ int si[256];
    if (tid == 0) { g_nnkey[b] = 0xFFFFFFFFFFFFFFFFull; g_done[b] = 0; }
    float bmax = -FLT_MAX; int bi = INT_MAX;
    for (int p = tid; p < PPB; p += 256) {
        int row = b * PPB + p;
        float bv = -FLT_MAX;
        #pragma unroll
        for (int s = 0; s < NSPLIT; s++) bv = fmaxf(bv, g_pval[s * NROWS + row]);
        float d2 = g_x2[row] - 2.0f * bv;
        float sc = sqrtf(fmaxf(d2, 0.0f));
        g_pscore[row] = sc;
        if (sc > bmax || (sc == bmax && p < bi)) { bmax = sc; bi = p; }
    }
    sv[tid] = bmax; si[tid] = bi;
    __syncthreads();
    for (int s = 128; s > 0; s >>= 1) {
        if (tid < s) {
            if (sv[tid + s] > sv[tid] || (sv[tid + s] == sv[tid] && si[tid + s] < si[tid])) {
                sv[tid] = sv[tid + s]; si[tid] = si[tid + s];
            }
        }
        __syncthreads();
    }
    if (tid == 0) g_qrow[b] = b * PPB + si[0];
}

// ---------------- exact fp32 argmin over mb, 4-rows-per-warp, atomic-merged ----------------
// grid (128, 8), block 256 = 8 warps x 32 rows
__global__ void k_qpart(const float* __restrict__ emb, const float* __restrict__ mb) {
    const int b = blockIdx.y;
    const int warp = threadIdx.x >> 5, lane = threadIdx.x & 31;
    const int r = lane >> 3, c = lane & 7;
    const float4* mb4 = reinterpret_cast<const float4*>(mb);
    const float4* q4p = reinterpret_cast<const float4*>(emb + (size_t)g_qrow[b] * DDIM);

    float4 q4[4];
    #pragma unroll
    for (int k = 0; k < 4; k++) q4[k] = q4p[k * 8 + c];

    float bv = FLT_MAX; int bi = INT_MAX;
    const int base = blockIdx.x * 256 + warp * 32;
    #pragma unroll
    for (int g = 0; g < 8; g++) {
        int row = base + g * 4 + r;
        float dot = 0.0f;
        #pragma unroll
        for (int k = 0; k < 4; k++) {
            float4 m = mb4[row * 32 + k * 8 + c];
            dot += q4[k].x * m.x + q4[k].y * m.y + q4[k].z * m.z + q4[k].w * m.w;
        }
        #pragma unroll
        for (int o = 1; o <= 4; o <<= 1) dot += __shfl_xor_sync(0xFFFFFFFF, dot, o);
        float d2 = g_y2[row] - 2.0f * dot;      // +q^2 constant: argmin-invariant
        if (d2 < bv) { bv = d2; bi = row; }     // rows ascending in sequence
    }
    // cross-group merge (r bits are lane bits 3,4)
    #pragma unroll
    for (int o = 8; o <= 16; o <<= 1) {
        float ov = __shfl_xor_sync(0xFFFFFFFF, bv, o);
        int oi = __shfl_xor_sync(0xFFFFFFFF, bi, o);
        if (ov < bv || (ov == bv && oi < bi)) { bv = ov; bi = oi; }
    }
    __shared__ float sv[8]; __shared__ int si[8];
    if (lane == 0) { sv[warp] = bv; si[warp] = bi; }
    __syncthreads();
    if (threadIdx.x == 0) {
        float v = sv[0]; int ix = si[0];
        for (int w = 1; w < 8; w++)
            if (sv[w] < v || (sv[w] == v && si[w] < ix)) { v = sv[w]; ix = si[w]; }
        unsigned long long key = ((unsigned long long)f2ord(v) << 32) | (unsigned)ix;
        atomicMin(&g_nnkey[b], key);
    }
}

// ---------------- dnn d^2 top-9 partials + last-block final merge ----------------
// grid (128, 8), block 256 = 8 warps x 32 rows
__global__ void k_dnn9(const float* __restrict__ emb, const float* __restrict__ mb,
                       float* __restrict__ out) {
    const int b = blockIdx.y;
    const int warp = threadIdx.x >> 5, lane = threadIdx.x & 31;
    const int r = lane >> 3, c = lane & 7;
    const int nn = (int)(g_nnkey[b] & 0xFFFFFFFFull);
    const float4* mb4 = reinterpret_cast<const float4*>(mb);
    const float4* q4p = reinterpret_cast<const float4*>(mb + (size_t)nn * DDIM);
    const float y2q = g_y2[nn];

    float4 q4[4];
    #pragma unroll
    for (int k = 0; k < 4; k++) q4[k] = q4p[k * 8 + c];

    float tv[KNEIGH]; int ti9[KNEIGH];
    #pragma unroll
    for (int j = 0; j < KNEIGH; j++) { tv[j] = FLT_MAX; ti9[j] = INT_MAX; }

    const int base = blockIdx.x * 256 + warp * 32;
    #pragma unroll
    for (int g = 0; g < 8; g++) {
        int row = base + g * 4 + r;
        float dot = 0.0f;
        #pragma unroll
        for (int k = 0; k < 4; k++) {
            float4 m = mb4[row * 32 + k * 8 + c];
            dot += q4[k].x * m.x + q4[k].y * m.y + q4[k].z * m.z + q4[k].w * m.w;
        }
        #pragma unroll
        for (int o = 1; o <= 4; o <<= 1) dot += __shfl_xor_sync(0xFFFFFFFF, dot, o);
        float d2 = y2q - 2.0f * dot + g_y2[row];
        // lane0 gathers the 4 group results and inserts (rows ascending)
        #pragma unroll
        for (int rr = 0; rr < 4; rr++) {
            float v = __shfl_sync(0xFFFFFFFF, d2, rr * 8);
            if (lane == 0) {
                int row2 = base + g * 4 + rr;
                if (v < tv[KNEIGH - 1] || (v == tv[KNEIGH - 1] && row2 < ti9[KNEIGH - 1])) {
                    int pos = KNEIGH - 1;
                    while (pos > 0 && (v < tv[pos - 1] || (v == tv[pos - 1] && row2 < ti9[pos - 1]))) {
                        tv[pos] = tv[pos - 1]; ti9[pos] = ti9[pos - 1]; pos--;
                    }
                    tv[pos] = v; ti9[pos] = row2;
                }
            }
        }
    }
    if (lane == 0) {
        int off = b * NDNN + (blockIdx.x * 8 + warp) * KNEIGH;
        #pragma unroll
        for (int j = 0; j < KNEIGH; j++) { g_d9v[off + j] = tv[j]; g_d9i[off + j] = ti9[j]; }
    }
    __syncthreads();

    // ---- last block for image b does the final merge + softmax + out[b] ----
    __shared__ int s_last;
    if (threadIdx.x == 0) {
        __threadfence();
        s_last = atomicAdd(&g_done[b], 1);
    }
    __syncthreads();
    if (s_last != gridDim.x - 1) return;

    const int tid = threadIdx.x;
    __shared__ float hv[256]; __shared__ int hidx[256]; __shared__ int hthr[256];
    __shared__ int sel[KNEIGH]; __shared__ float dists[KNEIGH];

    float mv[KNEIGH]; int mi[KNEIGH];
    #pragma unroll
    for (int j = 0; j < KNEIGH; j++) { mv[j] = FLT_MAX; mi[j] = INT_MAX; }
    for (int m = tid; m < NDNN; m += 256) {
        float v = g_d9v[b * NDNN + m];
        int ix = g_d9i[b * NDNN + m];
        if (v < mv[KNEIGH - 1] || (v == mv[KNEIGH - 1] && ix < mi[KNEIGH - 1])) {
            int pos = KNEIGH - 1;
            while (pos > 0 && (v < mv[pos - 1] || (v == mv[pos - 1] && ix < mi[pos - 1]))) {
                mv[pos] = mv[pos - 1]; mi[pos] = mi[pos - 1]; pos--;
            }
            mv[pos] = v; mi[pos] = ix;
        }
    }
    int cur = 0;
    for (int it = 0; it < KNEIGH; it++) {
        hv[tid] = (cur < KNEIGH) ? mv[cur] : FLT_MAX;
        hidx[tid] = (cur < KNEIGH) ? mi[cur] : INT_MAX;
        hthr[tid] = tid;
        __syncthreads();
        for (int s = 128; s > 0; s >>= 1) {
            if (tid < s) {
                if (hv[tid + s] < hv[tid] ||
                    (hv[tid + s] == hv[tid] && hidx[tid + s] < hidx[tid])) {
                    hv[tid] = hv[tid + s]; hidx[tid] = hidx[tid + s]; hthr[tid] = hthr[tid + s];
                }
            }
            __syncthreads();
        }
        if (tid == 0) sel[it] = hidx[0];
        int win = hthr[0];
        __syncthreads();
        if (tid == win) cur++;
    }

    if (tid < KNEIGH) {
        const float* q = emb + (size_t)g_qrow[b] * DDIM;
        const float* m = mb + (size_t)sel[tid] * DDIM;
        float dot = 0.0f, q2 = 0.0f;
        #pragma unroll 4
        for (int d = 0; d < DDIM; d++) { dot += q[d] * m[d]; q2 += q[d] * q[d]; }
        float d2 = q2 - 2.0f * dot + g_y2[sel[tid]];
        dists[tid] = sqrtf(fmaxf(d2, 0.0f));
    }
    __syncthreads();
    if (tid == 0) {
        float mx = dists[0];
        for (int j = 1; j < KNEIGH; j++) mx = fmaxf(mx, dists[j]);
        float sum = 0.0f, e0 = 0.0f;
        for (int j = 0; j < KNEIGH; j++) {
            float e = expf(dists[j] - mx);
            if (j == 0) e0 = e;
            sum += e;
        }
        float d2m = ord2f((uint32_t)(g_nnkey[b] >> 32));
        float score = sqrtf(fmaxf(g_x2[g_qrow[b]] + d2m, 0.0f));
        out[b] = (1.0f - e0 / sum) * score;
    }
}

// ---------------- fused upsample + separable Gaussian blur ----------------
__global__ void k_map(float* __restrict__ out) {
    char* smem = s_raw;
    float* pm = reinterpret_cast<float*>(smem + MAP_PM);
    float* gs = reinterpret_cast<float*>(smem + MAP_GS);
    float* up = reinterpret_cast<float*>(smem + MAP_UP);
    float* vt = reinterpret_cast<float*>(smem + MAP_VT);
    const int band = blockIdx.x, b = blockIdx.y;
    const int tid = threadIdx.x;
    const int r0 = band * 16;

    for (int i = tid; i < PPB; i += 256) pm[i] = g_pscore[b * PPB + i];
    if (tid < KSIZE) gs[tid] = g_gauss[tid];
    __syncthreads();

    for (int i = tid; i < 48 * 224; i += 256) {
        int j = i / 224, V = i % 224;
        int U = r0 - 16 + j;
        if (U < 0) U = -U;
        if (U > OUTSZ - 1) U = 2 * (OUTSZ - 1) - U;
        float su = ((float)U + 0.5f) * 0.125f - 0.5f;
        float sv = ((float)V + 0.5f) * 0.125f - 0.5f;
        int u0 = (int)floorf(su), v0 = (int)floorf(sv);
        float tu = su - (float)u0, tvv = sv - (float)v0;
        int u0c = min(max(u0, 0), WIO - 1), u1c = min(max(u0 + 1, 0), WIO - 1);
        int v0c = min(max(v0, 0), WIO - 1), v1c = min(max(v0 + 1, 0), WIO - 1);
        float v00 = pm[u0c * WIO + v0c], v01 = pm[u0c * WIO + v1c];
        float v10 = pm[u1c * WIO + v0c], v11 = pm[u1c * WIO + v1c];
        float top = v00 + tvv * (v01 - v00);
        float bot = v10 + tvv * (v11 - v10);
        up[i] = top + tu * (bot - top);
    }
    __syncthreads();

    for (int i = tid; i < 16 * 224; i += 256) {
        int du = i / 224, V = i % 224;
        float acc = 0.0f;
        #pragma unroll
        for (int k = 0; k < KSIZE; k++) acc += gs[k] * up[(du + k) * 224 + V];
        vt[i] = acc;
    }
    __syncthreads();

    for (int i = tid; i < 16 * 224; i += 256) {
        int du = i / 224, V = i % 224;
        float acc = 0.0f;
        #pragma unroll
        for (int k = 0; k < KSIZE; k++) {
            int jv = V - KRAD + k;
            if (jv < 0) jv = -jv;
            if (jv > OUTSZ - 1) jv = 2 * (OUTSZ - 1) - jv;
            acc += gs[k] * vt[du * 224 + jv];
        }
        out[BATCH + (b * OUTSZ + r0 + du) * OUTSZ + V] = acc;
    }
}

// ---------------- launcher ----------------
extern "C" void kernel_launch(void* const* d_in, const int* in_sizes, int n_in,
                              void* d_out, int out_size) {
    const float* emb = (const float*)d_in[0];
    const float* mb = (const float*)d_in[1];
    float* out = (float*)d_out;

    static bool attr_set = false;
    if (!attr_set) {
        cudaFuncSetAttribute(k_dist_mma, cudaFuncAttributeMaxDynamicSharedMemorySize, SMEM_TOTAL);
        cudaFuncSetAttribute(k_map, cudaFuncAttributeMaxDynamicSharedMemorySize, MAP_SMEM);
        attr_set = true;
    }

    k_prep<<<(MROWS + NROWS) / 32, 256>>>(emb, mb);

    dim3 gdist(NROWS / BNR, NSPLIT);
    k_dist_mma<<<gdist, 128, SMEM_TOTAL>>>();

    k_score<<<BATCH, 256>>>();

    dim3 gq(128, BATCH);
    k_qpart<<<gq, 256>>>(emb, mb);

    dim3 gd9(128, BATCH);
    k_dnn9<<<gd9, 256>>>(emb, mb, out);

    dim3 gmap(14, BATCH);
    k_map<<<gmap, 256, MAP_SMEM>>>(out);
}